// round 1
// baseline (speedup 1.0000x reference)
#include <cuda_runtime.h>
#include <math.h>

// ---------------------------------------------------------------------------
// CrossAttention: out = Wout @ softmax(scale * (Wq x)^T (Wk c) + mask) stuff
// Shapes: B=2, S=4096, H=8, D=160, QUERY_DIM=INNER=1280
// Round-0 baseline: fp32 tiled SGEMMs + materialized scores + row softmax.
// ---------------------------------------------------------------------------

namespace cfg {
constexpr int B  = 2;
constexpr int S  = 4096;
constexpr int H  = 8;
constexpr int D  = 160;
constexpr int QD = 1280;   // QUERY_DIM
constexpr int IN = 1280;   // INNER = H*D
}

// Scratch (static device globals: allocation at module load, allowed by rules)
__device__ float g_q[(size_t)cfg::B * cfg::IN * cfg::S];
__device__ float g_k[(size_t)cfg::B * cfg::IN * cfg::S];
__device__ float g_v[(size_t)cfg::B * cfg::IN * cfg::S];
__device__ float g_attn[(size_t)cfg::B * cfg::IN * cfg::S];
// Full score matrix: 2*8*4096*4096 floats = 1.07 GB
__device__ float g_scores[(size_t)cfg::B * cfg::H * cfg::S * cfg::S];

// ---------------------------------------------------------------------------
// Generic batched tiled SGEMM.
//   C[z][m][n] = alpha * sum_k Aelem(m,k) * Belem(k,n)  (+ bias[m])
//   TA=false: Aelem(m,k) = A[m*K + k]   (row-major M x K)
//   TA=true : Aelem(m,k) = A[k*M + m]   (stored K x M, i.e. compute A^T * B)
//   TB=false: Belem(k,n) = B[k*N + n]   (row-major K x N)
//   TB=true : Belem(k,n) = B[n*K + k]   (stored N x K, i.e. compute A * B^T)
// Batch via blockIdx.z with element strides sA/sB/sC.
// ---------------------------------------------------------------------------
template<int BM, int BN, int BK, int TM, int TN, bool TA, bool TB>
__global__ void __launch_bounds__((BM / TM) * (BN / TN))
gemm_kernel(const float* __restrict__ Ab, const float* __restrict__ Bb,
            float* __restrict__ Cb,
            int M, int N, int K,
            long sA, long sB, long sC,
            float alpha, const float* __restrict__ bias)
{
    constexpr int NT = (BM / TM) * (BN / TN);
    constexpr int AE = (BM * BK) / NT;
    constexpr int BE = (BN * BK) / NT;
    static_assert((BM * BK) % NT == 0 && (BN * BK) % NT == 0, "tile/thread mismatch");

    const float* A  = Ab + (long)blockIdx.z * sA;
    const float* Bp = Bb + (long)blockIdx.z * sB;
    float*       C  = Cb + (long)blockIdx.z * sC;

    const int m0 = blockIdx.y * BM;
    const int n0 = blockIdx.x * BN;
    const int t  = threadIdx.x;
    const int tx = t % (BN / TN);
    const int ty = t / (BN / TN);

    __shared__ float As[BK][BM + 4];
    __shared__ float Bs[BK][BN + 4];

    float acc[TM][TN];
    #pragma unroll
    for (int i = 0; i < TM; i++)
        #pragma unroll
        for (int j = 0; j < TN; j++) acc[i][j] = 0.f;

    for (int k0 = 0; k0 < K; k0 += BK) {
        // --- load A tile; enumerate with the contiguous global dim fastest ---
        #pragma unroll
        for (int i = 0; i < AE; i++) {
            int li = t + i * NT;
            int m, k;
            if (TA) { m = li % BM; k = li / BM; }     // contiguous in m
            else    { k = li % BK; m = li / BK; }     // contiguous in k
            int gm = m0 + m, gk = k0 + k;
            float v = 0.f;
            if (gm < M) v = TA ? A[(long)gk * M + gm] : A[(long)gm * K + gk];
            As[k][m] = v;
        }
        // --- load B tile ---
        #pragma unroll
        for (int i = 0; i < BE; i++) {
            int li = t + i * NT;
            int n, k;
            if (TB) { k = li % BK; n = li / BK; }     // contiguous in k
            else    { n = li % BN; k = li / BN; }     // contiguous in n
            int gn = n0 + n, gk = k0 + k;
            float v = 0.f;
            if (gn < N) v = TB ? Bp[(long)gn * K + gk] : Bp[(long)gk * N + gn];
            Bs[k][n] = v;
        }
        __syncthreads();

        #pragma unroll
        for (int kk = 0; kk < BK; kk++) {
            float a[TM], bfrag[TN];
            #pragma unroll
            for (int i = 0; i < TM; i++) a[i] = As[kk][ty * TM + i];
            #pragma unroll
            for (int j = 0; j < TN; j++) bfrag[j] = Bs[kk][tx * TN + j];
            #pragma unroll
            for (int i = 0; i < TM; i++)
                #pragma unroll
                for (int j = 0; j < TN; j++)
                    acc[i][j] = fmaf(a[i], bfrag[j], acc[i][j]);
        }
        __syncthreads();
    }

    #pragma unroll
    for (int i = 0; i < TM; i++) {
        int gm = m0 + ty * TM + i;
        if (gm >= M) continue;
        float badd = bias ? bias[gm] : 0.f;
        #pragma unroll
        for (int j = 0; j < TN; j++) {
            int gn = n0 + tx * TN + j;
            if (gn < N) C[(long)gm * N + gn] = acc[i][j] * alpha + badd;
        }
    }
}

// ---------------------------------------------------------------------------
// Row softmax over the key axis, with additive per-key mask.
// One block per (b,h,q) row of 4096 keys. mask[b*S + k] added before max.
// ---------------------------------------------------------------------------
__global__ void softmax_kernel(float* __restrict__ scores,
                               const float* __restrict__ mask)
{
    using namespace cfg;
    const long row = blockIdx.x;                       // (b*H + h)*S + q
    const int  b   = (int)(row / ((long)H * S));
    float*       p    = scores + row * (long)S;
    const float* mrow = mask + (long)b * S;

    __shared__ float buf[cfg::S];                      // 16 KB
    __shared__ float red[8];

    const int t    = threadIdx.x;
    const int nt   = blockDim.x;                       // 256
    const int lane = t & 31;
    const int warp = t >> 5;

    float lmax = -3.4e38f;
    for (int i = t; i < S; i += nt) {
        float v = p[i] + mrow[i];
        buf[i] = v;
        lmax = fmaxf(lmax, v);
    }
    #pragma unroll
    for (int o = 16; o; o >>= 1)
        lmax = fmaxf(lmax, __shfl_xor_sync(0xffffffffu, lmax, o));
    if (lane == 0) red[warp] = lmax;
    __syncthreads();
    float bmax = red[0];
    #pragma unroll
    for (int w = 1; w < 8; w++) bmax = fmaxf(bmax, red[w]);
    __syncthreads();                                   // before reusing red[]

    float lsum = 0.f;
    for (int i = t; i < S; i += nt) {
        float e = expf(buf[i] - bmax);
        buf[i] = e;
        lsum += e;
    }
    #pragma unroll
    for (int o = 16; o; o >>= 1)
        lsum += __shfl_xor_sync(0xffffffffu, lsum, o);
    if (lane == 0) red[warp] = lsum;
    __syncthreads();
    float bsum = 0.f;
    #pragma unroll
    for (int w = 0; w < 8; w++) bsum += red[w];

    float inv = 1.0f / bsum;
    for (int i = t; i < S; i += nt) p[i] = buf[i] * inv;
}

// ---------------------------------------------------------------------------
extern "C" void kernel_launch(void* const* d_in, const int* in_sizes, int n_in,
                              void* d_out, int out_size)
{
    using namespace cfg;
    (void)in_sizes; (void)n_in; (void)out_size;

    const float* hidden  = (const float*)d_in[0];  // (B, QD, 1, S)
    const float* context = (const float*)d_in[1];  // (B, QD, 1, S)
    const float* mask    = (const float*)d_in[2];  // (B, S, 1, 1)
    const float* Wq      = (const float*)d_in[3];  // (IN, QD)
    const float* Wk      = (const float*)d_in[4];
    const float* Wv      = (const float*)d_in[5];
    const float* Wout    = (const float*)d_in[6];  // (QD, IN)
    const float* bout    = (const float*)d_in[7];  // (QD)
    float*       out     = (float*)d_out;          // (B, QD, 1, S)

    void *pq, *pk, *pv, *pa, *ps;
    cudaGetSymbolAddress(&pq, g_q);
    cudaGetSymbolAddress(&pk, g_k);
    cudaGetSymbolAddress(&pv, g_v);
    cudaGetSymbolAddress(&pa, g_attn);
    cudaGetSymbolAddress(&ps, g_scores);
    float* q  = (float*)pq;
    float* k  = (float*)pk;
    float* v  = (float*)pv;
    float* at = (float*)pa;
    float* sc = (float*)ps;

    const float scale = 1.0f / sqrtf((float)D);

    // --- projections: C[b] = W (1280x1280) * X[b] (1280x4096) -------------
    dim3 gproj(S / 128, IN / 128, B);                  // (32, 10, 2)
    gemm_kernel<128,128,8,8,8,false,false><<<gproj, 256>>>(
        Wq, hidden, q, IN, S, QD, 0, (long)QD * S, (long)IN * S, 1.f, nullptr);
    gemm_kernel<128,128,8,8,8,false,false><<<gproj, 256>>>(
        Wk, context, k, IN, S, QD, 0, (long)QD * S, (long)IN * S, 1.f, nullptr);
    gemm_kernel<128,128,8,8,8,false,false><<<gproj, 256>>>(
        Wv, context, v, IN, S, QD, 0, (long)QD * S, (long)IN * S, 1.f, nullptr);

    // --- scores[b,h] = scale * Qh^T Kh : M=N=4096, K=160 ------------------
    dim3 gsc(S / 128, S / 128, B * H);                 // (32, 32, 16)
    gemm_kernel<128,128,8,8,8,true,false><<<gsc, 256>>>(
        q, k, sc, S, S, D,
        (long)D * S, (long)D * S, (long)S * S, scale, nullptr);

    // --- softmax rows (mask folded in) ------------------------------------
    softmax_kernel<<<B * H * S, 256>>>(sc, mask);

    // --- attn[b,h] = Vh (160x4096) * P^T : M=160, N=4096, K=4096 ----------
    dim3 gat(S / 128, 1, B * H);                       // (32, 1, 16)
    gemm_kernel<160,128,16,5,8,false,true><<<gat, 512>>>(
        v, sc, at, D, S, S,
        (long)D * S, (long)S * S, (long)D * S, 1.f, nullptr);

    // --- out = Wout * attn + bout -----------------------------------------
    dim3 gout(S / 128, QD / 128, B);                   // (32, 10, 2)
    gemm_kernel<128,128,8,8,8,false,false><<<gout, 256>>>(
        Wout, at, out, QD, S, IN, 0, (long)IN * S, (long)QD * S, 1.f, bout);
}

// round 2
// speedup vs baseline: 1.4990x; 1.4990x over previous
#include <cuda_runtime.h>
#include <math.h>
#include <stdint.h>

// ---------------------------------------------------------------------------
// CrossAttention, round 2: all GEMMs on tensor cores (TF32 mma.sync, fp32 acc)
// B=2, S=4096, H=8, D=160, QUERY_DIM=INNER=1280
// ---------------------------------------------------------------------------

namespace cfg {
constexpr int B  = 2;
constexpr int S  = 4096;
constexpr int H  = 8;
constexpr int D  = 160;
constexpr int QD = 1280;
constexpr int IN = 1280;
}

__device__ float g_q[(size_t)cfg::B * cfg::IN * cfg::S];
__device__ float g_k[(size_t)cfg::B * cfg::IN * cfg::S];
__device__ float g_v[(size_t)cfg::B * cfg::IN * cfg::S];
__device__ float g_attn[(size_t)cfg::B * cfg::IN * cfg::S];
__device__ float g_scores[(size_t)cfg::B * cfg::H * cfg::S * cfg::S]; // 1.07 GB

__device__ __forceinline__ float to_tf32(float x) {
    float r; asm("cvt.rna.tf32.f32 %0, %1;" : "=f"(r) : "f"(x)); return r;
}

__device__ __forceinline__ void mma8(float4& d, const uint4& a, const uint2& b) {
    asm volatile(
        "mma.sync.aligned.m16n8k8.row.col.f32.tf32.tf32.f32 "
        "{%0,%1,%2,%3}, {%4,%5,%6,%7}, {%8,%9}, {%0,%1,%2,%3};\n"
        : "+f"(d.x), "+f"(d.y), "+f"(d.z), "+f"(d.w)
        : "r"(a.x), "r"(a.y), "r"(a.z), "r"(a.w), "r"(b.x), "r"(b.y));
}

// Fragment-major smem offsets.
// A tile: per (ks=k/8, mt=m/16) fragment of 128 floats laid out [lane][reg]:
//   lane = (m%8)*4 + (k%4); reg = ((m>>3)&1) | (((k>>2)&1)<<1)
template<int BM> __device__ __forceinline__ int offA(int m, int k) {
    return (((k >> 3) * (BM / 16) + (m >> 4)) << 7)
         + ((((m & 7) << 2) | (k & 3)) << 2)
         + ((m >> 3) & 1) + (((k >> 2) & 1) << 1);
}
// B tile: per (ks=k/8, nt=n/8) fragment of 64 floats:
//   lane = (n%8)*4 + (k%4); reg = (k>>2)&1
template<int BN> __device__ __forceinline__ int offB(int k, int n) {
    return (((k >> 3) * (BN / 8) + (n >> 3)) << 6)
         + ((((n & 7) << 2) | (k & 3)) << 1)
         + ((k >> 2) & 1);
}

// ---------------------------------------------------------------------------
// TF32 tensor-core GEMM. C[z] = alpha * op(A[z]) * op(B[z]) (+ bias[m])
//   TA=false: A row-major MxK.  TA=true: A stored KxM (compute A^T B).
//   TB=false: B row-major KxN.  TB=true: B stored NxK (compute A B^T).
// All dims must divide the tile sizes exactly (asserted by launch choices).
// ---------------------------------------------------------------------------
template<int BM, int BN, int BK, int WM, int WN, bool TA, bool TB>
__global__ void __launch_bounds__((BM / WM) * (BN / WN) * 32)
mma_gemm(const float* __restrict__ Ab, const float* __restrict__ Bb,
         float* __restrict__ Cb, int M, int N, int K,
         long sA, long sB, long sC, float alpha, const float* __restrict__ bias)
{
    constexpr int NWARP = (BM / WM) * (BN / WN);
    constexpr int NT    = NWARP * 32;
    constexpr int AV    = (BM * BK) / (NT * 4);   // float4 A loads / thread
    constexpr int BV    = (BN * BK) / (NT * 4);
    constexpr int KS    = BK / 8;
    constexpr int MT    = WM / 16;
    constexpr int NTW   = WN / 8;
    static_assert((BM * BK) % (NT * 4) == 0 && (BN * BK) % (NT * 4) == 0, "staging");
    static_assert(AV >= 1 && BV >= 1, "staging");

    __shared__ __align__(16) float sm[2][BM * BK + BN * BK];

    const float* A  = Ab + (long)blockIdx.z * sA;
    const float* Bp = Bb + (long)blockIdx.z * sB;
    float*       C  = Cb + (long)blockIdx.z * sC;

    const int m0 = blockIdx.y * BM;
    const int n0 = blockIdx.x * BN;
    const int t = threadIdx.x, lane = t & 31, w = t >> 5;
    const int wn = w % (BN / WN), wm = w / (BN / WN);
    const int grp = lane >> 2, tig = lane & 3;

    float4 acc[MT][NTW];
    #pragma unroll
    for (int i = 0; i < MT; i++)
        #pragma unroll
        for (int j = 0; j < NTW; j++) acc[i][j] = make_float4(0.f, 0.f, 0.f, 0.f);

    float4 aR[AV], bR[BV];

    auto loadG = [&](int k0) {
        #pragma unroll
        for (int i = 0; i < AV; i++) {
            int f = t + i * NT;
            if (TA) { int mq = f % (BM / 4), kk = f / (BM / 4);
                aR[i] = *(const float4*)(A + (long)(k0 + kk) * M + m0 + mq * 4);
            } else { int kq = f % (BK / 4), mm = f / (BK / 4);
                aR[i] = *(const float4*)(A + (long)(m0 + mm) * K + k0 + kq * 4);
            }
        }
        #pragma unroll
        for (int i = 0; i < BV; i++) {
            int f = t + i * NT;
            if (TB) { int kq = f % (BK / 4), nn = f / (BK / 4);
                bR[i] = *(const float4*)(Bp + (long)(n0 + nn) * K + k0 + kq * 4);
            } else { int nq = f % (BN / 4), kk = f / (BN / 4);
                bR[i] = *(const float4*)(Bp + (long)(k0 + kk) * N + n0 + nq * 4);
            }
        }
    };

    auto storeS = [&](int buf) {
        float* sA_ = sm[buf];
        float* sB_ = sm[buf] + BM * BK;
        #pragma unroll
        for (int i = 0; i < AV; i++) {
            int f = t + i * NT;
            float v[4] = {aR[i].x, aR[i].y, aR[i].z, aR[i].w};
            if (TA) { int mq = f % (BM / 4), kk = f / (BM / 4);
                #pragma unroll
                for (int j = 0; j < 4; j++) sA_[offA<BM>(mq * 4 + j, kk)] = to_tf32(v[j]);
            } else { int kq = f % (BK / 4), mm = f / (BK / 4);
                #pragma unroll
                for (int j = 0; j < 4; j++) sA_[offA<BM>(mm, kq * 4 + j)] = to_tf32(v[j]);
            }
        }
        #pragma unroll
        for (int i = 0; i < BV; i++) {
            int f = t + i * NT;
            float v[4] = {bR[i].x, bR[i].y, bR[i].z, bR[i].w};
            if (TB) { int kq = f % (BK / 4), nn = f / (BK / 4);
                #pragma unroll
                for (int j = 0; j < 4; j++) sB_[offB<BN>(kq * 4 + j, nn)] = to_tf32(v[j]);
            } else { int nq = f % (BN / 4), kk = f / (BN / 4);
                #pragma unroll
                for (int j = 0; j < 4; j++) sB_[offB<BN>(kk, nq * 4 + j)] = to_tf32(v[j]);
            }
        }
    };

    auto compute = [&](int buf) {
        const float* sA_ = sm[buf];
        const float* sB_ = sm[buf] + BM * BK;
        #pragma unroll
        for (int ks = 0; ks < KS; ks++) {
            uint4 a[MT];
            uint2 b[NTW];
            #pragma unroll
            for (int mt = 0; mt < MT; mt++)
                a[mt] = *(const uint4*)(sA_ + ((ks * (BM / 16) + (wm * MT + mt)) << 7) + (lane << 2));
            #pragma unroll
            for (int nt = 0; nt < NTW; nt++)
                b[nt] = *(const uint2*)(sB_ + ((ks * (BN / 8) + (wn * NTW + nt)) << 6) + (lane << 1));
            #pragma unroll
            for (int mt = 0; mt < MT; mt++)
                #pragma unroll
                for (int nt = 0; nt < NTW; nt++)
                    mma8(acc[mt][nt], a[mt], b[nt]);
        }
    };

    const int nk = K / BK;
    loadG(0);
    storeS(0);
    __syncthreads();
    for (int it = 0; it < nk; ++it) {
        if (it + 1 < nk) loadG((it + 1) * BK);
        compute(it & 1);
        if (it + 1 < nk) {
            __syncthreads();
            storeS((it + 1) & 1);
            __syncthreads();
        }
    }

    // epilogue
    #pragma unroll
    for (int mt = 0; mt < MT; mt++) {
        int gm = m0 + wm * WM + mt * 16 + grp;
        float b0 = bias ? bias[gm] : 0.f;
        float b1 = bias ? bias[gm + 8] : 0.f;
        #pragma unroll
        for (int nt = 0; nt < NTW; nt++) {
            int gn = n0 + wn * WN + nt * 8 + tig * 2;
            float4 ac = acc[mt][nt];
            float2 v0 = make_float2(ac.x * alpha + b0, ac.y * alpha + b0);
            float2 v1 = make_float2(ac.z * alpha + b1, ac.w * alpha + b1);
            *(float2*)(C + (long)gm * N + gn) = v0;
            *(float2*)(C + (long)(gm + 8) * N + gn) = v1;
        }
    }
}

// ---------------------------------------------------------------------------
// Row softmax over keys with additive per-key mask, float4-vectorized.
// One block per (b,h,q) row of 4096 keys.
// ---------------------------------------------------------------------------
__global__ void softmax_kernel(float* __restrict__ scores,
                               const float* __restrict__ mask)
{
    using namespace cfg;
    const long row = blockIdx.x;                        // (b*H + h)*S + q
    const int  b   = (int)(row / ((long)H * S));
    float4*       p    = (float4*)(scores + row * (long)S);
    const float4* mrow = (const float4*)(mask + (long)b * S);

    __shared__ float4 buf[cfg::S / 4];                  // 16 KB
    __shared__ float red[8];

    const int t = threadIdx.x, nt = blockDim.x;         // 256
    const int lane = t & 31, warp = t >> 5;
    constexpr int NV = cfg::S / 4;

    float lmax = -3.4e38f;
    for (int i = t; i < NV; i += nt) {
        float4 v = p[i], m = mrow[i];
        v.x += m.x; v.y += m.y; v.z += m.z; v.w += m.w;
        buf[i] = v;
        lmax = fmaxf(lmax, fmaxf(fmaxf(v.x, v.y), fmaxf(v.z, v.w)));
    }
    #pragma unroll
    for (int o = 16; o; o >>= 1)
        lmax = fmaxf(lmax, __shfl_xor_sync(0xffffffffu, lmax, o));
    if (lane == 0) red[warp] = lmax;
    __syncthreads();
    float bmax = red[0];
    #pragma unroll
    for (int wv = 1; wv < 8; wv++) bmax = fmaxf(bmax, red[wv]);
    __syncthreads();

    float lsum = 0.f;
    for (int i = t; i < NV; i += nt) {
        float4 v = buf[i];
        v.x = expf(v.x - bmax); v.y = expf(v.y - bmax);
        v.z = expf(v.z - bmax); v.w = expf(v.w - bmax);
        buf[i] = v;
        lsum += v.x + v.y + v.z + v.w;
    }
    #pragma unroll
    for (int o = 16; o; o >>= 1)
        lsum += __shfl_xor_sync(0xffffffffu, lsum, o);
    if (lane == 0) red[warp] = lsum;
    __syncthreads();
    float bsum = 0.f;
    #pragma unroll
    for (int wv = 0; wv < 8; wv++) bsum += red[wv];

    float inv = 1.0f / bsum;
    for (int i = t; i < NV; i += nt) {
        float4 v = buf[i];
        v.x *= inv; v.y *= inv; v.z *= inv; v.w *= inv;
        p[i] = v;
    }
}

// ---------------------------------------------------------------------------
extern "C" void kernel_launch(void* const* d_in, const int* in_sizes, int n_in,
                              void* d_out, int out_size)
{
    using namespace cfg;
    (void)in_sizes; (void)n_in; (void)out_size;

    const float* hidden  = (const float*)d_in[0];  // (B, QD, 1, S)
    const float* context = (const float*)d_in[1];
    const float* mask    = (const float*)d_in[2];  // (B, S, 1, 1)
    const float* Wq      = (const float*)d_in[3];  // (IN, QD)
    const float* Wk      = (const float*)d_in[4];
    const float* Wv      = (const float*)d_in[5];
    const float* Wout    = (const float*)d_in[6];  // (QD, IN)
    const float* bout    = (const float*)d_in[7];
    float*       out     = (float*)d_out;          // (B, QD, 1, S)

    void *pq, *pk, *pv, *pa, *ps;
    cudaGetSymbolAddress(&pq, g_q);
    cudaGetSymbolAddress(&pk, g_k);
    cudaGetSymbolAddress(&pv, g_v);
    cudaGetSymbolAddress(&pa, g_attn);
    cudaGetSymbolAddress(&ps, g_scores);
    float* q  = (float*)pq;
    float* k  = (float*)pk;
    float* v  = (float*)pv;
    float* at = (float*)pa;
    float* sc = (float*)ps;

    const float scale = 1.0f / sqrtf((float)D);

    // projections: (1280x1280) * (1280x4096), batched over B
    dim3 gproj(S / 128, IN / 128, B);
    mma_gemm<128,128,16,64,32,false,false><<<gproj, 256>>>(
        Wq, hidden, q, IN, S, QD, 0, (long)QD * S, (long)IN * S, 1.f, nullptr);
    mma_gemm<128,128,16,64,32,false,false><<<gproj, 256>>>(
        Wk, context, k, IN, S, QD, 0, (long)QD * S, (long)IN * S, 1.f, nullptr);
    mma_gemm<128,128,16,64,32,false,false><<<gproj, 256>>>(
        Wv, context, v, IN, S, QD, 0, (long)QD * S, (long)IN * S, 1.f, nullptr);

    // scores[b,h] = scale * Qh^T Kh : M=N=4096, K=160
    dim3 gsc(S / 128, S / 128, B * H);
    mma_gemm<128,128,16,64,32,true,false><<<gsc, 256>>>(
        q, k, sc, S, S, D,
        (long)D * S, (long)D * S, (long)S * S, scale, nullptr);

    // softmax rows (mask folded in)
    softmax_kernel<<<B * H * S, 256>>>(sc, mask);

    // attn[b,h] = Vh (160x4096) * P^T : M=160, N=4096, K=4096  (160 = 5*32)
    dim3 gat(S / 128, D / 32, B * H);
    mma_gemm<32,128,16,32,32,false,true><<<gat, 128>>>(
        v, sc, at, D, S, S,
        (long)D * S, (long)S * S, (long)D * S, 1.f, nullptr);

    // out = Wout * attn + bout
    dim3 gout(S / 128, QD / 128, B);
    mma_gemm<128,128,16,64,32,false,false><<<gout, 256>>>(
        Wout, at, out, QD, S, IN, 0, (long)IN * S, (long)QD * S, 1.f, bout);
}

// round 3
// speedup vs baseline: 3.2753x; 2.1850x over previous
#include <cuda_runtime.h>
#include <math.h>
#include <stdint.h>

// ---------------------------------------------------------------------------
// CrossAttention, round 3: TF32 mma GEMMs with bank-conflict-free swizzled
// fragment-major shared layout (staging stores were 8..32-way conflicted).
// B=2, S=4096, H=8, D=160, QUERY_DIM=INNER=1280
// ---------------------------------------------------------------------------

namespace cfg {
constexpr int B  = 2;
constexpr int S  = 4096;
constexpr int H  = 8;
constexpr int D  = 160;
constexpr int QD = 1280;
constexpr int IN = 1280;
}

__device__ float g_q[(size_t)cfg::B * cfg::IN * cfg::S];
__device__ float g_k[(size_t)cfg::B * cfg::IN * cfg::S];
__device__ float g_v[(size_t)cfg::B * cfg::IN * cfg::S];
__device__ float g_attn[(size_t)cfg::B * cfg::IN * cfg::S];
__device__ float g_scores[(size_t)cfg::B * cfg::H * cfg::S * cfg::S]; // 1.07 GB

__device__ __forceinline__ float to_tf32(float x) {
    float r; asm("cvt.rna.tf32.f32 %0, %1;" : "=f"(r) : "f"(x)); return r;
}

__device__ __forceinline__ void mma8(float4& d, const uint4& a, const uint2& b) {
    asm volatile(
        "mma.sync.aligned.m16n8k8.row.col.f32.tf32.tf32.f32 "
        "{%0,%1,%2,%3}, {%4,%5,%6,%7}, {%8,%9}, {%0,%1,%2,%3};\n"
        : "+f"(d.x), "+f"(d.y), "+f"(d.z), "+f"(d.w)
        : "r"(a.x), "r"(a.y), "r"(a.z), "r"(a.w), "r"(b.x), "r"(b.y));
}

// --- swizzled fragment-major layout ---------------------------------------
// A fragment = 128 floats (16m x 8k). Loff = lane*4 + reg.
//   lane = (m%8)*4 + (k%4); reg = ((m>>3)&1) | (((k>>2)&1)<<1)
// Swizzle XORs float-addr bits [2:4] (byte [4:6]) with (Loff>>5)^frag:
// keeps 16B alignment for LDS.128, makes staging stores <=2-way conflicted.
__device__ __forceinline__ int swzA(int Loff, int fA) {
    return (fA << 7) + (Loff ^ ((((Loff >> 5) ^ fA) & 7) << 2));
}
template<int BM> __device__ __forceinline__ int offA(int m, int k) {
    int fA   = (k >> 3) * (BM / 16) + (m >> 4);
    int Loff = ((((m & 7) << 2) | (k & 3)) << 2)
             | ((m >> 3) & 1) | (((k >> 2) & 1) << 1);
    return swzA(Loff, fA);
}
// B fragment = 64 floats (8k x 8n). Loff = lane*2 + reg.
//   lane = (n%8)*4 + (k%4); reg = (k>>2)&1
// Swizzle XORs float bits [1:4] (byte [3:6]): keeps 8B alignment for LDS.64.
__device__ __forceinline__ int swzB(int Loff, int fB) {
    return (fB << 6) + (Loff ^ (((fB ^ (fB >> 4)) & 15) << 1));
}
template<int BN> __device__ __forceinline__ int offB(int k, int n) {
    int fB   = (k >> 3) * (BN / 8) + (n >> 3);
    int Loff = ((((n & 7) << 2) | (k & 3)) << 1) | ((k >> 2) & 1);
    return swzB(Loff, fB);
}

// ---------------------------------------------------------------------------
// TF32 tensor-core GEMM. C[z] = alpha * op(A[z]) * op(B[z]) (+ bias[m])
//   TA=false: A row-major MxK.  TA=true: A stored KxM (compute A^T B).
//   TB=false: B row-major KxN.  TB=true: B stored NxK (compute A B^T).
// ---------------------------------------------------------------------------
template<int BM, int BN, int BK, int WM, int WN, bool TA, bool TB>
__global__ void __launch_bounds__((BM / WM) * (BN / WN) * 32)
mma_gemm(const float* __restrict__ Ab, const float* __restrict__ Bb,
         float* __restrict__ Cb, int M, int N, int K,
         long sA, long sB, long sC, float alpha, const float* __restrict__ bias)
{
    constexpr int NWARP = (BM / WM) * (BN / WN);
    constexpr int NT    = NWARP * 32;
    constexpr int AV    = (BM * BK) / (NT * 4);
    constexpr int BV    = (BN * BK) / (NT * 4);
    constexpr int KS    = BK / 8;
    constexpr int MT    = WM / 16;
    constexpr int NTW   = WN / 8;
    static_assert((BM * BK) % (NT * 4) == 0 && (BN * BK) % (NT * 4) == 0, "staging");
    static_assert(AV >= 1 && BV >= 1, "staging");

    __shared__ __align__(16) float sm[2][BM * BK + BN * BK];

    const float* A  = Ab + (long)blockIdx.z * sA;
    const float* Bp = Bb + (long)blockIdx.z * sB;
    float*       C  = Cb + (long)blockIdx.z * sC;

    const int m0 = blockIdx.y * BM;
    const int n0 = blockIdx.x * BN;
    const int t = threadIdx.x, lane = t & 31, w = t >> 5;
    const int wn = w % (BN / WN), wm = w / (BN / WN);
    const int grp = lane >> 2, tig = lane & 3;

    float4 acc[MT][NTW];
    #pragma unroll
    for (int i = 0; i < MT; i++)
        #pragma unroll
        for (int j = 0; j < NTW; j++) acc[i][j] = make_float4(0.f, 0.f, 0.f, 0.f);

    float4 aR[AV], bR[BV];

    auto loadG = [&](int k0) {
        #pragma unroll
        for (int i = 0; i < AV; i++) {
            int f = t + i * NT;
            if (TA) { int mq = f % (BM / 4), kk = f / (BM / 4);
                aR[i] = *(const float4*)(A + (long)(k0 + kk) * M + m0 + mq * 4);
            } else { int kq = f % (BK / 4), mm = f / (BK / 4);
                aR[i] = *(const float4*)(A + (long)(m0 + mm) * K + k0 + kq * 4);
            }
        }
        #pragma unroll
        for (int i = 0; i < BV; i++) {
            int f = t + i * NT;
            if (TB) { int kq = f % (BK / 4), nn = f / (BK / 4);
                bR[i] = *(const float4*)(Bp + (long)(n0 + nn) * K + k0 + kq * 4);
            } else { int nq = f % (BN / 4), kk = f / (BN / 4);
                bR[i] = *(const float4*)(Bp + (long)(k0 + kk) * N + n0 + nq * 4);
            }
        }
    };

    auto storeS = [&](int buf) {
        float* sA_ = sm[buf];
        float* sB_ = sm[buf] + BM * BK;
        #pragma unroll
        for (int i = 0; i < AV; i++) {
            int f = t + i * NT;
            float v[4] = {aR[i].x, aR[i].y, aR[i].z, aR[i].w};
            if (TA) { int mq = f % (BM / 4), kk = f / (BM / 4);
                #pragma unroll
                for (int j = 0; j < 4; j++) sA_[offA<BM>(mq * 4 + j, kk)] = to_tf32(v[j]);
            } else { int kq = f % (BK / 4), mm = f / (BK / 4);
                #pragma unroll
                for (int j = 0; j < 4; j++) sA_[offA<BM>(mm, kq * 4 + j)] = to_tf32(v[j]);
            }
        }
        #pragma unroll
        for (int i = 0; i < BV; i++) {
            int f = t + i * NT;
            float v[4] = {bR[i].x, bR[i].y, bR[i].z, bR[i].w};
            if (TB) { int kq = f % (BK / 4), nn = f / (BK / 4);
                #pragma unroll
                for (int j = 0; j < 4; j++) sB_[offB<BN>(kq * 4 + j, nn)] = to_tf32(v[j]);
            } else { int nq = f % (BN / 4), kk = f / (BN / 4);
                #pragma unroll
                for (int j = 0; j < 4; j++) sB_[offB<BN>(kk, nq * 4 + j)] = to_tf32(v[j]);
            }
        }
    };

    auto compute = [&](int buf) {
        const float* sA_ = sm[buf];
        const float* sB_ = sm[buf] + BM * BK;
        #pragma unroll
        for (int ks = 0; ks < KS; ks++) {
            uint4 a[MT];
            uint2 b[NTW];
            #pragma unroll
            for (int mt = 0; mt < MT; mt++) {
                int fA = ks * (BM / 16) + (wm * MT + mt);
                a[mt] = *(const uint4*)(sA_ + swzA(lane << 2, fA));
            }
            #pragma unroll
            for (int nt = 0; nt < NTW; nt++) {
                int fB = ks * (BN / 8) + (wn * NTW + nt);
                b[nt] = *(const uint2*)(sB_ + swzB(lane << 1, fB));
            }
            #pragma unroll
            for (int mt = 0; mt < MT; mt++)
                #pragma unroll
                for (int nt = 0; nt < NTW; nt++)
                    mma8(acc[mt][nt], a[mt], b[nt]);
        }
    };

    const int nk = K / BK;
    loadG(0);
    storeS(0);
    __syncthreads();
    for (int it = 0; it < nk; ++it) {
        if (it + 1 < nk) loadG((it + 1) * BK);
        compute(it & 1);
        if (it + 1 < nk) {
            __syncthreads();
            storeS((it + 1) & 1);
            __syncthreads();
        }
    }

    // epilogue
    #pragma unroll
    for (int mt = 0; mt < MT; mt++) {
        int gm = m0 + wm * WM + mt * 16 + grp;
        float b0 = bias ? bias[gm] : 0.f;
        float b1 = bias ? bias[gm + 8] : 0.f;
        #pragma unroll
        for (int nt = 0; nt < NTW; nt++) {
            int gn = n0 + wn * WN + nt * 8 + tig * 2;
            float4 ac = acc[mt][nt];
            float2 v0 = make_float2(ac.x * alpha + b0, ac.y * alpha + b0);
            float2 v1 = make_float2(ac.z * alpha + b1, ac.w * alpha + b1);
            *(float2*)(C + (long)gm * N + gn) = v0;
            *(float2*)(C + (long)(gm + 8) * N + gn) = v1;
        }
    }
}

// ---------------------------------------------------------------------------
// Row softmax over keys with additive per-key mask, float4-vectorized.
// ---------------------------------------------------------------------------
__global__ void softmax_kernel(float* __restrict__ scores,
                               const float* __restrict__ mask)
{
    using namespace cfg;
    const long row = blockIdx.x;                        // (b*H + h)*S + q
    const int  b   = (int)(row / ((long)H * S));
    float4*       p    = (float4*)(scores + row * (long)S);
    const float4* mrow = (const float4*)(mask + (long)b * S);

    __shared__ float4 buf[cfg::S / 4];                  // 16 KB
    __shared__ float red[8];

    const int t = threadIdx.x, nt = blockDim.x;         // 256
    const int lane = t & 31, warp = t >> 5;
    constexpr int NV = cfg::S / 4;

    float lmax = -3.4e38f;
    for (int i = t; i < NV; i += nt) {
        float4 v = p[i], m = mrow[i];
        v.x += m.x; v.y += m.y; v.z += m.z; v.w += m.w;
        buf[i] = v;
        lmax = fmaxf(lmax, fmaxf(fmaxf(v.x, v.y), fmaxf(v.z, v.w)));
    }
    #pragma unroll
    for (int o = 16; o; o >>= 1)
        lmax = fmaxf(lmax, __shfl_xor_sync(0xffffffffu, lmax, o));
    if (lane == 0) red[warp] = lmax;
    __syncthreads();
    float bmax = red[0];
    #pragma unroll
    for (int wv = 1; wv < 8; wv++) bmax = fmaxf(bmax, red[wv]);
    __syncthreads();

    float lsum = 0.f;
    for (int i = t; i < NV; i += nt) {
        float4 v = buf[i];
        v.x = expf(v.x - bmax); v.y = expf(v.y - bmax);
        v.z = expf(v.z - bmax); v.w = expf(v.w - bmax);
        buf[i] = v;
        lsum += v.x + v.y + v.z + v.w;
    }
    #pragma unroll
    for (int o = 16; o; o >>= 1)
        lsum += __shfl_xor_sync(0xffffffffu, lsum, o);
    if (lane == 0) red[warp] = lsum;
    __syncthreads();
    float bsum = 0.f;
    #pragma unroll
    for (int wv = 0; wv < 8; wv++) bsum += red[wv];

    float inv = 1.0f / bsum;
    for (int i = t; i < NV; i += nt) {
        float4 v = buf[i];
        v.x *= inv; v.y *= inv; v.z *= inv; v.w *= inv;
        p[i] = v;
    }
}

// ---------------------------------------------------------------------------
extern "C" void kernel_launch(void* const* d_in, const int* in_sizes, int n_in,
                              void* d_out, int out_size)
{
    using namespace cfg;
    (void)in_sizes; (void)n_in; (void)out_size;

    const float* hidden  = (const float*)d_in[0];  // (B, QD, 1, S)
    const float* context = (const float*)d_in[1];
    const float* mask    = (const float*)d_in[2];  // (B, S, 1, 1)
    const float* Wq      = (const float*)d_in[3];  // (IN, QD)
    const float* Wk      = (const float*)d_in[4];
    const float* Wv      = (const float*)d_in[5];
    const float* Wout    = (const float*)d_in[6];  // (QD, IN)
    const float* bout    = (const float*)d_in[7];
    float*       out     = (float*)d_out;          // (B, QD, 1, S)

    void *pq, *pk, *pv, *pa, *ps;
    cudaGetSymbolAddress(&pq, g_q);
    cudaGetSymbolAddress(&pk, g_k);
    cudaGetSymbolAddress(&pv, g_v);
    cudaGetSymbolAddress(&pa, g_attn);
    cudaGetSymbolAddress(&ps, g_scores);
    float* q  = (float*)pq;
    float* k  = (float*)pk;
    float* v  = (float*)pv;
    float* at = (float*)pa;
    float* sc = (float*)ps;

    const float scale = 1.0f / sqrtf((float)D);

    // projections: (1280x1280) * (1280x4096), batched over B
    dim3 gproj(S / 128, IN / 128, B);
    mma_gemm<128,128,16,64,32,false,false><<<gproj, 256>>>(
        Wq, hidden, q, IN, S, QD, 0, (long)QD * S, (long)IN * S, 1.f, nullptr);
    mma_gemm<128,128,16,64,32,false,false><<<gproj, 256>>>(
        Wk, context, k, IN, S, QD, 0, (long)QD * S, (long)IN * S, 1.f, nullptr);
    mma_gemm<128,128,16,64,32,false,false><<<gproj, 256>>>(
        Wv, context, v, IN, S, QD, 0, (long)QD * S, (long)IN * S, 1.f, nullptr);

    // scores[b,h] = scale * Qh^T Kh : M=N=4096, K=160
    dim3 gsc(S / 128, S / 128, B * H);
    mma_gemm<128,128,16,64,32,true,false><<<gsc, 256>>>(
        q, k, sc, S, S, D,
        (long)D * S, (long)D * S, (long)S * S, scale, nullptr);

    // softmax rows (mask folded in)
    softmax_kernel<<<B * H * S, 256>>>(sc, mask);

    // attn[b,h] = Vh (160x4096) * P^T : M=160, N=4096, K=4096  (160 = 5*32)
    dim3 gat(S / 128, D / 32, B * H);
    mma_gemm<32,128,16,32,32,false,true><<<gat, 128>>>(
        v, sc, at, D, S, S,
        (long)D * S, (long)S * S, (long)D * S, 1.f, nullptr);

    // out = Wout * attn + bout
    dim3 gout(S / 128, QD / 128, B);
    mma_gemm<128,128,16,64,32,false,false><<<gout, 256>>>(
        Wout, at, out, QD, S, IN, 0, (long)IN * S, (long)QD * S, 1.f, bout);
}

// round 4
// speedup vs baseline: 3.6457x; 1.1131x over previous
#include <cuda_runtime.h>
#include <math.h>
#include <stdint.h>

// ---------------------------------------------------------------------------
// CrossAttention, round 4: projections/out via swizzled TF32 mma GEMM,
// attention mid-section fused into a flash-attention kernel (no score matrix).
// B=2, S=4096, H=8, D=160, QUERY_DIM=INNER=1280
// ---------------------------------------------------------------------------

namespace cfg {
constexpr int B  = 2;
constexpr int S  = 4096;
constexpr int H  = 8;
constexpr int D  = 160;
constexpr int QD = 1280;
constexpr int IN = 1280;
}

__device__ float g_q[(size_t)cfg::B * cfg::IN * cfg::S];
__device__ float g_k[(size_t)cfg::B * cfg::IN * cfg::S];
__device__ float g_v[(size_t)cfg::B * cfg::IN * cfg::S];
__device__ float g_attn[(size_t)cfg::B * cfg::IN * cfg::S];

__device__ __forceinline__ float to_tf32(float x) {
    float r; asm("cvt.rna.tf32.f32 %0, %1;" : "=f"(r) : "f"(x)); return r;
}

__device__ __forceinline__ void mma8(float4& d, const uint4& a, const uint2& b) {
    asm volatile(
        "mma.sync.aligned.m16n8k8.row.col.f32.tf32.tf32.f32 "
        "{%0,%1,%2,%3}, {%4,%5,%6,%7}, {%8,%9}, {%0,%1,%2,%3};\n"
        : "+f"(d.x), "+f"(d.y), "+f"(d.z), "+f"(d.w)
        : "r"(a.x), "r"(a.y), "r"(a.z), "r"(a.w), "r"(b.x), "r"(b.y));
}

// --- swizzled fragment-major shared layout (round-3, verified) -------------
__device__ __forceinline__ int swzA(int Loff, int fA) {
    return (fA << 7) + (Loff ^ ((((Loff >> 5) ^ fA) & 7) << 2));
}
template<int BM> __device__ __forceinline__ int offA(int m, int k) {
    int fA   = (k >> 3) * (BM / 16) + (m >> 4);
    int Loff = ((((m & 7) << 2) | (k & 3)) << 2)
             | ((m >> 3) & 1) | (((k >> 2) & 1) << 1);
    return swzA(Loff, fA);
}
__device__ __forceinline__ int swzB(int Loff, int fB) {
    return (fB << 6) + (Loff ^ (((fB ^ (fB >> 4)) & 15) << 1));
}
template<int BN> __device__ __forceinline__ int offB(int k, int n) {
    int fB   = (k >> 3) * (BN / 8) + (n >> 3);
    int Loff = ((((n & 7) << 2) | (k & 3)) << 1) | ((k >> 2) & 1);
    return swzB(Loff, fB);
}

// ---------------------------------------------------------------------------
// TF32 tensor-core GEMM (unchanged from round 3).
// ---------------------------------------------------------------------------
template<int BM, int BN, int BK, int WM, int WN, bool TA, bool TB>
__global__ void __launch_bounds__((BM / WM) * (BN / WN) * 32)
mma_gemm(const float* __restrict__ Ab, const float* __restrict__ Bb,
         float* __restrict__ Cb, int M, int N, int K,
         long sA, long sB, long sC, float alpha, const float* __restrict__ bias)
{
    constexpr int NWARP = (BM / WM) * (BN / WN);
    constexpr int NT    = NWARP * 32;
    constexpr int AV    = (BM * BK) / (NT * 4);
    constexpr int BV    = (BN * BK) / (NT * 4);
    constexpr int KS    = BK / 8;
    constexpr int MT    = WM / 16;
    constexpr int NTW   = WN / 8;

    __shared__ __align__(16) float sm[2][BM * BK + BN * BK];

    const float* A  = Ab + (long)blockIdx.z * sA;
    const float* Bp = Bb + (long)blockIdx.z * sB;
    float*       C  = Cb + (long)blockIdx.z * sC;

    const int m0 = blockIdx.y * BM;
    const int n0 = blockIdx.x * BN;
    const int t = threadIdx.x, lane = t & 31, w = t >> 5;
    const int wn = w % (BN / WN), wm = w / (BN / WN);
    const int grp = lane >> 2, tig = lane & 3;

    float4 acc[MT][NTW];
    #pragma unroll
    for (int i = 0; i < MT; i++)
        #pragma unroll
        for (int j = 0; j < NTW; j++) acc[i][j] = make_float4(0.f, 0.f, 0.f, 0.f);

    float4 aR[AV], bR[BV];

    auto loadG = [&](int k0) {
        #pragma unroll
        for (int i = 0; i < AV; i++) {
            int f = t + i * NT;
            if (TA) { int mq = f % (BM / 4), kk = f / (BM / 4);
                aR[i] = *(const float4*)(A + (long)(k0 + kk) * M + m0 + mq * 4);
            } else { int kq = f % (BK / 4), mm = f / (BK / 4);
                aR[i] = *(const float4*)(A + (long)(m0 + mm) * K + k0 + kq * 4);
            }
        }
        #pragma unroll
        for (int i = 0; i < BV; i++) {
            int f = t + i * NT;
            if (TB) { int kq = f % (BK / 4), nn = f / (BK / 4);
                bR[i] = *(const float4*)(Bp + (long)(n0 + nn) * K + k0 + kq * 4);
            } else { int nq = f % (BN / 4), kk = f / (BN / 4);
                bR[i] = *(const float4*)(Bp + (long)(k0 + kk) * N + n0 + nq * 4);
            }
        }
    };

    auto storeS = [&](int buf) {
        float* sA_ = sm[buf];
        float* sB_ = sm[buf] + BM * BK;
        #pragma unroll
        for (int i = 0; i < AV; i++) {
            int f = t + i * NT;
            float v[4] = {aR[i].x, aR[i].y, aR[i].z, aR[i].w};
            if (TA) { int mq = f % (BM / 4), kk = f / (BM / 4);
                #pragma unroll
                for (int j = 0; j < 4; j++) sA_[offA<BM>(mq * 4 + j, kk)] = to_tf32(v[j]);
            } else { int kq = f % (BK / 4), mm = f / (BK / 4);
                #pragma unroll
                for (int j = 0; j < 4; j++) sA_[offA<BM>(mm, kq * 4 + j)] = to_tf32(v[j]);
            }
        }
        #pragma unroll
        for (int i = 0; i < BV; i++) {
            int f = t + i * NT;
            float v[4] = {bR[i].x, bR[i].y, bR[i].z, bR[i].w};
            if (TB) { int kq = f % (BK / 4), nn = f / (BK / 4);
                #pragma unroll
                for (int j = 0; j < 4; j++) sB_[offB<BN>(kq * 4 + j, nn)] = to_tf32(v[j]);
            } else { int nq = f % (BN / 4), kk = f / (BN / 4);
                #pragma unroll
                for (int j = 0; j < 4; j++) sB_[offB<BN>(kk, nq * 4 + j)] = to_tf32(v[j]);
            }
        }
    };

    auto compute = [&](int buf) {
        const float* sA_ = sm[buf];
        const float* sB_ = sm[buf] + BM * BK;
        #pragma unroll
        for (int ks = 0; ks < KS; ks++) {
            uint4 a[MT];
            uint2 b[NTW];
            #pragma unroll
            for (int mt = 0; mt < MT; mt++) {
                int fA = ks * (BM / 16) + (wm * MT + mt);
                a[mt] = *(const uint4*)(sA_ + swzA(lane << 2, fA));
            }
            #pragma unroll
            for (int nt = 0; nt < NTW; nt++) {
                int fB = ks * (BN / 8) + (wn * NTW + nt);
                b[nt] = *(const uint2*)(sB_ + swzB(lane << 1, fB));
            }
            #pragma unroll
            for (int mt = 0; mt < MT; mt++)
                #pragma unroll
                for (int nt = 0; nt < NTW; nt++)
                    mma8(acc[mt][nt], a[mt], b[nt]);
        }
    };

    const int nk = K / BK;
    loadG(0);
    storeS(0);
    __syncthreads();
    for (int it = 0; it < nk; ++it) {
        if (it + 1 < nk) loadG((it + 1) * BK);
        compute(it & 1);
        if (it + 1 < nk) {
            __syncthreads();
            storeS((it + 1) & 1);
            __syncthreads();
        }
    }

    #pragma unroll
    for (int mt = 0; mt < MT; mt++) {
        int gm = m0 + wm * WM + mt * 16 + grp;
        float b0 = bias ? bias[gm] : 0.f;
        float b1 = bias ? bias[gm + 8] : 0.f;
        #pragma unroll
        for (int nt = 0; nt < NTW; nt++) {
            int gn = n0 + wn * WN + nt * 8 + tig * 2;
            float4 ac = acc[mt][nt];
            float2 v0 = make_float2(ac.x * alpha + b0, ac.y * alpha + b0);
            float2 v1 = make_float2(ac.z * alpha + b1, ac.w * alpha + b1);
            *(float2*)(C + (long)gm * N + gn) = v0;
            *(float2*)(C + (long)(gm + 8) * N + gn) = v1;
        }
    }
}

// ---------------------------------------------------------------------------
// Flash attention: per (b*h, 128-q tile) block; loop 64-key tiles.
// q,k,v layout per head: (D=160 rows, S cols), row stride S.
// Writes attn in the same layout. Softmax online with running m/l.
// Warps: 4 along q (wm) x 2 along n (wn).
// ---------------------------------------------------------------------------
namespace fl {
constexpr int BQ = 128;
constexpr int BK = 64;
constexpr int SQ_OFF   = 0;                       // 20*8 frags *128 = 20480
constexpr int SK_OFF   = SQ_OFF + 20480;          // 20*8 frags *64 = 10240
constexpr int SV_OFF   = SK_OFF + 10240;          // 8*20 frags *64 = 10240
constexpr int SP_OFF   = SV_OFF + 10240;          // 8*8 frags *128 = 8192
constexpr int SMASK    = SP_OFF + 8192;           // 64
constexpr int RMAX     = SMASK + 64;              // 2*128
constexpr int RSUM     = RMAX + 256;              // 2*128
constexpr int MS       = RSUM + 256;              // 128
constexpr int LS       = MS + 128;                // 128
constexpr int AS       = LS + 128;                // 128
constexpr int NFLOAT   = AS + 128;
constexpr int SMEM_B   = NFLOAT * 4;              // ~196 KB
}

__global__ void __launch_bounds__(256, 1)
flash_kernel(const float* __restrict__ qg, const float* __restrict__ kg,
             const float* __restrict__ vg, const float* __restrict__ mask,
             float* __restrict__ og, float scale)
{
    using namespace cfg;
    extern __shared__ float sm[];

    const int qt = blockIdx.x;
    const int bh = blockIdx.y;
    const int b  = bh / H;
    const long base = (long)bh * D * S;
    const float* Q = qg + base;
    const float* K = kg + base;
    const float* V = vg + base;
    float*       O = og + base;
    const float* mrow = mask + (long)b * S;
    const int q0 = qt * fl::BQ;

    const int t = threadIdx.x, lane = t & 31, w = t >> 5;
    const int wm = w >> 1, wn = w & 1;
    const int grp = lane >> 2, tig = lane & 3;

    if (t < 128) { sm[fl::MS + t] = -1e30f; sm[fl::LS + t] = 0.f; }

    // stage Q once: A-fragments (m=q 128, k=d 160)
    #pragma unroll
    for (int i = 0; i < 20; i++) {
        int f = t + i * 256;
        int mq = f & 31, dd = f >> 5;
        float4 val = *(const float4*)(Q + (long)dd * S + q0 + mq * 4);
        float vv[4] = {val.x, val.y, val.z, val.w};
        #pragma unroll
        for (int j = 0; j < 4; j++)
            sm[fl::SQ_OFF + offA<128>(mq * 4 + j, dd)] = to_tf32(vv[j]);
    }
    __syncthreads();

    float4 oacc[2][10];
    #pragma unroll
    for (int i = 0; i < 2; i++)
        #pragma unroll
        for (int j = 0; j < 10; j++) oacc[i][j] = make_float4(0.f, 0.f, 0.f, 0.f);

    for (int kt = 0; kt < S / fl::BK; kt++) {
        const int k0 = kt * fl::BK;
        if (kt) __syncthreads();

        // stage K: B-fragments (n=kpos 64, k=d 160)
        #pragma unroll
        for (int i = 0; i < 10; i++) {
            int f = t + i * 256;
            int nq = f & 15, dd = f >> 4;
            float4 val = *(const float4*)(K + (long)dd * S + k0 + nq * 4);
            float vv[4] = {val.x, val.y, val.z, val.w};
            #pragma unroll
            for (int j = 0; j < 4; j++)
                sm[fl::SK_OFF + offB<64>(dd, nq * 4 + j)] = to_tf32(vv[j]);
        }
        // stage V: B-fragments (n=d 160, k=kpos 64)
        #pragma unroll
        for (int i = 0; i < 10; i++) {
            int f = t + i * 256;
            int kq = f & 15, dd = f >> 4;
            float4 val = *(const float4*)(V + (long)dd * S + k0 + kq * 4);
            float vv[4] = {val.x, val.y, val.z, val.w};
            #pragma unroll
            for (int j = 0; j < 4; j++)
                sm[fl::SV_OFF + offB<160>(kq * 4 + j, dd)] = to_tf32(vv[j]);
        }
        if (t < 64) sm[fl::SMASK + t] = mrow[k0 + t];
        __syncthreads();

        // GEMM1: S = Q^T K  (m=128, n=64, k=160)
        float4 sacc[2][4];
        #pragma unroll
        for (int i = 0; i < 2; i++)
            #pragma unroll
            for (int j = 0; j < 4; j++) sacc[i][j] = make_float4(0.f, 0.f, 0.f, 0.f);
        #pragma unroll
        for (int ks = 0; ks < 20; ks++) {
            uint4 a[2]; uint2 bf[4];
            #pragma unroll
            for (int mt = 0; mt < 2; mt++)
                a[mt] = *(const uint4*)(sm + fl::SQ_OFF + swzA(lane << 2, ks * 8 + wm * 2 + mt));
            #pragma unroll
            for (int nt = 0; nt < 4; nt++)
                bf[nt] = *(const uint2*)(sm + fl::SK_OFF + swzB(lane << 1, ks * 8 + wn * 4 + nt));
            #pragma unroll
            for (int mt = 0; mt < 2; mt++)
                #pragma unroll
                for (int nt = 0; nt < 4; nt++)
                    mma8(sacc[mt][nt], a[mt], bf[nt]);
        }

        // scale + mask; per-row max (warp part)
        float rmax[2][2];
        #pragma unroll
        for (int mt = 0; mt < 2; mt++) { rmax[mt][0] = -1e30f; rmax[mt][1] = -1e30f; }
        #pragma unroll
        for (int mt = 0; mt < 2; mt++)
            #pragma unroll
            for (int nt = 0; nt < 4; nt++) {
                int c = wn * 32 + nt * 8 + tig * 2;
                float m0v = sm[fl::SMASK + c], m1v = sm[fl::SMASK + c + 1];
                float4& sv = sacc[mt][nt];
                sv.x = sv.x * scale + m0v;  sv.y = sv.y * scale + m1v;
                sv.z = sv.z * scale + m0v;  sv.w = sv.w * scale + m1v;
                rmax[mt][0] = fmaxf(rmax[mt][0], fmaxf(sv.x, sv.y));
                rmax[mt][1] = fmaxf(rmax[mt][1], fmaxf(sv.z, sv.w));
            }
        #pragma unroll
        for (int o = 1; o <= 2; o <<= 1)
            #pragma unroll
            for (int mt = 0; mt < 2; mt++) {
                rmax[mt][0] = fmaxf(rmax[mt][0], __shfl_xor_sync(0xffffffffu, rmax[mt][0], o));
                rmax[mt][1] = fmaxf(rmax[mt][1], __shfl_xor_sync(0xffffffffu, rmax[mt][1], o));
            }
        if (tig == 0)
            #pragma unroll
            for (int mt = 0; mt < 2; mt++) {
                int r = wm * 32 + mt * 16 + grp;
                sm[fl::RMAX + wn * 128 + r]     = rmax[mt][0];
                sm[fl::RMAX + wn * 128 + r + 8] = rmax[mt][1];
            }
        __syncthreads();

        if (t < 128) {
            float mo = sm[fl::MS + t];
            float mn = fmaxf(mo, fmaxf(sm[fl::RMAX + t], sm[fl::RMAX + 128 + t]));
            sm[fl::MS + t] = mn;
            sm[fl::AS + t] = __expf(mo - mn);
        }
        __syncthreads();

        // p = exp(s - m); partial sums; store P into A-frag layout; rescale O
        float rsum[2][2] = {{0.f, 0.f}, {0.f, 0.f}};
        #pragma unroll
        for (int mt = 0; mt < 2; mt++) {
            int r0 = wm * 32 + mt * 16 + grp;
            float mn0 = sm[fl::MS + r0], mn1 = sm[fl::MS + r0 + 8];
            #pragma unroll
            for (int nt = 0; nt < 4; nt++) {
                float4 sv = sacc[mt][nt];
                float px = __expf(sv.x - mn0), py = __expf(sv.y - mn0);
                float pz = __expf(sv.z - mn1), pw = __expf(sv.w - mn1);
                rsum[mt][0] += px + py;
                rsum[mt][1] += pz + pw;
                int c = wn * 32 + nt * 8 + tig * 2;
                sm[fl::SP_OFF + offA<128>(r0, c)]         = px;
                sm[fl::SP_OFF + offA<128>(r0, c + 1)]     = py;
                sm[fl::SP_OFF + offA<128>(r0 + 8, c)]     = pz;
                sm[fl::SP_OFF + offA<128>(r0 + 8, c + 1)] = pw;
            }
            float a0 = sm[fl::AS + r0], a1 = sm[fl::AS + r0 + 8];
            #pragma unroll
            for (int nt2 = 0; nt2 < 10; nt2++) {
                oacc[mt][nt2].x *= a0;  oacc[mt][nt2].y *= a0;
                oacc[mt][nt2].z *= a1;  oacc[mt][nt2].w *= a1;
            }
        }
        #pragma unroll
        for (int o = 1; o <= 2; o <<= 1)
            #pragma unroll
            for (int mt = 0; mt < 2; mt++) {
                rsum[mt][0] += __shfl_xor_sync(0xffffffffu, rsum[mt][0], o);
                rsum[mt][1] += __shfl_xor_sync(0xffffffffu, rsum[mt][1], o);
            }
        if (tig == 0)
            #pragma unroll
            for (int mt = 0; mt < 2; mt++) {
                int r = wm * 32 + mt * 16 + grp;
                sm[fl::RSUM + wn * 128 + r]     = rsum[mt][0];
                sm[fl::RSUM + wn * 128 + r + 8] = rsum[mt][1];
            }
        __syncthreads();

        if (t < 128)
            sm[fl::LS + t] = sm[fl::LS + t] * sm[fl::AS + t]
                           + sm[fl::RSUM + t] + sm[fl::RSUM + 128 + t];

        // GEMM2: O += P * V^T  (m=128 q, n=160 d, k=64)
        #pragma unroll
        for (int ks2 = 0; ks2 < 8; ks2++) {
            uint4 a[2]; uint2 bf[10];
            #pragma unroll
            for (int mt = 0; mt < 2; mt++)
                a[mt] = *(const uint4*)(sm + fl::SP_OFF + swzA(lane << 2, ks2 * 8 + wm * 2 + mt));
            #pragma unroll
            for (int nt2 = 0; nt2 < 10; nt2++)
                bf[nt2] = *(const uint2*)(sm + fl::SV_OFF + swzB(lane << 1, ks2 * 20 + wn * 10 + nt2));
            #pragma unroll
            for (int mt = 0; mt < 2; mt++)
                #pragma unroll
                for (int nt2 = 0; nt2 < 10; nt2++)
                    mma8(oacc[mt][nt2], a[mt], bf[nt2]);
        }
    }
    __syncthreads();

    // epilogue: O[d, q] = oacc / l
    #pragma unroll
    for (int mt = 0; mt < 2; mt++) {
        int rloc = wm * 32 + mt * 16 + grp;
        int gq   = q0 + rloc;
        float il0 = 1.0f / sm[fl::LS + rloc];
        float il1 = 1.0f / sm[fl::LS + rloc + 8];
        #pragma unroll
        for (int nt2 = 0; nt2 < 10; nt2++) {
            int d = wn * 80 + nt2 * 8 + tig * 2;
            float4 oa = oacc[mt][nt2];
            O[(long)d * S + gq]           = oa.x * il0;
            O[(long)(d + 1) * S + gq]     = oa.y * il0;
            O[(long)d * S + gq + 8]       = oa.z * il1;
            O[(long)(d + 1) * S + gq + 8] = oa.w * il1;
        }
    }
}

// ---------------------------------------------------------------------------
extern "C" void kernel_launch(void* const* d_in, const int* in_sizes, int n_in,
                              void* d_out, int out_size)
{
    using namespace cfg;
    (void)in_sizes; (void)n_in; (void)out_size;

    const float* hidden  = (const float*)d_in[0];  // (B, QD, 1, S)
    const float* context = (const float*)d_in[1];
    const float* mask    = (const float*)d_in[2];  // (B, S, 1, 1)
    const float* Wq      = (const float*)d_in[3];  // (IN, QD)
    const float* Wk      = (const float*)d_in[4];
    const float* Wv      = (const float*)d_in[5];
    const float* Wout    = (const float*)d_in[6];  // (QD, IN)
    const float* bout    = (const float*)d_in[7];
    float*       out     = (float*)d_out;          // (B, QD, 1, S)

    void *pq, *pk, *pv, *pa;
    cudaGetSymbolAddress(&pq, g_q);
    cudaGetSymbolAddress(&pk, g_k);
    cudaGetSymbolAddress(&pv, g_v);
    cudaGetSymbolAddress(&pa, g_attn);
    float* q  = (float*)pq;
    float* k  = (float*)pk;
    float* v  = (float*)pv;
    float* at = (float*)pa;

    const float scale = 1.0f / sqrtf((float)D);

    cudaFuncSetAttribute(flash_kernel,
                         cudaFuncAttributeMaxDynamicSharedMemorySize, fl::SMEM_B);

    // projections: (1280x1280) * (1280x4096), batched over B
    dim3 gproj(S / 128, IN / 128, B);
    mma_gemm<128,128,16,64,32,false,false><<<gproj, 256>>>(
        Wq, hidden, q, IN, S, QD, 0, (long)QD * S, (long)IN * S, 1.f, nullptr);
    mma_gemm<128,128,16,64,32,false,false><<<gproj, 256>>>(
        Wk, context, k, IN, S, QD, 0, (long)QD * S, (long)IN * S, 1.f, nullptr);
    mma_gemm<128,128,16,64,32,false,false><<<gproj, 256>>>(
        Wv, context, v, IN, S, QD, 0, (long)QD * S, (long)IN * S, 1.f, nullptr);

    // fused attention: scores + mask + softmax + P*V
    dim3 gfl(S / fl::BQ, B * H);
    flash_kernel<<<gfl, 256, fl::SMEM_B>>>(q, k, v, mask, at, scale);

    // out = Wout * attn + bout
    dim3 gout(S / 128, QD / 128, B);
    mma_gemm<128,128,16,64,32,false,false><<<gout, 256>>>(
        Wout, at, out, QD, S, IN, 0, (long)IN * S, (long)QD * S, 1.f, bout);
}

// round 5
// speedup vs baseline: 3.6719x; 1.0072x over previous
#include <cuda_runtime.h>
#include <math.h>
#include <stdint.h>

// ---------------------------------------------------------------------------
// CrossAttention, round 5: warp-owned-row flash attention (zero-barrier
// softmax, cp.async double-buffered K/V) + TF32 mma projections.
// B=2, S=4096, H=8, D=160, QUERY_DIM=INNER=1280
// ---------------------------------------------------------------------------

namespace cfg {
constexpr int B  = 2;
constexpr int S  = 4096;
constexpr int H  = 8;
constexpr int D  = 160;
constexpr int QD = 1280;
constexpr int IN = 1280;
}

__device__ float g_q[(size_t)cfg::B * cfg::IN * cfg::S];
__device__ float g_k[(size_t)cfg::B * cfg::IN * cfg::S];
__device__ float g_v[(size_t)cfg::B * cfg::IN * cfg::S];
__device__ float g_attn[(size_t)cfg::B * cfg::IN * cfg::S];

__device__ __forceinline__ float to_tf32(float x) {
    float r; asm("cvt.rna.tf32.f32 %0, %1;" : "=f"(r) : "f"(x)); return r;
}

__device__ __forceinline__ void mma8(float4& d, const uint4& a, const uint2& b) {
    asm volatile(
        "mma.sync.aligned.m16n8k8.row.col.f32.tf32.tf32.f32 "
        "{%0,%1,%2,%3}, {%4,%5,%6,%7}, {%8,%9}, {%0,%1,%2,%3};\n"
        : "+f"(d.x), "+f"(d.y), "+f"(d.z), "+f"(d.w)
        : "r"(a.x), "r"(a.y), "r"(a.z), "r"(a.w), "r"(b.x), "r"(b.y));
}

// --- swizzled fragment-major shared layout (round-3, verified) -------------
__device__ __forceinline__ int swzA(int Loff, int fA) {
    return (fA << 7) + (Loff ^ ((((Loff >> 5) ^ fA) & 7) << 2));
}
template<int BM> __device__ __forceinline__ int offA(int m, int k) {
    int fA   = (k >> 3) * (BM / 16) + (m >> 4);
    int Loff = ((((m & 7) << 2) | (k & 3)) << 2)
             | ((m >> 3) & 1) | (((k >> 2) & 1) << 1);
    return swzA(Loff, fA);
}
__device__ __forceinline__ int swzB(int Loff, int fB) {
    return (fB << 6) + (Loff ^ (((fB ^ (fB >> 4)) & 15) << 1));
}
template<int BN> __device__ __forceinline__ int offB(int k, int n) {
    int fB   = (k >> 3) * (BN / 8) + (n >> 3);
    int Loff = ((((n & 7) << 2) | (k & 3)) << 1) | ((k >> 2) & 1);
    return swzB(Loff, fB);
}

// ---------------------------------------------------------------------------
// TF32 tensor-core GEMM (round 3) + CVT_OUT flag (tf32-round the outputs so
// downstream kernels can copy them raw with identical rounding semantics).
// ---------------------------------------------------------------------------
template<int BM, int BN, int BK, int WM, int WN, bool TA, bool TB, bool CVT_OUT>
__global__ void __launch_bounds__((BM / WM) * (BN / WN) * 32)
mma_gemm(const float* __restrict__ Ab, const float* __restrict__ Bb,
         float* __restrict__ Cb, int M, int N, int K,
         long sA, long sB, long sC, float alpha, const float* __restrict__ bias)
{
    constexpr int NWARP = (BM / WM) * (BN / WN);
    constexpr int NT    = NWARP * 32;
    constexpr int AV    = (BM * BK) / (NT * 4);
    constexpr int BV    = (BN * BK) / (NT * 4);
    constexpr int KS    = BK / 8;
    constexpr int MT    = WM / 16;
    constexpr int NTW   = WN / 8;

    __shared__ __align__(16) float sm[2][BM * BK + BN * BK];

    const float* A  = Ab + (long)blockIdx.z * sA;
    const float* Bp = Bb + (long)blockIdx.z * sB;
    float*       C  = Cb + (long)blockIdx.z * sC;

    const int m0 = blockIdx.y * BM;
    const int n0 = blockIdx.x * BN;
    const int t = threadIdx.x, lane = t & 31, w = t >> 5;
    const int wn = w % (BN / WN), wm = w / (BN / WN);
    const int grp = lane >> 2, tig = lane & 3;

    float4 acc[MT][NTW];
    #pragma unroll
    for (int i = 0; i < MT; i++)
        #pragma unroll
        for (int j = 0; j < NTW; j++) acc[i][j] = make_float4(0.f, 0.f, 0.f, 0.f);

    float4 aR[AV], bR[BV];

    auto loadG = [&](int k0) {
        #pragma unroll
        for (int i = 0; i < AV; i++) {
            int f = t + i * NT;
            if (TA) { int mq = f % (BM / 4), kk = f / (BM / 4);
                aR[i] = *(const float4*)(A + (long)(k0 + kk) * M + m0 + mq * 4);
            } else { int kq = f % (BK / 4), mm = f / (BK / 4);
                aR[i] = *(const float4*)(A + (long)(m0 + mm) * K + k0 + kq * 4);
            }
        }
        #pragma unroll
        for (int i = 0; i < BV; i++) {
            int f = t + i * NT;
            if (TB) { int kq = f % (BK / 4), nn = f / (BK / 4);
                bR[i] = *(const float4*)(Bp + (long)(n0 + nn) * K + k0 + kq * 4);
            } else { int nq = f % (BN / 4), kk = f / (BN / 4);
                bR[i] = *(const float4*)(Bp + (long)(k0 + kk) * N + n0 + nq * 4);
            }
        }
    };

    auto storeS = [&](int buf) {
        float* sA_ = sm[buf];
        float* sB_ = sm[buf] + BM * BK;
        #pragma unroll
        for (int i = 0; i < AV; i++) {
            int f = t + i * NT;
            float v[4] = {aR[i].x, aR[i].y, aR[i].z, aR[i].w};
            if (TA) { int mq = f % (BM / 4), kk = f / (BM / 4);
                #pragma unroll
                for (int j = 0; j < 4; j++) sA_[offA<BM>(mq * 4 + j, kk)] = to_tf32(v[j]);
            } else { int kq = f % (BK / 4), mm = f / (BK / 4);
                #pragma unroll
                for (int j = 0; j < 4; j++) sA_[offA<BM>(mm, kq * 4 + j)] = to_tf32(v[j]);
            }
        }
        #pragma unroll
        for (int i = 0; i < BV; i++) {
            int f = t + i * NT;
            float v[4] = {bR[i].x, bR[i].y, bR[i].z, bR[i].w};
            if (TB) { int kq = f % (BK / 4), nn = f / (BK / 4);
                #pragma unroll
                for (int j = 0; j < 4; j++) sB_[offB<BN>(kq * 4 + j, nn)] = to_tf32(v[j]);
            } else { int nq = f % (BN / 4), kk = f / (BN / 4);
                #pragma unroll
                for (int j = 0; j < 4; j++) sB_[offB<BN>(kk, nq * 4 + j)] = to_tf32(v[j]);
            }
        }
    };

    auto compute = [&](int buf) {
        const float* sA_ = sm[buf];
        const float* sB_ = sm[buf] + BM * BK;
        #pragma unroll
        for (int ks = 0; ks < KS; ks++) {
            uint4 a[MT];
            uint2 b[NTW];
            #pragma unroll
            for (int mt = 0; mt < MT; mt++) {
                int fA = ks * (BM / 16) + (wm * MT + mt);
                a[mt] = *(const uint4*)(sA_ + swzA(lane << 2, fA));
            }
            #pragma unroll
            for (int nt = 0; nt < NTW; nt++) {
                int fB = ks * (BN / 8) + (wn * NTW + nt);
                b[nt] = *(const uint2*)(sB_ + swzB(lane << 1, fB));
            }
            #pragma unroll
            for (int mt = 0; mt < MT; mt++)
                #pragma unroll
                for (int nt = 0; nt < NTW; nt++)
                    mma8(acc[mt][nt], a[mt], b[nt]);
        }
    };

    const int nk = K / BK;
    loadG(0);
    storeS(0);
    __syncthreads();
    for (int it = 0; it < nk; ++it) {
        if (it + 1 < nk) loadG((it + 1) * BK);
        compute(it & 1);
        if (it + 1 < nk) {
            __syncthreads();
            storeS((it + 1) & 1);
            __syncthreads();
        }
    }

    #pragma unroll
    for (int mt = 0; mt < MT; mt++) {
        int gm = m0 + wm * WM + mt * 16 + grp;
        float b0 = bias ? bias[gm] : 0.f;
        float b1 = bias ? bias[gm + 8] : 0.f;
        #pragma unroll
        for (int nt = 0; nt < NTW; nt++) {
            int gn = n0 + wn * WN + nt * 8 + tig * 2;
            float4 ac = acc[mt][nt];
            float o0 = ac.x * alpha + b0, o1 = ac.y * alpha + b0;
            float o2 = ac.z * alpha + b1, o3 = ac.w * alpha + b1;
            if (CVT_OUT) { o0 = to_tf32(o0); o1 = to_tf32(o1);
                           o2 = to_tf32(o2); o3 = to_tf32(o3); }
            *(float2*)(C + (long)gm * N + gn)       = make_float2(o0, o1);
            *(float2*)(C + (long)(gm + 8) * N + gn) = make_float2(o2, o3);
        }
    }
}

// ---------------------------------------------------------------------------
// Flash attention v2: CTA = 128 threads (4 warps), BQ=128 (warp owns 32 rows),
// BK=32 keys/tile, cp.async double-buffered K/V, one __syncthreads per tile.
// Softmax entirely in registers (4-lane shfl reductions). Inputs pre-rounded
// to tf32 by the projection epilogue, so staging is a raw copy.
// K tile smem: d-row-major, stride 40 (8*tig+grp distinct mod 32 -> no bank
// conflicts). V tile: d-row-major, stride 36 (4*grp+tig distinct mod 32).
// ---------------------------------------------------------------------------
namespace f2 {
constexpr int BQ   = 128;
constexpr int BK   = 32;
constexpr int NTLE = cfg::S / BK;       // 128
constexpr int QSZ  = 20480;             // 128 x 160 A-frags
constexpr int KSTR = 40;
constexpr int VSTR = 36;
constexpr int KSZ  = 160 * KSTR;        // 6400
constexpr int VSZ  = 160 * VSTR;        // 5760
constexpr int MSZ  = 32;
constexpr int STG  = KSZ + VSZ + MSZ;   // 12192
constexpr int SMEM = (QSZ + 2 * STG) * 4;  // 178,688 B
}

__global__ void __launch_bounds__(128, 1)
flash2(const float* __restrict__ qg, const float* __restrict__ kg,
       const float* __restrict__ vg, const float* __restrict__ mask,
       float* __restrict__ og, float scale)
{
    using namespace cfg;
    extern __shared__ float sm[];

    const int qt = blockIdx.x, bh = blockIdx.y, b = bh / H;
    const long base = (long)bh * D * S;
    const float *Q = qg + base, *K = kg + base, *V = vg + base;
    float* O = og + base;
    const float* mrow = mask + (long)b * S;
    const int q0 = qt * f2::BQ;

    const int t = threadIdx.x, lane = t & 31, w = t >> 5;
    const int grp = lane >> 2, tig = lane & 3;

    // ---- stage Q once (values already tf32-rounded) ----
    #pragma unroll
    for (int i = 0; i < 40; i++) {
        int f = t + i * 128;
        int mq = f & 31, dd = f >> 5;
        float4 val = *(const float4*)(Q + (long)dd * S + q0 + mq * 4);
        float vv[4] = {val.x, val.y, val.z, val.w};
        #pragma unroll
        for (int j = 0; j < 4; j++)
            sm[offA<128>(mq * 4 + j, dd)] = vv[j];
    }

    auto stage = [&](int tile, int p) {
        float* dst = sm + f2::QSZ + p * f2::STG;
        const int k0 = tile * f2::BK;
        uint32_t kb = (uint32_t)__cvta_generic_to_shared(dst);
        uint32_t vb = kb + f2::KSZ * 4;
        uint32_t mb = vb + f2::VSZ * 4;
        #pragma unroll
        for (int i = 0; i < 10; i++) {
            int f = t + i * 128;
            int kq = (f & 7) * 4, dd = f >> 3;
            const float* src = K + (long)dd * S + k0 + kq;
            asm volatile("cp.async.cg.shared.global [%0], [%1], 16;\n"
                         :: "r"(kb + (uint32_t)(dd * f2::KSTR + kq) * 4), "l"(src));
        }
        #pragma unroll
        for (int i = 0; i < 10; i++) {
            int f = t + i * 128;
            int kq = (f & 7) * 4, dd = f >> 3;
            const float* src = V + (long)dd * S + k0 + kq;
            asm volatile("cp.async.cg.shared.global [%0], [%1], 16;\n"
                         :: "r"(vb + (uint32_t)(dd * f2::VSTR + kq) * 4), "l"(src));
        }
        if (t < 8) {
            const float* src = mrow + k0 + t * 4;
            asm volatile("cp.async.cg.shared.global [%0], [%1], 16;\n"
                         :: "r"(mb + (uint32_t)t * 16), "l"(src));
        }
        asm volatile("cp.async.commit_group;\n");
    };

    float4 oacc[2][20];
    #pragma unroll
    for (int i = 0; i < 2; i++)
        #pragma unroll
        for (int j = 0; j < 20; j++) oacc[i][j] = make_float4(0.f, 0.f, 0.f, 0.f);
    float mrun[2][2] = {{-1e30f, -1e30f}, {-1e30f, -1e30f}};
    float lrun[2][2] = {{0.f, 0.f}, {0.f, 0.f}};

    stage(0, 0);

    for (int it = 0; it < f2::NTLE; it++) {
        const int p = it & 1;
        asm volatile("cp.async.wait_group 0;\n" ::: "memory");
        __syncthreads();
        if (it + 1 < f2::NTLE) stage(it + 1, p ^ 1);

        const float* Kb = sm + f2::QSZ + p * f2::STG;
        const float* Vb = Kb + f2::KSZ;
        const float* Mb = Vb + f2::VSZ;

        // ---- GEMM1: scores(32q x 32k) per warp ----
        float4 sacc[2][4];
        #pragma unroll
        for (int i = 0; i < 2; i++)
            #pragma unroll
            for (int j = 0; j < 4; j++) sacc[i][j] = make_float4(0.f, 0.f, 0.f, 0.f);
        #pragma unroll
        for (int ks = 0; ks < 20; ks++) {
            uint4 a0 = *(const uint4*)(sm + swzA(lane << 2, ks * 8 + w * 2));
            uint4 a1 = *(const uint4*)(sm + swzA(lane << 2, ks * 8 + w * 2 + 1));
            const float* kr = Kb + (ks * 8 + tig) * f2::KSTR + grp;
            #pragma unroll
            for (int nt = 0; nt < 4; nt++) {
                uint2 bf = make_uint2(__float_as_uint(kr[nt * 8]),
                                      __float_as_uint(kr[nt * 8 + 4 * f2::KSTR]));
                mma8(sacc[0][nt], a0, bf);
                mma8(sacc[1][nt], a1, bf);
            }
        }

        // ---- softmax: pure register/warp-shuffle, rows owned by this warp ----
        #pragma unroll
        for (int mt = 0; mt < 2; mt++) {
            float r0 = -1e30f, r1 = -1e30f;
            #pragma unroll
            for (int nt = 0; nt < 4; nt++) {
                float mv0 = Mb[nt * 8 + tig * 2];
                float mv1 = Mb[nt * 8 + tig * 2 + 1];
                float4& s = sacc[mt][nt];
                s.x = fmaf(s.x, scale, mv0);  s.y = fmaf(s.y, scale, mv1);
                s.z = fmaf(s.z, scale, mv0);  s.w = fmaf(s.w, scale, mv1);
                r0 = fmaxf(r0, fmaxf(s.x, s.y));
                r1 = fmaxf(r1, fmaxf(s.z, s.w));
            }
            r0 = fmaxf(r0, __shfl_xor_sync(0xffffffffu, r0, 1));
            r0 = fmaxf(r0, __shfl_xor_sync(0xffffffffu, r0, 2));
            r1 = fmaxf(r1, __shfl_xor_sync(0xffffffffu, r1, 1));
            r1 = fmaxf(r1, __shfl_xor_sync(0xffffffffu, r1, 2));
            float mn0 = fmaxf(mrun[mt][0], r0);
            float mn1 = fmaxf(mrun[mt][1], r1);
            float a0 = __expf(mrun[mt][0] - mn0);
            float a1 = __expf(mrun[mt][1] - mn1);
            mrun[mt][0] = mn0;  mrun[mt][1] = mn1;

            float su0 = 0.f, su1 = 0.f;
            #pragma unroll
            for (int nt = 0; nt < 4; nt++) {
                float4& s = sacc[mt][nt];
                s.x = __expf(s.x - mn0);  s.y = __expf(s.y - mn0);
                s.z = __expf(s.z - mn1);  s.w = __expf(s.w - mn1);
                su0 += s.x + s.y;  su1 += s.z + s.w;
            }
            su0 += __shfl_xor_sync(0xffffffffu, su0, 1);
            su0 += __shfl_xor_sync(0xffffffffu, su0, 2);
            su1 += __shfl_xor_sync(0xffffffffu, su1, 1);
            su1 += __shfl_xor_sync(0xffffffffu, su1, 2);
            lrun[mt][0] = lrun[mt][0] * a0 + su0;
            lrun[mt][1] = lrun[mt][1] * a1 + su1;
            #pragma unroll
            for (int nf = 0; nf < 20; nf++) {
                oacc[mt][nf].x *= a0;  oacc[mt][nf].y *= a0;
                oacc[mt][nf].z *= a1;  oacc[mt][nf].w *= a1;
            }
        }

        // ---- GEMM2: O += P * V^T, P converted acc-layout -> A-layout via shfl
        #pragma unroll
        for (int ks2 = 0; ks2 < 4; ks2++) {
            uint4 pa[2];
            const int src = (lane & ~3) | (tig >> 1);
            #pragma unroll
            for (int mt = 0; mt < 2; mt++) {
                float4 c = sacc[mt][ks2];
                float s0  = __shfl_sync(0xffffffffu, c.x, src);
                float s1  = __shfl_sync(0xffffffffu, c.y, src);
                float s0b = __shfl_sync(0xffffffffu, c.x, src + 2);
                float s1b = __shfl_sync(0xffffffffu, c.y, src + 2);
                float A0 = (tig & 1) ? s1 : s0;
                float A2 = (tig & 1) ? s1b : s0b;
                s0  = __shfl_sync(0xffffffffu, c.z, src);
                s1  = __shfl_sync(0xffffffffu, c.w, src);
                s0b = __shfl_sync(0xffffffffu, c.z, src + 2);
                s1b = __shfl_sync(0xffffffffu, c.w, src + 2);
                float A1 = (tig & 1) ? s1 : s0;
                float A3 = (tig & 1) ? s1b : s0b;
                pa[mt] = make_uint4(__float_as_uint(A0), __float_as_uint(A1),
                                    __float_as_uint(A2), __float_as_uint(A3));
            }
            const float* vr = Vb + ks2 * 8 + tig;
            #pragma unroll
            for (int nf = 0; nf < 20; nf++) {
                uint2 bf = make_uint2(
                    __float_as_uint(vr[(nf * 8 + grp) * f2::VSTR]),
                    __float_as_uint(vr[(nf * 8 + grp) * f2::VSTR + 4]));
                mma8(oacc[0][nf], pa[0], bf);
                mma8(oacc[1][nf], pa[1], bf);
            }
        }
    }

    // ---- epilogue: O[d, q] = oacc / l ----
    #pragma unroll
    for (int mt = 0; mt < 2; mt++) {
        int r0 = w * 32 + mt * 16 + grp;
        int gq = q0 + r0;
        float il0 = 1.0f / lrun[mt][0];
        float il1 = 1.0f / lrun[mt][1];
        #pragma unroll
        for (int nf = 0; nf < 20; nf++) {
            int d = nf * 8 + tig * 2;
            float4 oa = oacc[mt][nf];
            O[(long)d * S + gq]           = oa.x * il0;
            O[(long)(d + 1) * S + gq]     = oa.y * il0;
            O[(long)d * S + gq + 8]       = oa.z * il1;
            O[(long)(d + 1) * S + gq + 8] = oa.w * il1;
        }
    }
}

// ---------------------------------------------------------------------------
extern "C" void kernel_launch(void* const* d_in, const int* in_sizes, int n_in,
                              void* d_out, int out_size)
{
    using namespace cfg;
    (void)in_sizes; (void)n_in; (void)out_size;

    const float* hidden  = (const float*)d_in[0];  // (B, QD, 1, S)
    const float* context = (const float*)d_in[1];
    const float* mask    = (const float*)d_in[2];  // (B, S, 1, 1)
    const float* Wq      = (const float*)d_in[3];  // (IN, QD)
    const float* Wk      = (const float*)d_in[4];
    const float* Wv      = (const float*)d_in[5];
    const float* Wout    = (const float*)d_in[6];  // (QD, IN)
    const float* bout    = (const float*)d_in[7];
    float*       out     = (float*)d_out;          // (B, QD, 1, S)

    void *pq, *pk, *pv, *pa;
    cudaGetSymbolAddress(&pq, g_q);
    cudaGetSymbolAddress(&pk, g_k);
    cudaGetSymbolAddress(&pv, g_v);
    cudaGetSymbolAddress(&pa, g_attn);
    float* q  = (float*)pq;
    float* k  = (float*)pk;
    float* v  = (float*)pv;
    float* at = (float*)pa;

    const float scale = 1.0f / sqrtf((float)D);

    cudaFuncSetAttribute(flash2,
                         cudaFuncAttributeMaxDynamicSharedMemorySize, f2::SMEM);

    // projections: (1280x1280) * (1280x4096), batched over B. CVT_OUT=true:
    // outputs are tf32-rounded so flash2 can copy them raw.
    dim3 gproj(S / 128, IN / 128, B);
    mma_gemm<128,128,16,64,32,false,false,true><<<gproj, 256>>>(
        Wq, hidden, q, IN, S, QD, 0, (long)QD * S, (long)IN * S, 1.f, nullptr);
    mma_gemm<128,128,16,64,32,false,false,true><<<gproj, 256>>>(
        Wk, context, k, IN, S, QD, 0, (long)QD * S, (long)IN * S, 1.f, nullptr);
    mma_gemm<128,128,16,64,32,false,false,true><<<gproj, 256>>>(
        Wv, context, v, IN, S, QD, 0, (long)QD * S, (long)IN * S, 1.f, nullptr);

    // fused attention
    dim3 gfl(S / f2::BQ, B * H);
    flash2<<<gfl, 128, f2::SMEM>>>(q, k, v, mask, at, scale);

    // out = Wout * attn + bout
    dim3 gout(S / 128, QD / 128, B);
    mma_gemm<128,128,16,64,32,false,false,false><<<gout, 256>>>(
        Wout, at, out, QD, S, IN, 0, (long)IN * S, (long)QD * S, 1.f, bout);
}

// round 6
// speedup vs baseline: 4.6951x; 1.2787x over previous
#include <cuda_runtime.h>
#include <math.h>
#include <stdint.h>

// ---------------------------------------------------------------------------
// CrossAttention, round 6: flash attention with 8 warps x 16 q-rows
// (2 warps/SMSP; round 5 ran 1 warp/SMSP and was issue-starved).
// B=2, S=4096, H=8, D=160, QUERY_DIM=INNER=1280
// ---------------------------------------------------------------------------

namespace cfg {
constexpr int B  = 2;
constexpr int S  = 4096;
constexpr int H  = 8;
constexpr int D  = 160;
constexpr int QD = 1280;
constexpr int IN = 1280;
}

__device__ float g_q[(size_t)cfg::B * cfg::IN * cfg::S];
__device__ float g_k[(size_t)cfg::B * cfg::IN * cfg::S];
__device__ float g_v[(size_t)cfg::B * cfg::IN * cfg::S];
__device__ float g_attn[(size_t)cfg::B * cfg::IN * cfg::S];

__device__ __forceinline__ float to_tf32(float x) {
    float r; asm("cvt.rna.tf32.f32 %0, %1;" : "=f"(r) : "f"(x)); return r;
}

__device__ __forceinline__ void mma8(float4& d, const uint4& a, const uint2& b) {
    asm volatile(
        "mma.sync.aligned.m16n8k8.row.col.f32.tf32.tf32.f32 "
        "{%0,%1,%2,%3}, {%4,%5,%6,%7}, {%8,%9}, {%0,%1,%2,%3};\n"
        : "+f"(d.x), "+f"(d.y), "+f"(d.z), "+f"(d.w)
        : "r"(a.x), "r"(a.y), "r"(a.z), "r"(a.w), "r"(b.x), "r"(b.y));
}

// --- swizzled fragment-major shared layout (round-3, verified) -------------
__device__ __forceinline__ int swzA(int Loff, int fA) {
    return (fA << 7) + (Loff ^ ((((Loff >> 5) ^ fA) & 7) << 2));
}
template<int BM> __device__ __forceinline__ int offA(int m, int k) {
    int fA   = (k >> 3) * (BM / 16) + (m >> 4);
    int Loff = ((((m & 7) << 2) | (k & 3)) << 2)
             | ((m >> 3) & 1) | (((k >> 2) & 1) << 1);
    return swzA(Loff, fA);
}
__device__ __forceinline__ int swzB(int Loff, int fB) {
    return (fB << 6) + (Loff ^ (((fB ^ (fB >> 4)) & 15) << 1));
}
template<int BN> __device__ __forceinline__ int offB(int k, int n) {
    int fB   = (k >> 3) * (BN / 8) + (n >> 3);
    int Loff = ((((n & 7) << 2) | (k & 3)) << 1) | ((k >> 2) & 1);
    return swzB(Loff, fB);
}

// ---------------------------------------------------------------------------
// TF32 tensor-core GEMM (round 3) + CVT_OUT flag.
// ---------------------------------------------------------------------------
template<int BM, int BN, int BK, int WM, int WN, bool TA, bool TB, bool CVT_OUT>
__global__ void __launch_bounds__((BM / WM) * (BN / WN) * 32)
mma_gemm(const float* __restrict__ Ab, const float* __restrict__ Bb,
         float* __restrict__ Cb, int M, int N, int K,
         long sA, long sB, long sC, float alpha, const float* __restrict__ bias)
{
    constexpr int NWARP = (BM / WM) * (BN / WN);
    constexpr int NT    = NWARP * 32;
    constexpr int AV    = (BM * BK) / (NT * 4);
    constexpr int BV    = (BN * BK) / (NT * 4);
    constexpr int KS    = BK / 8;
    constexpr int MT    = WM / 16;
    constexpr int NTW   = WN / 8;

    __shared__ __align__(16) float sm[2][BM * BK + BN * BK];

    const float* A  = Ab + (long)blockIdx.z * sA;
    const float* Bp = Bb + (long)blockIdx.z * sB;
    float*       C  = Cb + (long)blockIdx.z * sC;

    const int m0 = blockIdx.y * BM;
    const int n0 = blockIdx.x * BN;
    const int t = threadIdx.x, lane = t & 31, w = t >> 5;
    const int wn = w % (BN / WN), wm = w / (BN / WN);
    const int grp = lane >> 2, tig = lane & 3;

    float4 acc[MT][NTW];
    #pragma unroll
    for (int i = 0; i < MT; i++)
        #pragma unroll
        for (int j = 0; j < NTW; j++) acc[i][j] = make_float4(0.f, 0.f, 0.f, 0.f);

    float4 aR[AV], bR[BV];

    auto loadG = [&](int k0) {
        #pragma unroll
        for (int i = 0; i < AV; i++) {
            int f = t + i * NT;
            if (TA) { int mq = f % (BM / 4), kk = f / (BM / 4);
                aR[i] = *(const float4*)(A + (long)(k0 + kk) * M + m0 + mq * 4);
            } else { int kq = f % (BK / 4), mm = f / (BK / 4);
                aR[i] = *(const float4*)(A + (long)(m0 + mm) * K + k0 + kq * 4);
            }
        }
        #pragma unroll
        for (int i = 0; i < BV; i++) {
            int f = t + i * NT;
            if (TB) { int kq = f % (BK / 4), nn = f / (BK / 4);
                bR[i] = *(const float4*)(Bp + (long)(n0 + nn) * K + k0 + kq * 4);
            } else { int nq = f % (BN / 4), kk = f / (BN / 4);
                bR[i] = *(const float4*)(Bp + (long)(k0 + kk) * N + n0 + nq * 4);
            }
        }
    };

    auto storeS = [&](int buf) {
        float* sA_ = sm[buf];
        float* sB_ = sm[buf] + BM * BK;
        #pragma unroll
        for (int i = 0; i < AV; i++) {
            int f = t + i * NT;
            float v[4] = {aR[i].x, aR[i].y, aR[i].z, aR[i].w};
            if (TA) { int mq = f % (BM / 4), kk = f / (BM / 4);
                #pragma unroll
                for (int j = 0; j < 4; j++) sA_[offA<BM>(mq * 4 + j, kk)] = to_tf32(v[j]);
            } else { int kq = f % (BK / 4), mm = f / (BK / 4);
                #pragma unroll
                for (int j = 0; j < 4; j++) sA_[offA<BM>(mm, kq * 4 + j)] = to_tf32(v[j]);
            }
        }
        #pragma unroll
        for (int i = 0; i < BV; i++) {
            int f = t + i * NT;
            float v[4] = {bR[i].x, bR[i].y, bR[i].z, bR[i].w};
            if (TB) { int kq = f % (BK / 4), nn = f / (BK / 4);
                #pragma unroll
                for (int j = 0; j < 4; j++) sB_[offB<BN>(kq * 4 + j, nn)] = to_tf32(v[j]);
            } else { int nq = f % (BN / 4), kk = f / (BN / 4);
                #pragma unroll
                for (int j = 0; j < 4; j++) sB_[offB<BN>(kk, nq * 4 + j)] = to_tf32(v[j]);
            }
        }
    };

    auto compute = [&](int buf) {
        const float* sA_ = sm[buf];
        const float* sB_ = sm[buf] + BM * BK;
        #pragma unroll
        for (int ks = 0; ks < KS; ks++) {
            uint4 a[MT];
            uint2 b[NTW];
            #pragma unroll
            for (int mt = 0; mt < MT; mt++) {
                int fA = ks * (BM / 16) + (wm * MT + mt);
                a[mt] = *(const uint4*)(sA_ + swzA(lane << 2, fA));
            }
            #pragma unroll
            for (int nt = 0; nt < NTW; nt++) {
                int fB = ks * (BN / 8) + (wn * NTW + nt);
                b[nt] = *(const uint2*)(sB_ + swzB(lane << 1, fB));
            }
            #pragma unroll
            for (int mt = 0; mt < MT; mt++)
                #pragma unroll
                for (int nt = 0; nt < NTW; nt++)
                    mma8(acc[mt][nt], a[mt], b[nt]);
        }
    };

    const int nk = K / BK;
    loadG(0);
    storeS(0);
    __syncthreads();
    for (int it = 0; it < nk; ++it) {
        if (it + 1 < nk) loadG((it + 1) * BK);
        compute(it & 1);
        if (it + 1 < nk) {
            __syncthreads();
            storeS((it + 1) & 1);
            __syncthreads();
        }
    }

    #pragma unroll
    for (int mt = 0; mt < MT; mt++) {
        int gm = m0 + wm * WM + mt * 16 + grp;
        float b0 = bias ? bias[gm] : 0.f;
        float b1 = bias ? bias[gm + 8] : 0.f;
        #pragma unroll
        for (int nt = 0; nt < NTW; nt++) {
            int gn = n0 + wn * WN + nt * 8 + tig * 2;
            float4 ac = acc[mt][nt];
            float o0 = ac.x * alpha + b0, o1 = ac.y * alpha + b0;
            float o2 = ac.z * alpha + b1, o3 = ac.w * alpha + b1;
            if (CVT_OUT) { o0 = to_tf32(o0); o1 = to_tf32(o1);
                           o2 = to_tf32(o2); o3 = to_tf32(o3); }
            *(float2*)(C + (long)gm * N + gn)       = make_float2(o0, o1);
            *(float2*)(C + (long)(gm + 8) * N + gn) = make_float2(o2, o3);
        }
    }
}

// ---------------------------------------------------------------------------
// Flash attention v3: 256 threads (8 warps), BQ=128 -> each warp owns 16 q
// rows, BK=32 keys/tile, cp.async double-buffered K/V, one barrier per tile,
// softmax entirely in registers. Inputs pre-rounded to tf32 upstream.
// K smem: d-row-major stride 40 (conflict-free for 8*tig+grp access).
// V smem: d-row-major stride 36 (conflict-free for 4*grp+tig access).
// ---------------------------------------------------------------------------
namespace f2 {
constexpr int BQ   = 128;
constexpr int BK   = 32;
constexpr int NTLE = cfg::S / BK;       // 128
constexpr int QSZ  = 20480;             // 128 x 160 A-frags
constexpr int KSTR = 40;
constexpr int VSTR = 36;
constexpr int KSZ  = 160 * KSTR;        // 6400
constexpr int VSZ  = 160 * VSTR;        // 5760
constexpr int MSZ  = 32;
constexpr int STG  = KSZ + VSZ + MSZ;   // 12192
constexpr int SMEM = (QSZ + 2 * STG) * 4;  // 178,688 B
}

__global__ void __launch_bounds__(256, 1)
flash2(const float* __restrict__ qg, const float* __restrict__ kg,
       const float* __restrict__ vg, const float* __restrict__ mask,
       float* __restrict__ og, float scale)
{
    using namespace cfg;
    extern __shared__ float sm[];

    const int qt = blockIdx.x, bh = blockIdx.y, b = bh / H;
    const long base = (long)bh * D * S;
    const float *Q = qg + base, *K = kg + base, *V = vg + base;
    float* O = og + base;
    const float* mrow = mask + (long)b * S;
    const int q0 = qt * f2::BQ;

    const int t = threadIdx.x, lane = t & 31, w = t >> 5;
    const int grp = lane >> 2, tig = lane & 3;

    // ---- stage Q once (values already tf32-rounded) ----
    #pragma unroll
    for (int i = 0; i < 20; i++) {
        int f = t + i * 256;
        int mq = f & 31, dd = f >> 5;
        float4 val = *(const float4*)(Q + (long)dd * S + q0 + mq * 4);
        float vv[4] = {val.x, val.y, val.z, val.w};
        #pragma unroll
        for (int j = 0; j < 4; j++)
            sm[offA<128>(mq * 4 + j, dd)] = vv[j];
    }

    auto stage = [&](int tile, int p) {
        float* dst = sm + f2::QSZ + p * f2::STG;
        const int k0 = tile * f2::BK;
        uint32_t kb = (uint32_t)__cvta_generic_to_shared(dst);
        uint32_t vb = kb + f2::KSZ * 4;
        uint32_t mb = vb + f2::VSZ * 4;
        #pragma unroll
        for (int i = 0; i < 5; i++) {
            int f = t + i * 256;
            int kq = (f & 7) * 4, dd = f >> 3;
            const float* src = K + (long)dd * S + k0 + kq;
            asm volatile("cp.async.cg.shared.global [%0], [%1], 16;\n"
                         :: "r"(kb + (uint32_t)(dd * f2::KSTR + kq) * 4), "l"(src));
        }
        #pragma unroll
        for (int i = 0; i < 5; i++) {
            int f = t + i * 256;
            int kq = (f & 7) * 4, dd = f >> 3;
            const float* src = V + (long)dd * S + k0 + kq;
            asm volatile("cp.async.cg.shared.global [%0], [%1], 16;\n"
                         :: "r"(vb + (uint32_t)(dd * f2::VSTR + kq) * 4), "l"(src));
        }
        if (t < 8) {
            const float* src = mrow + k0 + t * 4;
            asm volatile("cp.async.cg.shared.global [%0], [%1], 16;\n"
                         :: "r"(mb + (uint32_t)t * 16), "l"(src));
        }
        asm volatile("cp.async.commit_group;\n");
    };

    float4 oacc[20];
    #pragma unroll
    for (int j = 0; j < 20; j++) oacc[j] = make_float4(0.f, 0.f, 0.f, 0.f);
    float mrun0 = -1e30f, mrun1 = -1e30f;
    float lrun0 = 0.f, lrun1 = 0.f;

    stage(0, 0);

    for (int it = 0; it < f2::NTLE; it++) {
        const int p = it & 1;
        asm volatile("cp.async.wait_group 0;\n" ::: "memory");
        __syncthreads();
        if (it + 1 < f2::NTLE) stage(it + 1, p ^ 1);

        const float* Kb = sm + f2::QSZ + p * f2::STG;
        const float* Vb = Kb + f2::KSZ;
        const float* Mb = Vb + f2::VSZ;

        // ---- GEMM1: scores(16q x 32k) for this warp's rows ----
        float4 sacc[4];
        #pragma unroll
        for (int j = 0; j < 4; j++) sacc[j] = make_float4(0.f, 0.f, 0.f, 0.f);
        #pragma unroll
        for (int ks = 0; ks < 20; ks++) {
            uint4 a0 = *(const uint4*)(sm + swzA(lane << 2, ks * 8 + w));
            const float* kr = Kb + (ks * 8 + tig) * f2::KSTR + grp;
            #pragma unroll
            for (int nt = 0; nt < 4; nt++) {
                uint2 bf = make_uint2(__float_as_uint(kr[nt * 8]),
                                      __float_as_uint(kr[nt * 8 + 4 * f2::KSTR]));
                mma8(sacc[nt], a0, bf);
            }
        }

        // ---- softmax: pure register/warp-shuffle (rows owned by this warp) --
        {
            float r0 = -1e30f, r1 = -1e30f;
            #pragma unroll
            for (int nt = 0; nt < 4; nt++) {
                float mv0 = Mb[nt * 8 + tig * 2];
                float mv1 = Mb[nt * 8 + tig * 2 + 1];
                float4& s = sacc[nt];
                s.x = fmaf(s.x, scale, mv0);  s.y = fmaf(s.y, scale, mv1);
                s.z = fmaf(s.z, scale, mv0);  s.w = fmaf(s.w, scale, mv1);
                r0 = fmaxf(r0, fmaxf(s.x, s.y));
                r1 = fmaxf(r1, fmaxf(s.z, s.w));
            }
            r0 = fmaxf(r0, __shfl_xor_sync(0xffffffffu, r0, 1));
            r0 = fmaxf(r0, __shfl_xor_sync(0xffffffffu, r0, 2));
            r1 = fmaxf(r1, __shfl_xor_sync(0xffffffffu, r1, 1));
            r1 = fmaxf(r1, __shfl_xor_sync(0xffffffffu, r1, 2));
            float mn0 = fmaxf(mrun0, r0);
            float mn1 = fmaxf(mrun1, r1);
            float a0 = __expf(mrun0 - mn0);
            float a1 = __expf(mrun1 - mn1);
            mrun0 = mn0;  mrun1 = mn1;

            float su0 = 0.f, su1 = 0.f;
            #pragma unroll
            for (int nt = 0; nt < 4; nt++) {
                float4& s = sacc[nt];
                s.x = __expf(s.x - mn0);  s.y = __expf(s.y - mn0);
                s.z = __expf(s.z - mn1);  s.w = __expf(s.w - mn1);
                su0 += s.x + s.y;  su1 += s.z + s.w;
            }
            su0 += __shfl_xor_sync(0xffffffffu, su0, 1);
            su0 += __shfl_xor_sync(0xffffffffu, su0, 2);
            su1 += __shfl_xor_sync(0xffffffffu, su1, 1);
            su1 += __shfl_xor_sync(0xffffffffu, su1, 2);
            lrun0 = lrun0 * a0 + su0;
            lrun1 = lrun1 * a1 + su1;
            #pragma unroll
            for (int nf = 0; nf < 20; nf++) {
                oacc[nf].x *= a0;  oacc[nf].y *= a0;
                oacc[nf].z *= a1;  oacc[nf].w *= a1;
            }
        }

        // ---- GEMM2: O += P * V^T, P converted acc-layout -> A-layout via shfl
        #pragma unroll
        for (int ks2 = 0; ks2 < 4; ks2++) {
            uint4 pa;
            const int src = (lane & ~3) | (tig >> 1);
            {
                float4 c = sacc[ks2];
                float s0  = __shfl_sync(0xffffffffu, c.x, src);
                float s1  = __shfl_sync(0xffffffffu, c.y, src);
                float s0b = __shfl_sync(0xffffffffu, c.x, src + 2);
                float s1b = __shfl_sync(0xffffffffu, c.y, src + 2);
                float A0 = (tig & 1) ? s1 : s0;
                float A2 = (tig & 1) ? s1b : s0b;
                s0  = __shfl_sync(0xffffffffu, c.z, src);
                s1  = __shfl_sync(0xffffffffu, c.w, src);
                s0b = __shfl_sync(0xffffffffu, c.z, src + 2);
                s1b = __shfl_sync(0xffffffffu, c.w, src + 2);
                float A1 = (tig & 1) ? s1 : s0;
                float A3 = (tig & 1) ? s1b : s0b;
                pa = make_uint4(__float_as_uint(A0), __float_as_uint(A1),
                                __float_as_uint(A2), __float_as_uint(A3));
            }
            const float* vr = Vb + ks2 * 8 + tig;
            #pragma unroll
            for (int nf = 0; nf < 20; nf++) {
                uint2 bf = make_uint2(
                    __float_as_uint(vr[(nf * 8 + grp) * f2::VSTR]),
                    __float_as_uint(vr[(nf * 8 + grp) * f2::VSTR + 4]));
                mma8(oacc[nf], pa, bf);
            }
        }
    }

    // ---- epilogue: O[d, q] = oacc / l ----
    {
        int r0 = w * 16 + grp;
        int gq = q0 + r0;
        float il0 = 1.0f / lrun0;
        float il1 = 1.0f / lrun1;
        #pragma unroll
        for (int nf = 0; nf < 20; nf++) {
            int d = nf * 8 + tig * 2;
            float4 oa = oacc[nf];
            O[(long)d * S + gq]           = oa.x * il0;
            O[(long)(d + 1) * S + gq]     = oa.y * il0;
            O[(long)d * S + gq + 8]       = oa.z * il1;
            O[(long)(d + 1) * S + gq + 8] = oa.w * il1;
        }
    }
}

// ---------------------------------------------------------------------------
extern "C" void kernel_launch(void* const* d_in, const int* in_sizes, int n_in,
                              void* d_out, int out_size)
{
    using namespace cfg;
    (void)in_sizes; (void)n_in; (void)out_size;

    const float* hidden  = (const float*)d_in[0];  // (B, QD, 1, S)
    const float* context = (const float*)d_in[1];
    const float* mask    = (const float*)d_in[2];  // (B, S, 1, 1)
    const float* Wq      = (const float*)d_in[3];  // (IN, QD)
    const float* Wk      = (const float*)d_in[4];
    const float* Wv      = (const float*)d_in[5];
    const float* Wout    = (const float*)d_in[6];  // (QD, IN)
    const float* bout    = (const float*)d_in[7];
    float*       out     = (float*)d_out;          // (B, QD, 1, S)

    void *pq, *pk, *pv, *pa;
    cudaGetSymbolAddress(&pq, g_q);
    cudaGetSymbolAddress(&pk, g_k);
    cudaGetSymbolAddress(&pv, g_v);
    cudaGetSymbolAddress(&pa, g_attn);
    float* q  = (float*)pq;
    float* k  = (float*)pk;
    float* v  = (float*)pv;
    float* at = (float*)pa;

    const float scale = 1.0f / sqrtf((float)D);

    cudaFuncSetAttribute(flash2,
                         cudaFuncAttributeMaxDynamicSharedMemorySize, f2::SMEM);

    // projections (outputs tf32-rounded for raw staging downstream)
    dim3 gproj(S / 128, IN / 128, B);
    mma_gemm<128,128,16,64,32,false,false,true><<<gproj, 256>>>(
        Wq, hidden, q, IN, S, QD, 0, (long)QD * S, (long)IN * S, 1.f, nullptr);
    mma_gemm<128,128,16,64,32,false,false,true><<<gproj, 256>>>(
        Wk, context, k, IN, S, QD, 0, (long)QD * S, (long)IN * S, 1.f, nullptr);
    mma_gemm<128,128,16,64,32,false,false,true><<<gproj, 256>>>(
        Wv, context, v, IN, S, QD, 0, (long)QD * S, (long)IN * S, 1.f, nullptr);

    // fused attention
    dim3 gfl(S / f2::BQ, B * H);
    flash2<<<gfl, 256, f2::SMEM>>>(q, k, v, mask, at, scale);

    // out = Wout * attn + bout
    dim3 gout(S / 128, QD / 128, B);
    mma_gemm<128,128,16,64,32,false,false,false><<<gout, 256>>>(
        Wout, at, out, QD, S, IN, 0, (long)IN * S, (long)QD * S, 1.f, bout);
}

// round 8
// speedup vs baseline: 4.8773x; 1.0388x over previous
#include <cuda_runtime.h>
#include <math.h>
#include <stdint.h>

// ---------------------------------------------------------------------------
// CrossAttention, round 7: K/V repacked into mma-B-fragment order in gmem so
// flash B operands are single LDS.64 (round 6 spent its cycles on 320 scalar
// LDS.32 per warp-tile; L1 crossbar was the roof).
// B=2, S=4096, H=8, D=160, QUERY_DIM=INNER=1280
// ---------------------------------------------------------------------------

namespace cfg {
constexpr int B  = 2;
constexpr int S  = 4096;
constexpr int H  = 8;
constexpr int D  = 160;
constexpr int QD = 1280;
constexpr int IN = 1280;
}

__device__ float g_q[(size_t)cfg::B * cfg::IN * cfg::S];
__device__ float g_k[(size_t)cfg::B * cfg::IN * cfg::S];
__device__ float g_v[(size_t)cfg::B * cfg::IN * cfg::S];
__device__ float g_attn[(size_t)cfg::B * cfg::IN * cfg::S];
// fragment-packed K/V: [bh][ktile 0..127][80 frags][64]
__device__ float g_kf[(size_t)cfg::B * cfg::H * 128 * 80 * 64];
__device__ float g_vf[(size_t)cfg::B * cfg::H * 128 * 80 * 64];

__device__ __forceinline__ float to_tf32(float x) {
    float r; asm("cvt.rna.tf32.f32 %0, %1;" : "=f"(r) : "f"(x)); return r;
}

__device__ __forceinline__ void mma8(float4& d, const uint4& a, const uint2& b) {
    asm volatile(
        "mma.sync.aligned.m16n8k8.row.col.f32.tf32.tf32.f32 "
        "{%0,%1,%2,%3}, {%4,%5,%6,%7}, {%8,%9}, {%0,%1,%2,%3};\n"
        : "+f"(d.x), "+f"(d.y), "+f"(d.z), "+f"(d.w)
        : "r"(a.x), "r"(a.y), "r"(a.z), "r"(a.w), "r"(b.x), "r"(b.y));
}

// --- swizzled fragment-major shared layout (round-3, verified) -------------
__device__ __forceinline__ int swzA(int Loff, int fA) {
    return (fA << 7) + (Loff ^ ((((Loff >> 5) ^ fA) & 7) << 2));
}
template<int BM> __device__ __forceinline__ int offA(int m, int k) {
    int fA   = (k >> 3) * (BM / 16) + (m >> 4);
    int Loff = ((((m & 7) << 2) | (k & 3)) << 2)
             | ((m >> 3) & 1) | (((k >> 2) & 1) << 1);
    return swzA(Loff, fA);
}
__device__ __forceinline__ int swzB(int Loff, int fB) {
    return (fB << 6) + (Loff ^ (((fB ^ (fB >> 4)) & 15) << 1));
}
template<int BN> __device__ __forceinline__ int offB(int k, int n) {
    int fB   = (k >> 3) * (BN / 8) + (n >> 3);
    int Loff = ((((n & 7) << 2) | (k & 3)) << 1) | ((k >> 2) & 1);
    return swzB(Loff, fB);
}

// ---------------------------------------------------------------------------
// TF32 tensor-core GEMM (round 3) + CVT_OUT flag.
// ---------------------------------------------------------------------------
template<int BM, int BN, int BK, int WM, int WN, bool TA, bool TB, bool CVT_OUT>
__global__ void __launch_bounds__((BM / WM) * (BN / WN) * 32)
mma_gemm(const float* __restrict__ Ab, const float* __restrict__ Bb,
         float* __restrict__ Cb, int M, int N, int K,
         long sA, long sB, long sC, float alpha, const float* __restrict__ bias)
{
    constexpr int NWARP = (BM / WM) * (BN / WN);
    constexpr int NT    = NWARP * 32;
    constexpr int AV    = (BM * BK) / (NT * 4);
    constexpr int BV    = (BN * BK) / (NT * 4);
    constexpr int KS    = BK / 8;
    constexpr int MT    = WM / 16;
    constexpr int NTW   = WN / 8;

    __shared__ __align__(16) float sm[2][BM * BK + BN * BK];

    const float* A  = Ab + (long)blockIdx.z * sA;
    const float* Bp = Bb + (long)blockIdx.z * sB;
    float*       C  = Cb + (long)blockIdx.z * sC;

    const int m0 = blockIdx.y * BM;
    const int n0 = blockIdx.x * BN;
    const int t = threadIdx.x, lane = t & 31, w = t >> 5;
    const int wn = w % (BN / WN), wm = w / (BN / WN);
    const int grp = lane >> 2, tig = lane & 3;

    float4 acc[MT][NTW];
    #pragma unroll
    for (int i = 0; i < MT; i++)
        #pragma unroll
        for (int j = 0; j < NTW; j++) acc[i][j] = make_float4(0.f, 0.f, 0.f, 0.f);

    float4 aR[AV], bR[BV];

    auto loadG = [&](int k0) {
        #pragma unroll
        for (int i = 0; i < AV; i++) {
            int f = t + i * NT;
            if (TA) { int mq = f % (BM / 4), kk = f / (BM / 4);
                aR[i] = *(const float4*)(A + (long)(k0 + kk) * M + m0 + mq * 4);
            } else { int kq = f % (BK / 4), mm = f / (BK / 4);
                aR[i] = *(const float4*)(A + (long)(m0 + mm) * K + k0 + kq * 4);
            }
        }
        #pragma unroll
        for (int i = 0; i < BV; i++) {
            int f = t + i * NT;
            if (TB) { int kq = f % (BK / 4), nn = f / (BK / 4);
                bR[i] = *(const float4*)(Bp + (long)(n0 + nn) * K + k0 + kq * 4);
            } else { int nq = f % (BN / 4), kk = f / (BN / 4);
                bR[i] = *(const float4*)(Bp + (long)(k0 + kk) * N + n0 + nq * 4);
            }
        }
    };

    auto storeS = [&](int buf) {
        float* sA_ = sm[buf];
        float* sB_ = sm[buf] + BM * BK;
        #pragma unroll
        for (int i = 0; i < AV; i++) {
            int f = t + i * NT;
            float v[4] = {aR[i].x, aR[i].y, aR[i].z, aR[i].w};
            if (TA) { int mq = f % (BM / 4), kk = f / (BM / 4);
                #pragma unroll
                for (int j = 0; j < 4; j++) sA_[offA<BM>(mq * 4 + j, kk)] = to_tf32(v[j]);
            } else { int kq = f % (BK / 4), mm = f / (BK / 4);
                #pragma unroll
                for (int j = 0; j < 4; j++) sA_[offA<BM>(mm, kq * 4 + j)] = to_tf32(v[j]);
            }
        }
        #pragma unroll
        for (int i = 0; i < BV; i++) {
            int f = t + i * NT;
            float v[4] = {bR[i].x, bR[i].y, bR[i].z, bR[i].w};
            if (TB) { int kq = f % (BK / 4), nn = f / (BK / 4);
                #pragma unroll
                for (int j = 0; j < 4; j++) sB_[offB<BN>(kq * 4 + j, nn)] = to_tf32(v[j]);
            } else { int nq = f % (BN / 4), kk = f / (BN / 4);
                #pragma unroll
                for (int j = 0; j < 4; j++) sB_[offB<BN>(kk, nq * 4 + j)] = to_tf32(v[j]);
            }
        }
    };

    auto compute = [&](int buf) {
        const float* sA_ = sm[buf];
        const float* sB_ = sm[buf] + BM * BK;
        #pragma unroll
        for (int ks = 0; ks < KS; ks++) {
            uint4 a[MT];
            uint2 b[NTW];
            #pragma unroll
            for (int mt = 0; mt < MT; mt++) {
                int fA = ks * (BM / 16) + (wm * MT + mt);
                a[mt] = *(const uint4*)(sA_ + swzA(lane << 2, fA));
            }
            #pragma unroll
            for (int nt = 0; nt < NTW; nt++) {
                int fB = ks * (BN / 8) + (wn * NTW + nt);
                b[nt] = *(const uint2*)(sB_ + swzB(lane << 1, fB));
            }
            #pragma unroll
            for (int mt = 0; mt < MT; mt++)
                #pragma unroll
                for (int nt = 0; nt < NTW; nt++)
                    mma8(acc[mt][nt], a[mt], b[nt]);
        }
    };

    const int nk = K / BK;
    loadG(0);
    storeS(0);
    __syncthreads();
    for (int it = 0; it < nk; ++it) {
        if (it + 1 < nk) loadG((it + 1) * BK);
        compute(it & 1);
        if (it + 1 < nk) {
            __syncthreads();
            storeS((it + 1) & 1);
            __syncthreads();
        }
    }

    #pragma unroll
    for (int mt = 0; mt < MT; mt++) {
        int gm = m0 + wm * WM + mt * 16 + grp;
        float b0 = bias ? bias[gm] : 0.f;
        float b1 = bias ? bias[gm + 8] : 0.f;
        #pragma unroll
        for (int nt = 0; nt < NTW; nt++) {
            int gn = n0 + wn * WN + nt * 8 + tig * 2;
            float4 ac = acc[mt][nt];
            float o0 = ac.x * alpha + b0, o1 = ac.y * alpha + b0;
            float o2 = ac.z * alpha + b1, o3 = ac.w * alpha + b1;
            if (CVT_OUT) { o0 = to_tf32(o0); o1 = to_tf32(o1);
                           o2 = to_tf32(o2); o3 = to_tf32(o3); }
            *(float2*)(C + (long)gm * N + gn)       = make_float2(o0, o1);
            *(float2*)(C + (long)(gm + 8) * N + gn) = make_float2(o2, o3);
        }
    }
}

// ---------------------------------------------------------------------------
// Repack K/V (per head, per 32-key tile) into mma-B-fragment order.
// Kf frag = ks*4 + nt  (k=d contraction):  inner = ((kp%8)*4 + (d%4))*2 + ((d>>2)&1)
// Vf frag = ks2*20 + nf (k=kp contraction): inner = ((d%8)*4 + (kp%4))*2 + ((kp>>2)&1)
// One block per (ktile, bh); coalesced LDG in, coalesced STG.128 out.
// ---------------------------------------------------------------------------
__global__ void __launch_bounds__(256)
repack_kv(const float* __restrict__ kg, const float* __restrict__ vg,
          float* __restrict__ kf, float* __restrict__ vf)
{
    using namespace cfg;
    __shared__ float sK[160 * 33], sV[160 * 33];
    const int kt = blockIdx.x, bh = blockIdx.y;
    const long base = (long)bh * D * S;
    const int k0 = kt * 32;
    const int t = threadIdx.x;

    #pragma unroll
    for (int i = 0; i < 5; i++) {
        int f = t + i * 256;                 // 0..1279
        int row = f >> 3, cv = f & 7;
        float4 a = *(const float4*)(kg + base + (long)row * S + k0 + cv * 4);
        float4 b = *(const float4*)(vg + base + (long)row * S + k0 + cv * 4);
        int sa = row * 33 + cv * 4;
        sK[sa] = a.x; sK[sa + 1] = a.y; sK[sa + 2] = a.z; sK[sa + 3] = a.w;
        sV[sa] = b.x; sV[sa + 1] = b.y; sV[sa + 2] = b.z; sV[sa + 3] = b.w;
    }
    __syncthreads();

    const long obase = ((long)bh * 128 + kt) * 5120;
    #pragma unroll
    for (int i = 0; i < 5; i++) {
        int g = t + i * 256;                 // 0..1279 output float4s
        int frag = g >> 4, u = g & 15;
        {   // K
            int ks = frag >> 2, nt = frag & 3;
            float o[4];
            #pragma unroll
            for (int j = 0; j < 4; j++) {
                int inner = u * 4 + j;
                int ln = inner >> 1, rg = inner & 1;
                int d  = ks * 8 + (ln & 3) + 4 * rg;
                int kp = nt * 8 + (ln >> 2);
                o[j] = sK[d * 33 + kp];
            }
            *(float4*)(kf + obase + frag * 64 + u * 4) = make_float4(o[0], o[1], o[2], o[3]);
        }
        {   // V
            int ks2 = frag / 20, nf = frag % 20;
            float o[4];
            #pragma unroll
            for (int j = 0; j < 4; j++) {
                int inner = u * 4 + j;
                int ln = inner >> 1, rg = inner & 1;
                int d  = nf * 8 + (ln >> 2);
                int kp = ks2 * 8 + (ln & 3) + 4 * rg;
                o[j] = sV[d * 33 + kp];
            }
            *(float4*)(vf + obase + frag * 64 + u * 4) = make_float4(o[0], o[1], o[2], o[3]);
        }
    }
}

// ---------------------------------------------------------------------------
// Flash attention v4: 8 warps x 16 q-rows, BK=32, cp.async double-buffered
// fragment-packed K/V (B operands = single conflict-free LDS.64).
// ---------------------------------------------------------------------------
namespace f2 {
constexpr int BQ   = 128;
constexpr int BK   = 32;
constexpr int NTLE = cfg::S / BK;          // 128
constexpr int QSZ  = 20480;                // 128 x 160 A-frags
constexpr int KSZ  = 5120;                 // 80 frags x 64
constexpr int VSZ  = 5120;
constexpr int MSZ  = 32;
constexpr int STG  = KSZ + VSZ + MSZ;      // 10272
constexpr int SMEM = (QSZ + 2 * STG) * 4;  // 164,096 B
}

__global__ void __launch_bounds__(256, 1)
flash2(const float* __restrict__ qg, const float* __restrict__ kfg,
       const float* __restrict__ vfg, const float* __restrict__ mask,
       float* __restrict__ og, float scale)
{
    using namespace cfg;
    extern __shared__ float sm[];

    const int qt = blockIdx.x, bh = blockIdx.y, b = bh / H;
    const long base = (long)bh * D * S;
    const float* Q = qg + base;
    float* O = og + base;
    const float* Kf = kfg + (long)bh * 128 * 5120;
    const float* Vf = vfg + (long)bh * 128 * 5120;
    const float* mrow = mask + (long)b * S;
    const int q0 = qt * f2::BQ;

    const int t = threadIdx.x, lane = t & 31, w = t >> 5;
    const int grp = lane >> 2, tig = lane & 3;

    // ---- stage Q once (values already tf32-rounded) ----
    #pragma unroll
    for (int i = 0; i < 20; i++) {
        int f = t + i * 256;
        int mq = f & 31, dd = f >> 5;
        float4 val = *(const float4*)(Q + (long)dd * S + q0 + mq * 4);
        float vv[4] = {val.x, val.y, val.z, val.w};
        #pragma unroll
        for (int j = 0; j < 4; j++)
            sm[offA<128>(mq * 4 + j, dd)] = vv[j];
    }

    auto stage = [&](int tile, int p) {
        float* dst = sm + f2::QSZ + p * f2::STG;
        uint32_t kb = (uint32_t)__cvta_generic_to_shared(dst);
        uint32_t vb = kb + f2::KSZ * 4;
        uint32_t mb = vb + f2::VSZ * 4;
        const float* Kt = Kf + (long)tile * 5120;
        const float* Vt = Vf + (long)tile * 5120;
        #pragma unroll
        for (int i = 0; i < 5; i++) {
            int c = t + i * 256;               // 0..1279 16B chunks
            asm volatile("cp.async.cg.shared.global [%0], [%1], 16;\n"
                         :: "r"(kb + (uint32_t)c * 16), "l"(Kt + c * 4));
        }
        #pragma unroll
        for (int i = 0; i < 5; i++) {
            int c = t + i * 256;
            asm volatile("cp.async.cg.shared.global [%0], [%1], 16;\n"
                         :: "r"(vb + (uint32_t)c * 16), "l"(Vt + c * 4));
        }
        if (t < 8) {
            const float* src = mrow + tile * f2::BK + t * 4;
            asm volatile("cp.async.cg.shared.global [%0], [%1], 16;\n"
                         :: "r"(mb + (uint32_t)t * 16), "l"(src));
        }
        asm volatile("cp.async.commit_group;\n");
    };

    float4 oacc[20];
    #pragma unroll
    for (int j = 0; j < 20; j++) oacc[j] = make_float4(0.f, 0.f, 0.f, 0.f);
    float mrun0 = -1e30f, mrun1 = -1e30f;
    float lrun0 = 0.f, lrun1 = 0.f;

    stage(0, 0);

    for (int it = 0; it < f2::NTLE; it++) {
        const int p = it & 1;
        asm volatile("cp.async.wait_group 0;\n" ::: "memory");
        __syncthreads();
        if (it + 1 < f2::NTLE) stage(it + 1, p ^ 1);

        const float* Kb = sm + f2::QSZ + p * f2::STG;
        const float* Vb = Kb + f2::KSZ;
        const float* Mb = Vb + f2::VSZ;

        // ---- GEMM1: scores(16q x 32k) for this warp's rows ----
        float4 sacc[4];
        #pragma unroll
        for (int j = 0; j < 4; j++) sacc[j] = make_float4(0.f, 0.f, 0.f, 0.f);
        #pragma unroll
        for (int ks = 0; ks < 20; ks++) {
            uint4 a0 = *(const uint4*)(sm + swzA(lane << 2, ks * 8 + w));
            #pragma unroll
            for (int nt = 0; nt < 4; nt++) {
                uint2 bf = *(const uint2*)(Kb + (ks * 4 + nt) * 64 + (lane << 1));
                mma8(sacc[nt], a0, bf);
            }
        }

        // ---- softmax: pure register/warp-shuffle (rows owned by this warp) --
        {
            float r0 = -1e30f, r1 = -1e30f;
            #pragma unroll
            for (int nt = 0; nt < 4; nt++) {
                float mv0 = Mb[nt * 8 + tig * 2];
                float mv1 = Mb[nt * 8 + tig * 2 + 1];
                float4& s = sacc[nt];
                s.x = fmaf(s.x, scale, mv0);  s.y = fmaf(s.y, scale, mv1);
                s.z = fmaf(s.z, scale, mv0);  s.w = fmaf(s.w, scale, mv1);
                r0 = fmaxf(r0, fmaxf(s.x, s.y));
                r1 = fmaxf(r1, fmaxf(s.z, s.w));
            }
            r0 = fmaxf(r0, __shfl_xor_sync(0xffffffffu, r0, 1));
            r0 = fmaxf(r0, __shfl_xor_sync(0xffffffffu, r0, 2));
            r1 = fmaxf(r1, __shfl_xor_sync(0xffffffffu, r1, 1));
            r1 = fmaxf(r1, __shfl_xor_sync(0xffffffffu, r1, 2));
            float mn0 = fmaxf(mrun0, r0);
            float mn1 = fmaxf(mrun1, r1);
            float a0 = __expf(mrun0 - mn0);
            float a1 = __expf(mrun1 - mn1);
            mrun0 = mn0;  mrun1 = mn1;

            float su0 = 0.f, su1 = 0.f;
            #pragma unroll
            for (int nt = 0; nt < 4; nt++) {
                float4& s = sacc[nt];
                s.x = __expf(s.x - mn0);  s.y = __expf(s.y - mn0);
                s.z = __expf(s.z - mn1);  s.w = __expf(s.w - mn1);
                su0 += s.x + s.y;  su1 += s.z + s.w;
            }
            su0 += __shfl_xor_sync(0xffffffffu, su0, 1);
            su0 += __shfl_xor_sync(0xffffffffu, su0, 2);
            su1 += __shfl_xor_sync(0xffffffffu, su1, 1);
            su1 += __shfl_xor_sync(0xffffffffu, su1, 2);
            lrun0 = lrun0 * a0 + su0;
            lrun1 = lrun1 * a1 + su1;
            #pragma unroll
            for (int nf = 0; nf < 20; nf++) {
                oacc[nf].x *= a0;  oacc[nf].y *= a0;
                oacc[nf].z *= a1;  oacc[nf].w *= a1;
            }
        }

        // ---- GEMM2: O += P * V^T, P converted acc-layout -> A-layout via shfl
        #pragma unroll
        for (int ks2 = 0; ks2 < 4; ks2++) {
            uint4 pa;
            const int src = (lane & ~3) | (tig >> 1);
            {
                float4 c = sacc[ks2];
                float s0  = __shfl_sync(0xffffffffu, c.x, src);
                float s1  = __shfl_sync(0xffffffffu, c.y, src);
                float s0b = __shfl_sync(0xffffffffu, c.x, src + 2);
                float s1b = __shfl_sync(0xffffffffu, c.y, src + 2);
                float A0 = (tig & 1) ? s1 : s0;
                float A2 = (tig & 1) ? s1b : s0b;
                s0  = __shfl_sync(0xffffffffu, c.z, src);
                s1  = __shfl_sync(0xffffffffu, c.w, src);
                s0b = __shfl_sync(0xffffffffu, c.z, src + 2);
                s1b = __shfl_sync(0xffffffffu, c.w, src + 2);
                float A1 = (tig & 1) ? s1 : s0;
                float A3 = (tig & 1) ? s1b : s0b;
                pa = make_uint4(__float_as_uint(A0), __float_as_uint(A1),
                                __float_as_uint(A2), __float_as_uint(A3));
            }
            #pragma unroll
            for (int nf = 0; nf < 20; nf++) {
                uint2 bf = *(const uint2*)(Vb + (ks2 * 20 + nf) * 64 + (lane << 1));
                mma8(oacc[nf], pa, bf);
            }
        }
    }

    // ---- epilogue: O[d, q] = oacc / l ----
    {
        int r0 = w * 16 + grp;
        int gq = q0 + r0;
        float il0 = 1.0f / lrun0;
        float il1 = 1.0f / lrun1;
        #pragma unroll
        for (int nf = 0; nf < 20; nf++) {
            int d = nf * 8 + tig * 2;
            float4 oa = oacc[nf];
            O[(long)d * S + gq]           = oa.x * il0;
            O[(long)(d + 1) * S + gq]     = oa.y * il0;
            O[(long)d * S + gq + 8]       = oa.z * il1;
            O[(long)(d + 1) * S + gq + 8] = oa.w * il1;
        }
    }
}

// ---------------------------------------------------------------------------
extern "C" void kernel_launch(void* const* d_in, const int* in_sizes, int n_in,
                              void* d_out, int out_size)
{
    using namespace cfg;
    (void)in_sizes; (void)n_in; (void)out_size;

    const float* hidden  = (const float*)d_in[0];  // (B, QD, 1, S)
    const float* context = (const float*)d_in[1];
    const float* mask    = (const float*)d_in[2];  // (B, S, 1, 1)
    const float* Wq      = (const float*)d_in[3];  // (IN, QD)
    const float* Wk      = (const float*)d_in[4];
    const float* Wv      = (const float*)d_in[5];
    const float* Wout    = (const float*)d_in[6];  // (QD, IN)
    const float* bout    = (const float*)d_in[7];
    float*       out     = (float*)d_out;          // (B, QD, 1, S)

    void *pq, *pk, *pv, *pa, *pkf, *pvf;
    cudaGetSymbolAddress(&pq, g_q);
    cudaGetSymbolAddress(&pk, g_k);
    cudaGetSymbolAddress(&pv, g_v);
    cudaGetSymbolAddress(&pa, g_attn);
    cudaGetSymbolAddress(&pkf, g_kf);
    cudaGetSymbolAddress(&pvf, g_vf);
    float* q  = (float*)pq;
    float* k  = (float*)pk;
    float* v  = (float*)pv;
    float* at = (float*)pa;
    float* kf = (float*)pkf;
    float* vf = (float*)pvf;

    const float scale = 1.0f / sqrtf((float)D);

    cudaFuncSetAttribute(flash2,
                         cudaFuncAttributeMaxDynamicSharedMemorySize, f2::SMEM);

    // projections (outputs tf32-rounded for raw staging downstream)
    dim3 gproj(S / 128, IN / 128, B);
    mma_gemm<128,128,16,64,32,false,false,true><<<gproj, 256>>>(
        Wq, hidden, q, IN, S, QD, 0, (long)QD * S, (long)IN * S, 1.f, nullptr);
    mma_gemm<128,128,16,64,32,false,false,true><<<gproj, 256>>>(
        Wk, context, k, IN, S, QD, 0, (long)QD * S, (long)IN * S, 1.f, nullptr);
    mma_gemm<128,128,16,64,32,false,false,true><<<gproj, 256>>>(
        Wv, context, v, IN, S, QD, 0, (long)QD * S, (long)IN * S, 1.f, nullptr);

    // repack K/V into mma-B-fragment order
    dim3 grep(128, B * H);
    repack_kv<<<grep, 256>>>(k, v, kf, vf);

    // fused attention
    dim3 gfl(S / f2::BQ, B * H);
    flash2<<<gfl, 256, f2::SMEM>>>(q, kf, vf, mask, at, scale);

    // out = Wout * attn + bout
    dim3 gout(S / 128, QD / 128, B);
    mma_gemm<128,128,16,64,32,false,false,false><<<gout, 256>>>(
        Wout, at, out, QD, S, IN, 0, (long)IN * S, (long)QD * S, 1.f, bout);
}

// round 9
// speedup vs baseline: 5.2504x; 1.0765x over previous
#include <cuda_runtime.h>
#include <math.h>
#include <stdint.h>

// ---------------------------------------------------------------------------
// CrossAttention, round 9: flash with Q in registers (no A-operand LDS),
// pair-interleaved B fragments (1 LDS.128 feeds 2 mma), 4-stage cp.async.
// B=2, S=4096, H=8, D=160, QUERY_DIM=INNER=1280
// ---------------------------------------------------------------------------

namespace cfg {
constexpr int B  = 2;
constexpr int S  = 4096;
constexpr int H  = 8;
constexpr int D  = 160;
constexpr int QD = 1280;
constexpr int IN = 1280;
}

__device__ float g_q[(size_t)cfg::B * cfg::IN * cfg::S];
__device__ float g_k[(size_t)cfg::B * cfg::IN * cfg::S];
__device__ float g_v[(size_t)cfg::B * cfg::IN * cfg::S];
__device__ float g_attn[(size_t)cfg::B * cfg::IN * cfg::S];
// pair-interleaved fragment-packed K/V: [bh][ktile 0..127][40 pairs][128]
__device__ float g_kf[(size_t)cfg::B * cfg::H * 128 * 40 * 128];
__device__ float g_vf[(size_t)cfg::B * cfg::H * 128 * 40 * 128];

__device__ __forceinline__ float to_tf32(float x) {
    float r; asm("cvt.rna.tf32.f32 %0, %1;" : "=f"(r) : "f"(x)); return r;
}

__device__ __forceinline__ void mma8(float4& d, const uint4& a, const uint2& b) {
    asm volatile(
        "mma.sync.aligned.m16n8k8.row.col.f32.tf32.tf32.f32 "
        "{%0,%1,%2,%3}, {%4,%5,%6,%7}, {%8,%9}, {%0,%1,%2,%3};\n"
        : "+f"(d.x), "+f"(d.y), "+f"(d.z), "+f"(d.w)
        : "r"(a.x), "r"(a.y), "r"(a.z), "r"(a.w), "r"(b.x), "r"(b.y));
}

// --- swizzled fragment-major shared layout (round-3, used by mma_gemm) ----
__device__ __forceinline__ int swzA(int Loff, int fA) {
    return (fA << 7) + (Loff ^ ((((Loff >> 5) ^ fA) & 7) << 2));
}
template<int BM> __device__ __forceinline__ int offA(int m, int k) {
    int fA   = (k >> 3) * (BM / 16) + (m >> 4);
    int Loff = ((((m & 7) << 2) | (k & 3)) << 2)
             | ((m >> 3) & 1) | (((k >> 2) & 1) << 1);
    return swzA(Loff, fA);
}
__device__ __forceinline__ int swzB(int Loff, int fB) {
    return (fB << 6) + (Loff ^ (((fB ^ (fB >> 4)) & 15) << 1));
}
template<int BN> __device__ __forceinline__ int offB(int k, int n) {
    int fB   = (k >> 3) * (BN / 8) + (n >> 3);
    int Loff = ((((n & 7) << 2) | (k & 3)) << 1) | ((k >> 2) & 1);
    return swzB(Loff, fB);
}

// ---------------------------------------------------------------------------
// TF32 tensor-core GEMM (round 3) + CVT_OUT flag. Unchanged.
// ---------------------------------------------------------------------------
template<int BM, int BN, int BK, int WM, int WN, bool TA, bool TB, bool CVT_OUT>
__global__ void __launch_bounds__((BM / WM) * (BN / WN) * 32)
mma_gemm(const float* __restrict__ Ab, const float* __restrict__ Bb,
         float* __restrict__ Cb, int M, int N, int K,
         long sA, long sB, long sC, float alpha, const float* __restrict__ bias)
{
    constexpr int NWARP = (BM / WM) * (BN / WN);
    constexpr int NT    = NWARP * 32;
    constexpr int AV    = (BM * BK) / (NT * 4);
    constexpr int BV    = (BN * BK) / (NT * 4);
    constexpr int KS    = BK / 8;
    constexpr int MT    = WM / 16;
    constexpr int NTW   = WN / 8;

    __shared__ __align__(16) float sm[2][BM * BK + BN * BK];

    const float* A  = Ab + (long)blockIdx.z * sA;
    const float* Bp = Bb + (long)blockIdx.z * sB;
    float*       C  = Cb + (long)blockIdx.z * sC;

    const int m0 = blockIdx.y * BM;
    const int n0 = blockIdx.x * BN;
    const int t = threadIdx.x, lane = t & 31, w = t >> 5;
    const int wn = w % (BN / WN), wm = w / (BN / WN);
    const int grp = lane >> 2, tig = lane & 3;

    float4 acc[MT][NTW];
    #pragma unroll
    for (int i = 0; i < MT; i++)
        #pragma unroll
        for (int j = 0; j < NTW; j++) acc[i][j] = make_float4(0.f, 0.f, 0.f, 0.f);

    float4 aR[AV], bR[BV];

    auto loadG = [&](int k0) {
        #pragma unroll
        for (int i = 0; i < AV; i++) {
            int f = t + i * NT;
            if (TA) { int mq = f % (BM / 4), kk = f / (BM / 4);
                aR[i] = *(const float4*)(A + (long)(k0 + kk) * M + m0 + mq * 4);
            } else { int kq = f % (BK / 4), mm = f / (BK / 4);
                aR[i] = *(const float4*)(A + (long)(m0 + mm) * K + k0 + kq * 4);
            }
        }
        #pragma unroll
        for (int i = 0; i < BV; i++) {
            int f = t + i * NT;
            if (TB) { int kq = f % (BK / 4), nn = f / (BK / 4);
                bR[i] = *(const float4*)(Bp + (long)(n0 + nn) * K + k0 + kq * 4);
            } else { int nq = f % (BN / 4), kk = f / (BN / 4);
                bR[i] = *(const float4*)(Bp + (long)(k0 + kk) * N + n0 + nq * 4);
            }
        }
    };

    auto storeS = [&](int buf) {
        float* sA_ = sm[buf];
        float* sB_ = sm[buf] + BM * BK;
        #pragma unroll
        for (int i = 0; i < AV; i++) {
            int f = t + i * NT;
            float v[4] = {aR[i].x, aR[i].y, aR[i].z, aR[i].w};
            if (TA) { int mq = f % (BM / 4), kk = f / (BM / 4);
                #pragma unroll
                for (int j = 0; j < 4; j++) sA_[offA<BM>(mq * 4 + j, kk)] = to_tf32(v[j]);
            } else { int kq = f % (BK / 4), mm = f / (BK / 4);
                #pragma unroll
                for (int j = 0; j < 4; j++) sA_[offA<BM>(mm, kq * 4 + j)] = to_tf32(v[j]);
            }
        }
        #pragma unroll
        for (int i = 0; i < BV; i++) {
            int f = t + i * NT;
            float v[4] = {bR[i].x, bR[i].y, bR[i].z, bR[i].w};
            if (TB) { int kq = f % (BK / 4), nn = f / (BK / 4);
                #pragma unroll
                for (int j = 0; j < 4; j++) sB_[offB<BN>(kq * 4 + j, nn)] = to_tf32(v[j]);
            } else { int nq = f % (BN / 4), kk = f / (BN / 4);
                #pragma unroll
                for (int j = 0; j < 4; j++) sB_[offB<BN>(kk, nq * 4 + j)] = to_tf32(v[j]);
            }
        }
    };

    auto compute = [&](int buf) {
        const float* sA_ = sm[buf];
        const float* sB_ = sm[buf] + BM * BK;
        #pragma unroll
        for (int ks = 0; ks < KS; ks++) {
            uint4 a[MT];
            uint2 b[NTW];
            #pragma unroll
            for (int mt = 0; mt < MT; mt++) {
                int fA = ks * (BM / 16) + (wm * MT + mt);
                a[mt] = *(const uint4*)(sA_ + swzA(lane << 2, fA));
            }
            #pragma unroll
            for (int nt = 0; nt < NTW; nt++) {
                int fB = ks * (BN / 8) + (wn * NTW + nt);
                b[nt] = *(const uint2*)(sB_ + swzB(lane << 1, fB));
            }
            #pragma unroll
            for (int mt = 0; mt < MT; mt++)
                #pragma unroll
                for (int nt = 0; nt < NTW; nt++)
                    mma8(acc[mt][nt], a[mt], b[nt]);
        }
    };

    const int nk = K / BK;
    loadG(0);
    storeS(0);
    __syncthreads();
    for (int it = 0; it < nk; ++it) {
        if (it + 1 < nk) loadG((it + 1) * BK);
        compute(it & 1);
        if (it + 1 < nk) {
            __syncthreads();
            storeS((it + 1) & 1);
            __syncthreads();
        }
    }

    #pragma unroll
    for (int mt = 0; mt < MT; mt++) {
        int gm = m0 + wm * WM + mt * 16 + grp;
        float b0 = bias ? bias[gm] : 0.f;
        float b1 = bias ? bias[gm + 8] : 0.f;
        #pragma unroll
        for (int nt = 0; nt < NTW; nt++) {
            int gn = n0 + wn * WN + nt * 8 + tig * 2;
            float4 ac = acc[mt][nt];
            float o0 = ac.x * alpha + b0, o1 = ac.y * alpha + b0;
            float o2 = ac.z * alpha + b1, o3 = ac.w * alpha + b1;
            if (CVT_OUT) { o0 = to_tf32(o0); o1 = to_tf32(o1);
                           o2 = to_tf32(o2); o3 = to_tf32(o3); }
            *(float2*)(C + (long)gm * N + gn)       = make_float2(o0, o1);
            *(float2*)(C + (long)(gm + 8) * N + gn) = make_float2(o2, o3);
        }
    }
}

// ---------------------------------------------------------------------------
// Repack K/V (per head, per 32-key tile) into PAIR-INTERLEAVED B-fragment
// order: each 128-float block serves one LDS.128 per lane feeding TWO mma8.
// K pair pr = ks*2 + nt2 (ks 0..19, nt2 0..1):
//   [l*4+0] = K[d0][kpe]  [l*4+1] = K[d0+4][kpe]
//   [l*4+2] = K[d0][kpe+8][l*4+3] = K[d0+4][kpe+8]
//   with d0 = ks*8 + (l&3), kpe = nt2*16 + (l>>2)
// V pair pr = ks2*10 + nf2 (ks2 0..3, nf2 0..9):
//   [l*4+0] = V[de][kp0]  [l*4+1] = V[de][kp0+4]
//   [l*4+2] = V[de+8][kp0][l*4+3] = V[de+8][kp0+4]
//   with de = nf2*16 + (l>>2), kp0 = ks2*8 + (l&3)
// ---------------------------------------------------------------------------
__global__ void __launch_bounds__(256)
repack_kv(const float* __restrict__ kg, const float* __restrict__ vg,
          float* __restrict__ kf, float* __restrict__ vf)
{
    using namespace cfg;
    __shared__ float sK[160 * 33], sV[160 * 33];
    const int kt = blockIdx.x, bh = blockIdx.y;
    const long base = (long)bh * D * S;
    const int k0 = kt * 32;
    const int t = threadIdx.x;

    #pragma unroll
    for (int i = 0; i < 5; i++) {
        int f = t + i * 256;                 // 0..1279
        int row = f >> 3, cv = f & 7;
        float4 a = *(const float4*)(kg + base + (long)row * S + k0 + cv * 4);
        float4 b = *(const float4*)(vg + base + (long)row * S + k0 + cv * 4);
        int sa = row * 33 + cv * 4;
        sK[sa] = a.x; sK[sa + 1] = a.y; sK[sa + 2] = a.z; sK[sa + 3] = a.w;
        sV[sa] = b.x; sV[sa + 1] = b.y; sV[sa + 2] = b.z; sV[sa + 3] = b.w;
    }
    __syncthreads();

    const long obase = ((long)bh * 128 + kt) * 5120;
    #pragma unroll
    for (int i = 0; i < 5; i++) {
        int g = t + i * 256;                 // 0..1279 output float4s
        int pr = g >> 5, l = g & 31;
        {   // K
            int ks = pr >> 1, nt2 = pr & 1;
            int d0 = ks * 8 + (l & 3);
            int kpe = nt2 * 16 + (l >> 2);
            float4 o = make_float4(sK[d0 * 33 + kpe],
                                   sK[(d0 + 4) * 33 + kpe],
                                   sK[d0 * 33 + kpe + 8],
                                   sK[(d0 + 4) * 33 + kpe + 8]);
            *(float4*)(kf + obase + pr * 128 + l * 4) = o;
        }
        {   // V
            int ks2 = pr / 10, nf2 = pr % 10;
            int de = nf2 * 16 + (l >> 2);
            int kp0 = ks2 * 8 + (l & 3);
            float4 o = make_float4(sV[de * 33 + kp0],
                                   sV[de * 33 + kp0 + 4],
                                   sV[(de + 8) * 33 + kp0],
                                   sV[(de + 8) * 33 + kp0 + 4]);
            *(float4*)(vf + obase + pr * 128 + l * 4) = o;
        }
    }
}

// ---------------------------------------------------------------------------
// Flash attention v5: 8 warps x 16 q-rows, BK=32. Q A-fragments pre-gathered
// into registers (no A LDS). B operands: one LDS.128 -> two mma8. 4-stage
// cp.async pipeline (wait_group 2), one __syncthreads per tile.
// ---------------------------------------------------------------------------
namespace f3 {
constexpr int BQ   = 128;
constexpr int BK   = 32;
constexpr int NTLE = cfg::S / BK;           // 128
constexpr int KSZ  = 5120;                  // 40 pairs x 128
constexpr int VSZ  = 5120;
constexpr int MSZ  = 32;
constexpr int STG  = KSZ + VSZ + MSZ;       // 10272 floats / stage
constexpr int NST  = 4;
constexpr int SMEM = NST * STG * 4;         // 164,352 B
}

__global__ void __launch_bounds__(256, 1)
flash3(const float* __restrict__ qg, const float* __restrict__ kfg,
       const float* __restrict__ vfg, const float* __restrict__ mask,
       float* __restrict__ og, float scale)
{
    using namespace cfg;
    extern __shared__ float sm[];

    const int qt = blockIdx.x, bh = blockIdx.y, b = bh / H;
    const long base = (long)bh * D * S;
    const float* Q = qg + base;
    float* O = og + base;
    const float* Kf = kfg + (long)bh * 128 * 5120;
    const float* Vf = vfg + (long)bh * 128 * 5120;
    const float* mrow = mask + (long)b * S;
    const int q0 = qt * f3::BQ;

    const int t = threadIdx.x, lane = t & 31, w = t >> 5;
    const int grp = lane >> 2, tig = lane & 3;

    // ---- gather Q A-fragments into registers (once; values already tf32) --
    uint4 qa[20];
    {
        const int m0 = q0 + w * 16 + grp;
        #pragma unroll
        for (int ks = 0; ks < 20; ks++) {
            int d0 = ks * 8 + tig;
            qa[ks] = make_uint4(
                __float_as_uint(Q[(long)d0 * S + m0]),
                __float_as_uint(Q[(long)d0 * S + m0 + 8]),
                __float_as_uint(Q[(long)(d0 + 4) * S + m0]),
                __float_as_uint(Q[(long)(d0 + 4) * S + m0 + 8]));
        }
    }

    const uint32_t sbase = (uint32_t)__cvta_generic_to_shared(sm);

    auto stage = [&](int tile) {
        const int slot = tile & (f3::NST - 1);
        const uint32_t kb = sbase + (uint32_t)(slot * f3::STG) * 4;
        const uint32_t vb = kb + f3::KSZ * 4;
        const uint32_t mb = vb + f3::VSZ * 4;
        const float* Kt = Kf + (long)tile * 5120;
        const float* Vt = Vf + (long)tile * 5120;
        #pragma unroll
        for (int i = 0; i < 5; i++) {
            int c = t + i * 256;
            asm volatile("cp.async.cg.shared.global [%0], [%1], 16;\n"
                         :: "r"(kb + (uint32_t)c * 16), "l"(Kt + c * 4));
        }
        #pragma unroll
        for (int i = 0; i < 5; i++) {
            int c = t + i * 256;
            asm volatile("cp.async.cg.shared.global [%0], [%1], 16;\n"
                         :: "r"(vb + (uint32_t)c * 16), "l"(Vt + c * 4));
        }
        if (t < 8) {
            const float* src = mrow + tile * f3::BK + t * 4;
            asm volatile("cp.async.cg.shared.global [%0], [%1], 16;\n"
                         :: "r"(mb + (uint32_t)t * 16), "l"(src));
        }
        asm volatile("cp.async.commit_group;\n");
    };

    float4 oacc[20];
    #pragma unroll
    for (int j = 0; j < 20; j++) oacc[j] = make_float4(0.f, 0.f, 0.f, 0.f);
    float mrun0 = -1e30f, mrun1 = -1e30f;
    float lrun0 = 0.f, lrun1 = 0.f;

    stage(0); stage(1); stage(2);

    for (int it = 0; it < f3::NTLE; it++) {
        asm volatile("cp.async.wait_group 2;\n" ::: "memory");
        __syncthreads();
        if (it + 3 < f3::NTLE) stage(it + 3);
        else asm volatile("cp.async.commit_group;\n");

        const float* Kb = sm + (it & (f3::NST - 1)) * f3::STG;
        const float* Vb = Kb + f3::KSZ;
        const float* Mb = Vb + f3::VSZ;

        // ---- GEMM1: scores(16q x 32k); A from regs, B one LDS.128/2 mma ----
        float4 sacc[4];
        #pragma unroll
        for (int j = 0; j < 4; j++) sacc[j] = make_float4(0.f, 0.f, 0.f, 0.f);
        #pragma unroll
        for (int ks = 0; ks < 20; ks++) {
            uint4 b0 = *(const uint4*)(Kb + (ks * 2) * 128 + (lane << 2));
            uint4 b1 = *(const uint4*)(Kb + (ks * 2 + 1) * 128 + (lane << 2));
            mma8(sacc[0], qa[ks], make_uint2(b0.x, b0.y));
            mma8(sacc[1], qa[ks], make_uint2(b0.z, b0.w));
            mma8(sacc[2], qa[ks], make_uint2(b1.x, b1.y));
            mma8(sacc[3], qa[ks], make_uint2(b1.z, b1.w));
        }

        // ---- softmax (register/warp-shuffle; rows owned by this warp) ------
        {
            float r0 = -1e30f, r1 = -1e30f;
            #pragma unroll
            for (int nt = 0; nt < 4; nt++) {
                float mv0 = Mb[nt * 8 + tig * 2];
                float mv1 = Mb[nt * 8 + tig * 2 + 1];
                float4& s = sacc[nt];
                s.x = fmaf(s.x, scale, mv0);  s.y = fmaf(s.y, scale, mv1);
                s.z = fmaf(s.z, scale, mv0);  s.w = fmaf(s.w, scale, mv1);
                r0 = fmaxf(r0, fmaxf(s.x, s.y));
                r1 = fmaxf(r1, fmaxf(s.z, s.w));
            }
            r0 = fmaxf(r0, __shfl_xor_sync(0xffffffffu, r0, 1));
            r0 = fmaxf(r0, __shfl_xor_sync(0xffffffffu, r0, 2));
            r1 = fmaxf(r1, __shfl_xor_sync(0xffffffffu, r1, 1));
            r1 = fmaxf(r1, __shfl_xor_sync(0xffffffffu, r1, 2));
            float mn0 = fmaxf(mrun0, r0);
            float mn1 = fmaxf(mrun1, r1);
            float a0 = __expf(mrun0 - mn0);
            float a1 = __expf(mrun1 - mn1);
            mrun0 = mn0;  mrun1 = mn1;

            float su0 = 0.f, su1 = 0.f;
            #pragma unroll
            for (int nt = 0; nt < 4; nt++) {
                float4& s = sacc[nt];
                s.x = __expf(s.x - mn0);  s.y = __expf(s.y - mn0);
                s.z = __expf(s.z - mn1);  s.w = __expf(s.w - mn1);
                su0 += s.x + s.y;  su1 += s.z + s.w;
            }
            su0 += __shfl_xor_sync(0xffffffffu, su0, 1);
            su0 += __shfl_xor_sync(0xffffffffu, su0, 2);
            su1 += __shfl_xor_sync(0xffffffffu, su1, 1);
            su1 += __shfl_xor_sync(0xffffffffu, su1, 2);
            lrun0 = lrun0 * a0 + su0;
            lrun1 = lrun1 * a1 + su1;
            #pragma unroll
            for (int nf = 0; nf < 20; nf++) {
                oacc[nf].x *= a0;  oacc[nf].y *= a0;
                oacc[nf].z *= a1;  oacc[nf].w *= a1;
            }
        }

        // ---- GEMM2: O += P * V^T; P -> A-layout via shfl; B paired ---------
        #pragma unroll
        for (int ks2 = 0; ks2 < 4; ks2++) {
            uint4 pa;
            const int src = (lane & ~3) | (tig >> 1);
            {
                float4 c = sacc[ks2];
                float s0  = __shfl_sync(0xffffffffu, c.x, src);
                float s1  = __shfl_sync(0xffffffffu, c.y, src);
                float s0b = __shfl_sync(0xffffffffu, c.x, src + 2);
                float s1b = __shfl_sync(0xffffffffu, c.y, src + 2);
                float A0 = (tig & 1) ? s1 : s0;
                float A2 = (tig & 1) ? s1b : s0b;
                s0  = __shfl_sync(0xffffffffu, c.z, src);
                s1  = __shfl_sync(0xffffffffu, c.w, src);
                s0b = __shfl_sync(0xffffffffu, c.z, src + 2);
                s1b = __shfl_sync(0xffffffffu, c.w, src + 2);
                float A1 = (tig & 1) ? s1 : s0;
                float A3 = (tig & 1) ? s1b : s0b;
                pa = make_uint4(__float_as_uint(A0), __float_as_uint(A1),
                                __float_as_uint(A2), __float_as_uint(A3));
            }
            #pragma unroll
            for (int nf2 = 0; nf2 < 10; nf2++) {
                uint4 bb = *(const uint4*)(Vb + (ks2 * 10 + nf2) * 128 + (lane << 2));
                mma8(oacc[2 * nf2],     pa, make_uint2(bb.x, bb.y));
                mma8(oacc[2 * nf2 + 1], pa, make_uint2(bb.z, bb.w));
            }
        }
    }

    // ---- epilogue: O[d, q] = oacc / l ----
    {
        int r0 = w * 16 + grp;
        int gq = q0 + r0;
        float il0 = 1.0f / lrun0;
        float il1 = 1.0f / lrun1;
        #pragma unroll
        for (int nf = 0; nf < 20; nf++) {
            int d = nf * 8 + tig * 2;
            float4 oa = oacc[nf];
            O[(long)d * S + gq]           = oa.x * il0;
            O[(long)(d + 1) * S + gq]     = oa.y * il0;
            O[(long)d * S + gq + 8]       = oa.z * il1;
            O[(long)(d + 1) * S + gq + 8] = oa.w * il1;
        }
    }
}

// ---------------------------------------------------------------------------
extern "C" void kernel_launch(void* const* d_in, const int* in_sizes, int n_in,
                              void* d_out, int out_size)
{
    using namespace cfg;
    (void)in_sizes; (void)n_in; (void)out_size;

    const float* hidden  = (const float*)d_in[0];  // (B, QD, 1, S)
    const float* context = (const float*)d_in[1];
    const float* mask    = (const float*)d_in[2];  // (B, S, 1, 1)
    const float* Wq      = (const float*)d_in[3];  // (IN, QD)
    const float* Wk      = (const float*)d_in[4];
    const float* Wv      = (const float*)d_in[5];
    const float* Wout    = (const float*)d_in[6];  // (QD, IN)
    const float* bout    = (const float*)d_in[7];
    float*       out     = (float*)d_out;          // (B, QD, 1, S)

    void *pq, *pk, *pv, *pa, *pkf, *pvf;
    cudaGetSymbolAddress(&pq, g_q);
    cudaGetSymbolAddress(&pk, g_k);
    cudaGetSymbolAddress(&pv, g_v);
    cudaGetSymbolAddress(&pa, g_attn);
    cudaGetSymbolAddress(&pkf, g_kf);
    cudaGetSymbolAddress(&pvf, g_vf);
    float* q  = (float*)pq;
    float* k  = (float*)pk;
    float* v  = (float*)pv;
    float* at = (float*)pa;
    float* kf = (float*)pkf;
    float* vf = (float*)pvf;

    const float scale = 1.0f / sqrtf((float)D);

    cudaFuncSetAttribute(flash3,
                         cudaFuncAttributeMaxDynamicSharedMemorySize, f3::SMEM);

    // projections (outputs tf32-rounded for raw staging downstream)
    dim3 gproj(S / 128, IN / 128, B);
    mma_gemm<128,128,16,64,32,false,false,true><<<gproj, 256>>>(
        Wq, hidden, q, IN, S, QD, 0, (long)QD * S, (long)IN * S, 1.f, nullptr);
    mma_gemm<128,128,16,64,32,false,false,true><<<gproj, 256>>>(
        Wk, context, k, IN, S, QD, 0, (long)QD * S, (long)IN * S, 1.f, nullptr);
    mma_gemm<128,128,16,64,32,false,false,true><<<gproj, 256>>>(
        Wv, context, v, IN, S, QD, 0, (long)QD * S, (long)IN * S, 1.f, nullptr);

    // repack K/V into pair-interleaved mma-B-fragment order
    dim3 grep(128, B * H);
    repack_kv<<<grep, 256>>>(k, v, kf, vf);

    // fused attention
    dim3 gfl(S / f3::BQ, B * H);
    flash3<<<gfl, 256, f3::SMEM>>>(q, kf, vf, mask, at, scale);

    // out = Wout * attn + bout
    dim3 gout(S / 128, QD / 128, B);
    mma_gemm<128,128,16,64,32,false,false,false><<<gout, 256>>>(
        Wout, at, out, QD, S, IN, 0, (long)IN * S, (long)QD * S, 1.f, bout);
}

// round 10
// speedup vs baseline: 6.0065x; 1.1440x over previous
#include <cuda_runtime.h>
#include <math.h>
#include <stdint.h>

// ---------------------------------------------------------------------------
// CrossAttention, round 10: dense GEMMs rebuilt as fragment-packed cp.async
// GEMMs (repack_a/repack_b + gemm_fp), flash attention unchanged (round 9).
// B=2, S=4096, H=8, D=160, QUERY_DIM=INNER=1280
// ---------------------------------------------------------------------------

namespace cfg {
constexpr int B  = 2;
constexpr int S  = 4096;
constexpr int H  = 8;
constexpr int D  = 160;
constexpr int QD = 1280;
constexpr int IN = 1280;
}

__device__ float g_q[(size_t)cfg::B * cfg::IN * cfg::S];
__device__ float g_k[(size_t)cfg::B * cfg::IN * cfg::S];
__device__ float g_v[(size_t)cfg::B * cfg::IN * cfg::S];
__device__ float g_attn[(size_t)cfg::B * cfg::IN * cfg::S];
// pair-interleaved fragment-packed K/V for flash: [bh][ktile][40 pairs][128]
__device__ float g_kf[(size_t)cfg::B * cfg::H * 128 * 40 * 128];
__device__ float g_vf[(size_t)cfg::B * cfg::H * 128 * 40 * 128];
// A-fragment-packed weights: [mt 10][kf 160][mg 8][128]
__device__ float g_wqf[(size_t)10 * 160 * 8 * 128];
__device__ float g_wkf[(size_t)10 * 160 * 8 * 128];
__device__ float g_wvf[(size_t)10 * 160 * 8 * 128];
__device__ float g_wof[(size_t)10 * 160 * 8 * 128];
// B-fragment-pair-packed activations: [z][nt 32][kf 160][np 8][128]
__device__ float g_hf[(size_t)cfg::B * 32 * 160 * 8 * 128];
__device__ float g_cf[(size_t)cfg::B * 32 * 160 * 8 * 128];
__device__ float g_af[(size_t)cfg::B * 32 * 160 * 8 * 128];

__device__ __forceinline__ float to_tf32(float x) {
    float r; asm("cvt.rna.tf32.f32 %0, %1;" : "=f"(r) : "f"(x)); return r;
}

__device__ __forceinline__ void mma8(float4& d, const uint4& a, const uint2& b) {
    asm volatile(
        "mma.sync.aligned.m16n8k8.row.col.f32.tf32.tf32.f32 "
        "{%0,%1,%2,%3}, {%4,%5,%6,%7}, {%8,%9}, {%0,%1,%2,%3};\n"
        : "+f"(d.x), "+f"(d.y), "+f"(d.z), "+f"(d.w)
        : "r"(a.x), "r"(a.y), "r"(a.z), "r"(a.w), "r"(b.x), "r"(b.y));
}

// ---------------------------------------------------------------------------
// repack_a: weight W (1280 x 1280 row-major) -> A-fragment order, tf32.
// Fragment (kf, mg) of m-tile mt; lane l holds float4:
//   { W[mg16+(l>>2)][kf8+(l&3)], W[+8 row][..], W[..][k+4], W[+8][k+4] }
// grid (kc=10, mc=20), 256 thr. Tile: 64 m-rows x 128 k.
// ---------------------------------------------------------------------------
__global__ void __launch_bounds__(256)
repack_a(const float* __restrict__ Wg, float* __restrict__ Wf)
{
    __shared__ float sW[64 * 132];
    const int kc = blockIdx.x, mc = blockIdx.y;
    const int t = threadIdx.x;
    #pragma unroll
    for (int i = 0; i < 8; i++) {
        int c = t + i * 256;
        int row = c >> 5, c4 = c & 31;
        float4 v = *(const float4*)(Wg + (long)(mc * 64 + row) * 1280 + kc * 128 + c4 * 4);
        float* d = sW + row * 132 + c4 * 4;
        d[0] = to_tf32(v.x); d[1] = to_tf32(v.y);
        d[2] = to_tf32(v.z); d[3] = to_tf32(v.w);
    }
    __syncthreads();
    const int mt = mc >> 1, mgh = (mc & 1) * 4;
    #pragma unroll
    for (int i = 0; i < 8; i++) {
        int o = t + i * 256;
        int fr = o >> 5, l = o & 31;
        int kfl = fr >> 2, mg = fr & 3;
        int rb = mg * 16 + (l >> 2);
        int cb = kfl * 8 + (l & 3);
        float4 out = make_float4(sW[rb * 132 + cb],       sW[(rb + 8) * 132 + cb],
                                 sW[rb * 132 + cb + 4],   sW[(rb + 8) * 132 + cb + 4]);
        *(float4*)(Wf + ((long)(mt * 160 + kc * 16 + kfl) * 8 + mgh + mg) * 128 + l * 4) = out;
    }
}

// ---------------------------------------------------------------------------
// repack_b: activation X (1280 k-rows x 4096 n-cols, row stride 4096) ->
// pair-interleaved B-fragment order, tf32. Pair (kf, np); lane l float4:
//   { X[kf8+(l&3)][np16+(l>>2)], X[k+4][n], X[k][n+8], X[k+4][n+8] }
// grid (nt=32, kc=20, z), 256 thr. Tile: 64 k-rows x 128 n.
// ---------------------------------------------------------------------------
__global__ void __launch_bounds__(256)
repack_b(const float* __restrict__ Xg, float* __restrict__ Xf, long sX, long sXf)
{
    __shared__ float sB[64 * 132];
    const int nt = blockIdx.x, kc = blockIdx.y, z = blockIdx.z;
    const float* X  = Xg + (long)z * sX;
    float*       Xo = Xf + (long)z * sXf;
    const int t = threadIdx.x;
    #pragma unroll
    for (int i = 0; i < 8; i++) {
        int c = t + i * 256;
        int row = c >> 5, c4 = c & 31;
        float4 v = *(const float4*)(X + (long)(kc * 64 + row) * 4096 + nt * 128 + c4 * 4);
        float* d = sB + row * 132 + c4 * 4;
        d[0] = to_tf32(v.x); d[1] = to_tf32(v.y);
        d[2] = to_tf32(v.z); d[3] = to_tf32(v.w);
    }
    __syncthreads();
    #pragma unroll
    for (int i = 0; i < 8; i++) {
        int o = t + i * 256;
        int fr = o >> 5, l = o & 31;
        int kfl = fr >> 3, np = fr & 7;
        int rb = kfl * 8 + (l & 3);
        int cb = np * 16 + (l >> 2);
        float4 out = make_float4(sB[rb * 132 + cb],       sB[(rb + 4) * 132 + cb],
                                 sB[rb * 132 + cb + 8],   sB[(rb + 4) * 132 + cb + 8]);
        *(float4*)(Xo + ((long)(nt * 160 + kc * 8 + kfl) * 8 + np) * 128 + l * 4) = out;
    }
}

// ---------------------------------------------------------------------------
// gemm_fp: C(1280 x 4096) = Wf (A-frag packed) * Xf (B-frag-pair packed).
// 8 warps x 16 rows, BN=128, BK=32, 3-stage cp.async (96 KB, 2 CTAs/SM).
// grid (nt=32, mt=10, z). C row-major (stride 4096), batch stride sC.
// ---------------------------------------------------------------------------
namespace gp {
constexpr int TILE  = 4096;                 // floats per operand per stage
constexpr int STG   = 2 * TILE;
constexpr int NST   = 3;
constexpr int SMEM  = NST * STG * 4;        // 98,304 B
constexpr int NIT   = 40;                   // K=1280 / BK=32
}

template<bool CVT_OUT, bool BIAS>
__global__ void __launch_bounds__(256, 2)
gemm_fp(const float* __restrict__ Af, const float* __restrict__ Bf,
        float* __restrict__ Cb, long sB, long sC, const float* __restrict__ bias)
{
    extern __shared__ float sm[];
    const int nt = blockIdx.x, mt = blockIdx.y, z = blockIdx.z;
    const float* At = Af + (long)mt * 160 * 8 * 128;
    const float* Bt = Bf + (long)z * sB + (long)nt * 160 * 8 * 128;
    float* C = Cb + (long)z * sC;

    const int t = threadIdx.x, lane = t & 31, w = t >> 5;
    const uint32_t sbase = (uint32_t)__cvta_generic_to_shared(sm);

    auto stage = [&](int it) {
        const int slot = it % gp::NST;
        const uint32_t ab = sbase + (uint32_t)(slot * gp::STG) * 4;
        const uint32_t bb = ab + gp::TILE * 4;
        const float* As = At + (long)it * gp::TILE;
        const float* Bs = Bt + (long)it * gp::TILE;
        #pragma unroll
        for (int i = 0; i < 4; i++) {
            int c = t + i * 256;
            asm volatile("cp.async.cg.shared.global [%0], [%1], 16;\n"
                         :: "r"(ab + (uint32_t)c * 16), "l"(As + c * 4));
        }
        #pragma unroll
        for (int i = 0; i < 4; i++) {
            int c = t + i * 256;
            asm volatile("cp.async.cg.shared.global [%0], [%1], 16;\n"
                         :: "r"(bb + (uint32_t)c * 16), "l"(Bs + c * 4));
        }
        asm volatile("cp.async.commit_group;\n");
    };

    float4 acc[16];
    #pragma unroll
    for (int j = 0; j < 16; j++) acc[j] = make_float4(0.f, 0.f, 0.f, 0.f);

    stage(0); stage(1);

    for (int it = 0; it < gp::NIT; it++) {
        asm volatile("cp.async.wait_group 1;\n" ::: "memory");
        __syncthreads();
        if (it + 2 < gp::NIT) stage(it + 2);

        const float* As_ = sm + (it % gp::NST) * gp::STG;
        const float* Bs_ = As_ + gp::TILE;

        #pragma unroll
        for (int ks = 0; ks < 4; ks++) {
            uint4 a = *(const uint4*)(As_ + (ks * 8 + w) * 128 + (lane << 2));
            #pragma unroll
            for (int np = 0; np < 8; np++) {
                uint4 bv = *(const uint4*)(Bs_ + (ks * 8 + np) * 128 + (lane << 2));
                mma8(acc[2 * np],     a, make_uint2(bv.x, bv.y));
                mma8(acc[2 * np + 1], a, make_uint2(bv.z, bv.w));
            }
        }
    }

    const int m0 = mt * 128 + w * 16 + (lane >> 2);
    const int nb = nt * 128 + (lane & 3) * 2;
    float b0 = 0.f, b1 = 0.f;
    if (BIAS) { b0 = bias[m0]; b1 = bias[m0 + 8]; }
    #pragma unroll
    for (int j = 0; j < 16; j++) {
        float4 ac = acc[j];
        float o0 = ac.x + b0, o1 = ac.y + b0;
        float o2 = ac.z + b1, o3 = ac.w + b1;
        if (CVT_OUT) { o0 = to_tf32(o0); o1 = to_tf32(o1);
                       o2 = to_tf32(o2); o3 = to_tf32(o3); }
        int n = nb + j * 8;
        *(float2*)(C + (long)m0 * 4096 + n)       = make_float2(o0, o1);
        *(float2*)(C + (long)(m0 + 8) * 4096 + n) = make_float2(o2, o3);
    }
}

// ---------------------------------------------------------------------------
// repack_kv (round 9, unchanged): K/V -> pair-interleaved B-fragment order.
// ---------------------------------------------------------------------------
__global__ void __launch_bounds__(256)
repack_kv(const float* __restrict__ kg, const float* __restrict__ vg,
          float* __restrict__ kf, float* __restrict__ vf)
{
    using namespace cfg;
    __shared__ float sK[160 * 33], sV[160 * 33];
    const int kt = blockIdx.x, bh = blockIdx.y;
    const long base = (long)bh * D * S;
    const int k0 = kt * 32;
    const int t = threadIdx.x;

    #pragma unroll
    for (int i = 0; i < 5; i++) {
        int f = t + i * 256;
        int row = f >> 3, cv = f & 7;
        float4 a = *(const float4*)(kg + base + (long)row * S + k0 + cv * 4);
        float4 b = *(const float4*)(vg + base + (long)row * S + k0 + cv * 4);
        int sa = row * 33 + cv * 4;
        sK[sa] = a.x; sK[sa + 1] = a.y; sK[sa + 2] = a.z; sK[sa + 3] = a.w;
        sV[sa] = b.x; sV[sa + 1] = b.y; sV[sa + 2] = b.z; sV[sa + 3] = b.w;
    }
    __syncthreads();

    const long obase = ((long)bh * 128 + kt) * 5120;
    #pragma unroll
    for (int i = 0; i < 5; i++) {
        int g = t + i * 256;
        int pr = g >> 5, l = g & 31;
        {
            int ks = pr >> 1, nt2 = pr & 1;
            int d0 = ks * 8 + (l & 3);
            int kpe = nt2 * 16 + (l >> 2);
            float4 o = make_float4(sK[d0 * 33 + kpe],       sK[(d0 + 4) * 33 + kpe],
                                   sK[d0 * 33 + kpe + 8],   sK[(d0 + 4) * 33 + kpe + 8]);
            *(float4*)(kf + obase + pr * 128 + l * 4) = o;
        }
        {
            int ks2 = pr / 10, nf2 = pr % 10;
            int de = nf2 * 16 + (l >> 2);
            int kp0 = ks2 * 8 + (l & 3);
            float4 o = make_float4(sV[de * 33 + kp0],       sV[de * 33 + kp0 + 4],
                                   sV[(de + 8) * 33 + kp0], sV[(de + 8) * 33 + kp0 + 4]);
            *(float4*)(vf + obase + pr * 128 + l * 4) = o;
        }
    }
}

// ---------------------------------------------------------------------------
// Flash attention (round 9, unchanged): 8 warps x 16 q-rows, Q in registers,
// paired B fragments, 4-stage cp.async.
// ---------------------------------------------------------------------------
namespace f3 {
constexpr int BQ   = 128;
constexpr int BK   = 32;
constexpr int NTLE = cfg::S / BK;
constexpr int KSZ  = 5120;
constexpr int VSZ  = 5120;
constexpr int MSZ  = 32;
constexpr int STG  = KSZ + VSZ + MSZ;
constexpr int NST  = 4;
constexpr int SMEM = NST * STG * 4;
}

__global__ void __launch_bounds__(256, 1)
flash3(const float* __restrict__ qg, const float* __restrict__ kfg,
       const float* __restrict__ vfg, const float* __restrict__ mask,
       float* __restrict__ og, float scale)
{
    using namespace cfg;
    extern __shared__ float sm[];

    const int qt = blockIdx.x, bh = blockIdx.y, b = bh / H;
    const long base = (long)bh * D * S;
    const float* Q = qg + base;
    float* O = og + base;
    const float* Kf = kfg + (long)bh * 128 * 5120;
    const float* Vf = vfg + (long)bh * 128 * 5120;
    const float* mrow = mask + (long)b * S;
    const int q0 = qt * f3::BQ;

    const int t = threadIdx.x, lane = t & 31, w = t >> 5;
    const int grp = lane >> 2, tig = lane & 3;

    uint4 qa[20];
    {
        const int m0 = q0 + w * 16 + grp;
        #pragma unroll
        for (int ks = 0; ks < 20; ks++) {
            int d0 = ks * 8 + tig;
            qa[ks] = make_uint4(
                __float_as_uint(Q[(long)d0 * S + m0]),
                __float_as_uint(Q[(long)d0 * S + m0 + 8]),
                __float_as_uint(Q[(long)(d0 + 4) * S + m0]),
                __float_as_uint(Q[(long)(d0 + 4) * S + m0 + 8]));
        }
    }

    const uint32_t sbase = (uint32_t)__cvta_generic_to_shared(sm);

    auto stage = [&](int tile) {
        const int slot = tile & (f3::NST - 1);
        const uint32_t kb = sbase + (uint32_t)(slot * f3::STG) * 4;
        const uint32_t vb = kb + f3::KSZ * 4;
        const uint32_t mb = vb + f3::VSZ * 4;
        const float* Kt = Kf + (long)tile * 5120;
        const float* Vt = Vf + (long)tile * 5120;
        #pragma unroll
        for (int i = 0; i < 5; i++) {
            int c = t + i * 256;
            asm volatile("cp.async.cg.shared.global [%0], [%1], 16;\n"
                         :: "r"(kb + (uint32_t)c * 16), "l"(Kt + c * 4));
        }
        #pragma unroll
        for (int i = 0; i < 5; i++) {
            int c = t + i * 256;
            asm volatile("cp.async.cg.shared.global [%0], [%1], 16;\n"
                         :: "r"(vb + (uint32_t)c * 16), "l"(Vt + c * 4));
        }
        if (t < 8) {
            const float* src = mrow + tile * f3::BK + t * 4;
            asm volatile("cp.async.cg.shared.global [%0], [%1], 16;\n"
                         :: "r"(mb + (uint32_t)t * 16), "l"(src));
        }
        asm volatile("cp.async.commit_group;\n");
    };

    float4 oacc[20];
    #pragma unroll
    for (int j = 0; j < 20; j++) oacc[j] = make_float4(0.f, 0.f, 0.f, 0.f);
    float mrun0 = -1e30f, mrun1 = -1e30f;
    float lrun0 = 0.f, lrun1 = 0.f;

    stage(0); stage(1); stage(2);

    for (int it = 0; it < f3::NTLE; it++) {
        asm volatile("cp.async.wait_group 2;\n" ::: "memory");
        __syncthreads();
        if (it + 3 < f3::NTLE) stage(it + 3);
        else asm volatile("cp.async.commit_group;\n");

        const float* Kb = sm + (it & (f3::NST - 1)) * f3::STG;
        const float* Vb = Kb + f3::KSZ;
        const float* Mb = Vb + f3::VSZ;

        float4 sacc[4];
        #pragma unroll
        for (int j = 0; j < 4; j++) sacc[j] = make_float4(0.f, 0.f, 0.f, 0.f);
        #pragma unroll
        for (int ks = 0; ks < 20; ks++) {
            uint4 b0 = *(const uint4*)(Kb + (ks * 2) * 128 + (lane << 2));
            uint4 b1 = *(const uint4*)(Kb + (ks * 2 + 1) * 128 + (lane << 2));
            mma8(sacc[0], qa[ks], make_uint2(b0.x, b0.y));
            mma8(sacc[1], qa[ks], make_uint2(b0.z, b0.w));
            mma8(sacc[2], qa[ks], make_uint2(b1.x, b1.y));
            mma8(sacc[3], qa[ks], make_uint2(b1.z, b1.w));
        }

        {
            float r0 = -1e30f, r1 = -1e30f;
            #pragma unroll
            for (int nt = 0; nt < 4; nt++) {
                float mv0 = Mb[nt * 8 + tig * 2];
                float mv1 = Mb[nt * 8 + tig * 2 + 1];
                float4& s = sacc[nt];
                s.x = fmaf(s.x, scale, mv0);  s.y = fmaf(s.y, scale, mv1);
                s.z = fmaf(s.z, scale, mv0);  s.w = fmaf(s.w, scale, mv1);
                r0 = fmaxf(r0, fmaxf(s.x, s.y));
                r1 = fmaxf(r1, fmaxf(s.z, s.w));
            }
            r0 = fmaxf(r0, __shfl_xor_sync(0xffffffffu, r0, 1));
            r0 = fmaxf(r0, __shfl_xor_sync(0xffffffffu, r0, 2));
            r1 = fmaxf(r1, __shfl_xor_sync(0xffffffffu, r1, 1));
            r1 = fmaxf(r1, __shfl_xor_sync(0xffffffffu, r1, 2));
            float mn0 = fmaxf(mrun0, r0);
            float mn1 = fmaxf(mrun1, r1);
            float a0 = __expf(mrun0 - mn0);
            float a1 = __expf(mrun1 - mn1);
            mrun0 = mn0;  mrun1 = mn1;

            float su0 = 0.f, su1 = 0.f;
            #pragma unroll
            for (int nt = 0; nt < 4; nt++) {
                float4& s = sacc[nt];
                s.x = __expf(s.x - mn0);  s.y = __expf(s.y - mn0);
                s.z = __expf(s.z - mn1);  s.w = __expf(s.w - mn1);
                su0 += s.x + s.y;  su1 += s.z + s.w;
            }
            su0 += __shfl_xor_sync(0xffffffffu, su0, 1);
            su0 += __shfl_xor_sync(0xffffffffu, su0, 2);
            su1 += __shfl_xor_sync(0xffffffffu, su1, 1);
            su1 += __shfl_xor_sync(0xffffffffu, su1, 2);
            lrun0 = lrun0 * a0 + su0;
            lrun1 = lrun1 * a1 + su1;
            #pragma unroll
            for (int nf = 0; nf < 20; nf++) {
                oacc[nf].x *= a0;  oacc[nf].y *= a0;
                oacc[nf].z *= a1;  oacc[nf].w *= a1;
            }
        }

        #pragma unroll
        for (int ks2 = 0; ks2 < 4; ks2++) {
            uint4 pa;
            const int src = (lane & ~3) | (tig >> 1);
            {
                float4 c = sacc[ks2];
                float s0  = __shfl_sync(0xffffffffu, c.x, src);
                float s1  = __shfl_sync(0xffffffffu, c.y, src);
                float s0b = __shfl_sync(0xffffffffu, c.x, src + 2);
                float s1b = __shfl_sync(0xffffffffu, c.y, src + 2);
                float A0 = (tig & 1) ? s1 : s0;
                float A2 = (tig & 1) ? s1b : s0b;
                s0  = __shfl_sync(0xffffffffu, c.z, src);
                s1  = __shfl_sync(0xffffffffu, c.w, src);
                s0b = __shfl_sync(0xffffffffu, c.z, src + 2);
                s1b = __shfl_sync(0xffffffffu, c.w, src + 2);
                float A1 = (tig & 1) ? s1 : s0;
                float A3 = (tig & 1) ? s1b : s0b;
                pa = make_uint4(__float_as_uint(A0), __float_as_uint(A1),
                                __float_as_uint(A2), __float_as_uint(A3));
            }
            #pragma unroll
            for (int nf2 = 0; nf2 < 10; nf2++) {
                uint4 bb = *(const uint4*)(Vb + (ks2 * 10 + nf2) * 128 + (lane << 2));
                mma8(oacc[2 * nf2],     pa, make_uint2(bb.x, bb.y));
                mma8(oacc[2 * nf2 + 1], pa, make_uint2(bb.z, bb.w));
            }
        }
    }

    {
        int r0 = w * 16 + grp;
        int gq = q0 + r0;
        float il0 = 1.0f / lrun0;
        float il1 = 1.0f / lrun1;
        #pragma unroll
        for (int nf = 0; nf < 20; nf++) {
            int d = nf * 8 + tig * 2;
            float4 oa = oacc[nf];
            O[(long)d * S + gq]           = oa.x * il0;
            O[(long)(d + 1) * S + gq]     = oa.y * il0;
            O[(long)d * S + gq + 8]       = oa.z * il1;
            O[(long)(d + 1) * S + gq + 8] = oa.w * il1;
        }
    }
}

// ---------------------------------------------------------------------------
extern "C" void kernel_launch(void* const* d_in, const int* in_sizes, int n_in,
                              void* d_out, int out_size)
{
    using namespace cfg;
    (void)in_sizes; (void)n_in; (void)out_size;

    const float* hidden  = (const float*)d_in[0];  // (B, QD, 1, S)
    const float* context = (const float*)d_in[1];
    const float* mask    = (const float*)d_in[2];  // (B, S, 1, 1)
    const float* Wq      = (const float*)d_in[3];  // (IN, QD)
    const float* Wk      = (const float*)d_in[4];
    const float* Wv      = (const float*)d_in[5];
    const float* Wout    = (const float*)d_in[6];  // (QD, IN)
    const float* bout    = (const float*)d_in[7];
    float*       out     = (float*)d_out;          // (B, QD, 1, S)

    void *pq, *pk, *pv, *pa, *pkf, *pvf, *pwq, *pwk, *pwv, *pwo, *phf, *pcf, *paf;
    cudaGetSymbolAddress(&pq,  g_q);
    cudaGetSymbolAddress(&pk,  g_k);
    cudaGetSymbolAddress(&pv,  g_v);
    cudaGetSymbolAddress(&pa,  g_attn);
    cudaGetSymbolAddress(&pkf, g_kf);
    cudaGetSymbolAddress(&pvf, g_vf);
    cudaGetSymbolAddress(&pwq, g_wqf);
    cudaGetSymbolAddress(&pwk, g_wkf);
    cudaGetSymbolAddress(&pwv, g_wvf);
    cudaGetSymbolAddress(&pwo, g_wof);
    cudaGetSymbolAddress(&phf, g_hf);
    cudaGetSymbolAddress(&pcf, g_cf);
    cudaGetSymbolAddress(&paf, g_af);
    float* q   = (float*)pq;
    float* k   = (float*)pk;
    float* v   = (float*)pv;
    float* at  = (float*)pa;
    float* kf  = (float*)pkf;
    float* vf  = (float*)pvf;
    float* wqf = (float*)pwq;
    float* wkf = (float*)pwk;
    float* wvf = (float*)pwv;
    float* wof = (float*)pwo;
    float* hf  = (float*)phf;
    float* cf  = (float*)pcf;
    float* af  = (float*)paf;

    const float scale = 1.0f / sqrtf((float)D);
    const long sPack = (long)32 * 160 * 8 * 128;   // per-batch packed activation
    const long sAct  = (long)QD * S;               // per-batch activation

    cudaFuncSetAttribute(flash3,
                         cudaFuncAttributeMaxDynamicSharedMemorySize, f3::SMEM);
    cudaFuncSetAttribute(gemm_fp<true, false>,
                         cudaFuncAttributeMaxDynamicSharedMemorySize, gp::SMEM);
    cudaFuncSetAttribute(gemm_fp<false, true>,
                         cudaFuncAttributeMaxDynamicSharedMemorySize, gp::SMEM);

    // 1. pack weights (A-fragment order, tf32)
    dim3 gra(10, 20);
    repack_a<<<gra, 256>>>(Wq,   wqf);
    repack_a<<<gra, 256>>>(Wk,   wkf);
    repack_a<<<gra, 256>>>(Wv,   wvf);
    repack_a<<<gra, 256>>>(Wout, wof);

    // 2. pack activations (B-fragment-pair order, tf32)
    dim3 grb(32, 20, B);
    repack_b<<<grb, 256>>>(hidden,  hf, sAct, sPack);
    repack_b<<<grb, 256>>>(context, cf, sAct, sPack);

    // 3. projections
    dim3 gg(32, 10, B);
    gemm_fp<true, false><<<gg, 256, gp::SMEM>>>(wqf, hf, q, sPack, sAct, nullptr);
    gemm_fp<true, false><<<gg, 256, gp::SMEM>>>(wkf, cf, k, sPack, sAct, nullptr);
    gemm_fp<true, false><<<gg, 256, gp::SMEM>>>(wvf, cf, v, sPack, sAct, nullptr);

    // 4. pack K/V for flash
    dim3 grep(128, B * H);
    repack_kv<<<grep, 256>>>(k, v, kf, vf);

    // 5. fused attention
    dim3 gfl(S / f3::BQ, B * H);
    flash3<<<gfl, 256, f3::SMEM>>>(q, kf, vf, mask, at, scale);

    // 6. pack attn, then out = Wout * attn + bout
    repack_b<<<grb, 256>>>(at, af, sAct, sPack);
    gemm_fp<false, true><<<gg, 256, gp::SMEM>>>(wof, af, out, sPack, sAct, bout);
}

// round 11
// speedup vs baseline: 6.8603x; 1.1421x over previous
#include <cuda_runtime.h>
#include <math.h>
#include <stdint.h>

// ---------------------------------------------------------------------------
// CrossAttention, round 11: flash split into 128-thread CTAs (2 independent
// CTAs/SM instead of one coupled 256-thread CTA); projection launches merged.
// B=2, S=4096, H=8, D=160, QUERY_DIM=INNER=1280
// ---------------------------------------------------------------------------

namespace cfg {
constexpr int B  = 2;
constexpr int S  = 4096;
constexpr int H  = 8;
constexpr int D  = 160;
constexpr int QD = 1280;
constexpr int IN = 1280;
}

constexpr long WSZ   = (long)10 * 160 * 8 * 128;   // packed weight size
constexpr long SPACK = (long)32 * 160 * 8 * 128;   // packed activation / batch

__device__ float g_q[(size_t)cfg::B * cfg::IN * cfg::S];
__device__ float g_k[(size_t)cfg::B * cfg::IN * cfg::S];
__device__ float g_v[(size_t)cfg::B * cfg::IN * cfg::S];
__device__ float g_attn[(size_t)cfg::B * cfg::IN * cfg::S];
// pair-interleaved fragment-packed K/V for flash: [bh][ktile][40 pairs][128]
__device__ float g_kf[(size_t)cfg::B * cfg::H * 128 * 40 * 128];
__device__ float g_vf[(size_t)cfg::B * cfg::H * 128 * 40 * 128];
// A-fragment-packed weights, one block: [Wq | Wk | Wv | Wout]
__device__ float g_wf[(size_t)4 * WSZ];
// B-fragment-pair-packed activations
__device__ float g_hf[(size_t)cfg::B * SPACK];
__device__ float g_cf[(size_t)cfg::B * SPACK];
__device__ float g_af[(size_t)cfg::B * SPACK];

__device__ __forceinline__ float to_tf32(float x) {
    float r; asm("cvt.rna.tf32.f32 %0, %1;" : "=f"(r) : "f"(x)); return r;
}

__device__ __forceinline__ void mma8(float4& d, const uint4& a, const uint2& b) {
    asm volatile(
        "mma.sync.aligned.m16n8k8.row.col.f32.tf32.tf32.f32 "
        "{%0,%1,%2,%3}, {%4,%5,%6,%7}, {%8,%9}, {%0,%1,%2,%3};\n"
        : "+f"(d.x), "+f"(d.y), "+f"(d.z), "+f"(d.w)
        : "r"(a.x), "r"(a.y), "r"(a.z), "r"(a.w), "r"(b.x), "r"(b.y));
}

// ---------------------------------------------------------------------------
// repack_a4: all four weights -> A-fragment order (tf32), one launch.
// grid (kc=10, mc=20, z=4), 256 thr.
// ---------------------------------------------------------------------------
__global__ void __launch_bounds__(256)
repack_a4(const float* __restrict__ w0, const float* __restrict__ w1,
          const float* __restrict__ w2, const float* __restrict__ w3,
          float* __restrict__ wf_all)
{
    __shared__ float sW[64 * 132];
    const int kc = blockIdx.x, mc = blockIdx.y, z = blockIdx.z;
    const float* Wg = (z == 0) ? w0 : (z == 1) ? w1 : (z == 2) ? w2 : w3;
    float* Wf = wf_all + (long)z * WSZ;
    const int t = threadIdx.x;
    #pragma unroll
    for (int i = 0; i < 8; i++) {
        int c = t + i * 256;
        int row = c >> 5, c4 = c & 31;
        float4 v = *(const float4*)(Wg + (long)(mc * 64 + row) * 1280 + kc * 128 + c4 * 4);
        float* d = sW + row * 132 + c4 * 4;
        d[0] = to_tf32(v.x); d[1] = to_tf32(v.y);
        d[2] = to_tf32(v.z); d[3] = to_tf32(v.w);
    }
    __syncthreads();
    const int mt = mc >> 1, mgh = (mc & 1) * 4;
    #pragma unroll
    for (int i = 0; i < 8; i++) {
        int o = t + i * 256;
        int fr = o >> 5, l = o & 31;
        int kfl = fr >> 2, mg = fr & 3;
        int rb = mg * 16 + (l >> 2);
        int cb = kfl * 8 + (l & 3);
        float4 out = make_float4(sW[rb * 132 + cb],       sW[(rb + 8) * 132 + cb],
                                 sW[rb * 132 + cb + 4],   sW[(rb + 8) * 132 + cb + 4]);
        *(float4*)(Wf + ((long)(mt * 160 + kc * 16 + kfl) * 8 + mgh + mg) * 128 + l * 4) = out;
    }
}

// ---------------------------------------------------------------------------
// repack_b core (shared by the merged and single variants).
// ---------------------------------------------------------------------------
__device__ __forceinline__ void repack_b_body(const float* __restrict__ X,
                                              float* __restrict__ Xo,
                                              int nt, int kc, int t, float* sB)
{
    #pragma unroll
    for (int i = 0; i < 8; i++) {
        int c = t + i * 256;
        int row = c >> 5, c4 = c & 31;
        float4 v = *(const float4*)(X + (long)(kc * 64 + row) * 4096 + nt * 128 + c4 * 4);
        float* d = sB + row * 132 + c4 * 4;
        d[0] = to_tf32(v.x); d[1] = to_tf32(v.y);
        d[2] = to_tf32(v.z); d[3] = to_tf32(v.w);
    }
    __syncthreads();
    #pragma unroll
    for (int i = 0; i < 8; i++) {
        int o = t + i * 256;
        int fr = o >> 5, l = o & 31;
        int kfl = fr >> 3, np = fr & 7;
        int rb = kfl * 8 + (l & 3);
        int cb = np * 16 + (l >> 2);
        float4 out = make_float4(sB[rb * 132 + cb],       sB[(rb + 4) * 132 + cb],
                                 sB[rb * 132 + cb + 8],   sB[(rb + 4) * 132 + cb + 8]);
        *(float4*)(Xo + ((long)(nt * 160 + kc * 8 + kfl) * 8 + np) * 128 + l * 4) = out;
    }
}

// merged hidden+context pack: grid (32, 20, 2*B); z = which*B + b
__global__ void __launch_bounds__(256)
repack_b2(const float* __restrict__ hidden, const float* __restrict__ context,
          float* __restrict__ hf, float* __restrict__ cf, long sX)
{
    __shared__ float sB[64 * 132];
    const int z = blockIdx.z;
    const int which = z / cfg::B, b = z % cfg::B;
    const float* X  = (which ? context : hidden) + (long)b * sX;
    float*       Xo = (which ? cf : hf) + (long)b * SPACK;
    repack_b_body(X, Xo, blockIdx.x, blockIdx.y, threadIdx.x, sB);
}

// single-source pack (attn): grid (32, 20, B)
__global__ void __launch_bounds__(256)
repack_b(const float* __restrict__ Xg, float* __restrict__ Xf, long sX, long sXf)
{
    __shared__ float sB[64 * 132];
    const int z = blockIdx.z;
    repack_b_body(Xg + (long)z * sX, Xf + (long)z * sXf,
                  blockIdx.x, blockIdx.y, threadIdx.x, sB);
}

// ---------------------------------------------------------------------------
// gemm core: C(1280 x 4096) = Af (A-frag) * Bf (B-frag-pair), 8 warps x 16
// rows, BN=128, BK=32, 3-stage cp.async (96 KB, 2 CTAs/SM).
// ---------------------------------------------------------------------------
namespace gp {
constexpr int TILE  = 4096;
constexpr int STG   = 2 * TILE;
constexpr int NST   = 3;
constexpr int SMEM  = NST * STG * 4;        // 98,304 B
constexpr int NIT   = 40;
}

template<bool CVT_OUT, bool BIAS>
__device__ __forceinline__ void gemm_body(const float* At, const float* Bt,
                                          float* C, const float* bias,
                                          int nt, int mt, float* sm)
{
    const int t = threadIdx.x, lane = t & 31, w = t >> 5;
    const uint32_t sbase = (uint32_t)__cvta_generic_to_shared(sm);

    auto stage = [&](int it) {
        const int slot = it % gp::NST;
        const uint32_t ab = sbase + (uint32_t)(slot * gp::STG) * 4;
        const uint32_t bb = ab + gp::TILE * 4;
        const float* As = At + (long)it * gp::TILE;
        const float* Bs = Bt + (long)it * gp::TILE;
        #pragma unroll
        for (int i = 0; i < 4; i++) {
            int c = t + i * 256;
            asm volatile("cp.async.cg.shared.global [%0], [%1], 16;\n"
                         :: "r"(ab + (uint32_t)c * 16), "l"(As + c * 4));
        }
        #pragma unroll
        for (int i = 0; i < 4; i++) {
            int c = t + i * 256;
            asm volatile("cp.async.cg.shared.global [%0], [%1], 16;\n"
                         :: "r"(bb + (uint32_t)c * 16), "l"(Bs + c * 4));
        }
        asm volatile("cp.async.commit_group;\n");
    };

    float4 acc[16];
    #pragma unroll
    for (int j = 0; j < 16; j++) acc[j] = make_float4(0.f, 0.f, 0.f, 0.f);

    stage(0); stage(1);

    for (int it = 0; it < gp::NIT; it++) {
        asm volatile("cp.async.wait_group 1;\n" ::: "memory");
        __syncthreads();
        if (it + 2 < gp::NIT) stage(it + 2);

        const float* As_ = sm + (it % gp::NST) * gp::STG;
        const float* Bs_ = As_ + gp::TILE;

        #pragma unroll
        for (int ks = 0; ks < 4; ks++) {
            uint4 a = *(const uint4*)(As_ + (ks * 8 + w) * 128 + (lane << 2));
            #pragma unroll
            for (int np = 0; np < 8; np++) {
                uint4 bv = *(const uint4*)(Bs_ + (ks * 8 + np) * 128 + (lane << 2));
                mma8(acc[2 * np],     a, make_uint2(bv.x, bv.y));
                mma8(acc[2 * np + 1], a, make_uint2(bv.z, bv.w));
            }
        }
    }

    const int m0 = mt * 128 + w * 16 + (lane >> 2);
    const int nb = nt * 128 + (lane & 3) * 2;
    float b0 = 0.f, b1 = 0.f;
    if (BIAS) { b0 = bias[m0]; b1 = bias[m0 + 8]; }
    #pragma unroll
    for (int j = 0; j < 16; j++) {
        float4 ac = acc[j];
        float o0 = ac.x + b0, o1 = ac.y + b0;
        float o2 = ac.z + b1, o3 = ac.w + b1;
        if (CVT_OUT) { o0 = to_tf32(o0); o1 = to_tf32(o1);
                       o2 = to_tf32(o2); o3 = to_tf32(o3); }
        int n = nb + j * 8;
        *(float2*)(C + (long)m0 * 4096 + n)       = make_float2(o0, o1);
        *(float2*)(C + (long)(m0 + 8) * 4096 + n) = make_float2(o2, o3);
    }
}

// merged q/k/v projections: grid (32, 10, 3*B); z = p*B + b
__global__ void __launch_bounds__(256, 2)
gemm_proj(const float* __restrict__ wf, const float* __restrict__ hf,
          const float* __restrict__ cf, float* __restrict__ q,
          float* __restrict__ k, float* __restrict__ v, long sC)
{
    extern __shared__ float sm[];
    const int nt = blockIdx.x, mt = blockIdx.y, z = blockIdx.z;
    const int p = z / cfg::B, b = z % cfg::B;
    const float* At = wf + (long)p * WSZ + (long)mt * 160 * 8 * 128;
    const float* Bt = ((p == 0) ? hf : cf) + (long)b * SPACK + (long)nt * 160 * 8 * 128;
    float* C = ((p == 0) ? q : (p == 1) ? k : v) + (long)b * sC;
    gemm_body<true, false>(At, Bt, C, nullptr, nt, mt, sm);
}

// out projection: grid (32, 10, B)
__global__ void __launch_bounds__(256, 2)
gemm_out(const float* __restrict__ wf, const float* __restrict__ af,
         float* __restrict__ out, long sC, const float* __restrict__ bias)
{
    extern __shared__ float sm[];
    const int nt = blockIdx.x, mt = blockIdx.y, z = blockIdx.z;
    const float* At = wf + (long)3 * WSZ + (long)mt * 160 * 8 * 128;
    const float* Bt = af + (long)z * SPACK + (long)nt * 160 * 8 * 128;
    float* C = out + (long)z * sC;
    gemm_body<false, true>(At, Bt, C, bias, nt, mt, sm);
}

// ---------------------------------------------------------------------------
// repack_kv (unchanged): K/V -> pair-interleaved B-fragment order.
// ---------------------------------------------------------------------------
__global__ void __launch_bounds__(256)
repack_kv(const float* __restrict__ kg, const float* __restrict__ vg,
          float* __restrict__ kf, float* __restrict__ vf)
{
    using namespace cfg;
    __shared__ float sK[160 * 33], sV[160 * 33];
    const int kt = blockIdx.x, bh = blockIdx.y;
    const long base = (long)bh * D * S;
    const int k0 = kt * 32;
    const int t = threadIdx.x;

    #pragma unroll
    for (int i = 0; i < 5; i++) {
        int f = t + i * 256;
        int row = f >> 3, cv = f & 7;
        float4 a = *(const float4*)(kg + base + (long)row * S + k0 + cv * 4);
        float4 b = *(const float4*)(vg + base + (long)row * S + k0 + cv * 4);
        int sa = row * 33 + cv * 4;
        sK[sa] = a.x; sK[sa + 1] = a.y; sK[sa + 2] = a.z; sK[sa + 3] = a.w;
        sV[sa] = b.x; sV[sa + 1] = b.y; sV[sa + 2] = b.z; sV[sa + 3] = b.w;
    }
    __syncthreads();

    const long obase = ((long)bh * 128 + kt) * 5120;
    #pragma unroll
    for (int i = 0; i < 5; i++) {
        int g = t + i * 256;
        int pr = g >> 5, l = g & 31;
        {
            int ks = pr >> 1, nt2 = pr & 1;
            int d0 = ks * 8 + (l & 3);
            int kpe = nt2 * 16 + (l >> 2);
            float4 o = make_float4(sK[d0 * 33 + kpe],       sK[(d0 + 4) * 33 + kpe],
                                   sK[d0 * 33 + kpe + 8],   sK[(d0 + 4) * 33 + kpe + 8]);
            *(float4*)(kf + obase + pr * 128 + l * 4) = o;
        }
        {
            int ks2 = pr / 10, nf2 = pr % 10;
            int de = nf2 * 16 + (l >> 2);
            int kp0 = ks2 * 8 + (l & 3);
            float4 o = make_float4(sV[de * 33 + kp0],       sV[de * 33 + kp0 + 4],
                                   sV[(de + 8) * 33 + kp0], sV[(de + 8) * 33 + kp0 + 4]);
            *(float4*)(vf + obase + pr * 128 + l * 4) = o;
        }
    }
}

// ---------------------------------------------------------------------------
// Flash attention v6: 128-thread CTAs (4 warps x 16 q-rows, BQ=64), 2-stage
// cp.async, 2 independent CTAs per SM. Q in registers, paired B fragments.
// ---------------------------------------------------------------------------
namespace f4 {
constexpr int BQ   = 64;
constexpr int BK   = 32;
constexpr int NTLE = cfg::S / BK;           // 128
constexpr int KSZ  = 5120;
constexpr int VSZ  = 5120;
constexpr int MSZ  = 32;
constexpr int STG  = KSZ + VSZ + MSZ;       // 10272 floats
constexpr int NST  = 2;
constexpr int SMEM = NST * STG * 4;         // 82,176 B -> 2 CTAs/SM
}

__global__ void __launch_bounds__(128, 2)
flash4(const float* __restrict__ qg, const float* __restrict__ kfg,
       const float* __restrict__ vfg, const float* __restrict__ mask,
       float* __restrict__ og, float scale)
{
    using namespace cfg;
    extern __shared__ float sm[];

    const int qt = blockIdx.x, bh = blockIdx.y, b = bh / H;
    const long base = (long)bh * D * S;
    const float* Q = qg + base;
    float* O = og + base;
    const float* Kf = kfg + (long)bh * 128 * 5120;
    const float* Vf = vfg + (long)bh * 128 * 5120;
    const float* mrow = mask + (long)b * S;
    const int q0 = qt * f4::BQ;

    const int t = threadIdx.x, lane = t & 31, w = t >> 5;
    const int grp = lane >> 2, tig = lane & 3;

    uint4 qa[20];
    {
        const int m0 = q0 + w * 16 + grp;
        #pragma unroll
        for (int ks = 0; ks < 20; ks++) {
            int d0 = ks * 8 + tig;
            qa[ks] = make_uint4(
                __float_as_uint(Q[(long)d0 * S + m0]),
                __float_as_uint(Q[(long)d0 * S + m0 + 8]),
                __float_as_uint(Q[(long)(d0 + 4) * S + m0]),
                __float_as_uint(Q[(long)(d0 + 4) * S + m0 + 8]));
        }
    }

    const uint32_t sbase = (uint32_t)__cvta_generic_to_shared(sm);

    auto stage = [&](int tile) {
        const int slot = tile & (f4::NST - 1);
        const uint32_t kb = sbase + (uint32_t)(slot * f4::STG) * 4;
        const uint32_t vb = kb + f4::KSZ * 4;
        const uint32_t mb = vb + f4::VSZ * 4;
        const float* Kt = Kf + (long)tile * 5120;
        const float* Vt = Vf + (long)tile * 5120;
        #pragma unroll
        for (int i = 0; i < 10; i++) {
            int c = t + i * 128;
            asm volatile("cp.async.cg.shared.global [%0], [%1], 16;\n"
                         :: "r"(kb + (uint32_t)c * 16), "l"(Kt + c * 4));
        }
        #pragma unroll
        for (int i = 0; i < 10; i++) {
            int c = t + i * 128;
            asm volatile("cp.async.cg.shared.global [%0], [%1], 16;\n"
                         :: "r"(vb + (uint32_t)c * 16), "l"(Vt + c * 4));
        }
        if (t < 8) {
            const float* src = mrow + tile * f4::BK + t * 4;
            asm volatile("cp.async.cg.shared.global [%0], [%1], 16;\n"
                         :: "r"(mb + (uint32_t)t * 16), "l"(src));
        }
        asm volatile("cp.async.commit_group;\n");
    };

    float4 oacc[20];
    #pragma unroll
    for (int j = 0; j < 20; j++) oacc[j] = make_float4(0.f, 0.f, 0.f, 0.f);
    float mrun0 = -1e30f, mrun1 = -1e30f;
    float lrun0 = 0.f, lrun1 = 0.f;

    stage(0);

    for (int it = 0; it < f4::NTLE; it++) {
        asm volatile("cp.async.wait_group 0;\n" ::: "memory");
        __syncthreads();
        if (it + 1 < f4::NTLE) stage(it + 1);

        const float* Kb = sm + (it & (f4::NST - 1)) * f4::STG;
        const float* Vb = Kb + f4::KSZ;
        const float* Mb = Vb + f4::VSZ;

        // ---- GEMM1: scores(16q x 32k) ----
        float4 sacc[4];
        #pragma unroll
        for (int j = 0; j < 4; j++) sacc[j] = make_float4(0.f, 0.f, 0.f, 0.f);
        #pragma unroll
        for (int ks = 0; ks < 20; ks++) {
            uint4 b0 = *(const uint4*)(Kb + (ks * 2) * 128 + (lane << 2));
            uint4 b1 = *(const uint4*)(Kb + (ks * 2 + 1) * 128 + (lane << 2));
            mma8(sacc[0], qa[ks], make_uint2(b0.x, b0.y));
            mma8(sacc[1], qa[ks], make_uint2(b0.z, b0.w));
            mma8(sacc[2], qa[ks], make_uint2(b1.x, b1.y));
            mma8(sacc[3], qa[ks], make_uint2(b1.z, b1.w));
        }

        // ---- softmax (register/warp-shuffle; rows owned by this warp) ------
        {
            float r0 = -1e30f, r1 = -1e30f;
            #pragma unroll
            for (int nt = 0; nt < 4; nt++) {
                float mv0 = Mb[nt * 8 + tig * 2];
                float mv1 = Mb[nt * 8 + tig * 2 + 1];
                float4& s = sacc[nt];
                s.x = fmaf(s.x, scale, mv0);  s.y = fmaf(s.y, scale, mv1);
                s.z = fmaf(s.z, scale, mv0);  s.w = fmaf(s.w, scale, mv1);
                r0 = fmaxf(r0, fmaxf(s.x, s.y));
                r1 = fmaxf(r1, fmaxf(s.z, s.w));
            }
            r0 = fmaxf(r0, __shfl_xor_sync(0xffffffffu, r0, 1));
            r0 = fmaxf(r0, __shfl_xor_sync(0xffffffffu, r0, 2));
            r1 = fmaxf(r1, __shfl_xor_sync(0xffffffffu, r1, 1));
            r1 = fmaxf(r1, __shfl_xor_sync(0xffffffffu, r1, 2));
            float mn0 = fmaxf(mrun0, r0);
            float mn1 = fmaxf(mrun1, r1);
            float a0 = __expf(mrun0 - mn0);
            float a1 = __expf(mrun1 - mn1);
            mrun0 = mn0;  mrun1 = mn1;

            float su0 = 0.f, su1 = 0.f;
            #pragma unroll
            for (int nt = 0; nt < 4; nt++) {
                float4& s = sacc[nt];
                s.x = __expf(s.x - mn0);  s.y = __expf(s.y - mn0);
                s.z = __expf(s.z - mn1);  s.w = __expf(s.w - mn1);
                su0 += s.x + s.y;  su1 += s.z + s.w;
            }
            su0 += __shfl_xor_sync(0xffffffffu, su0, 1);
            su0 += __shfl_xor_sync(0xffffffffu, su0, 2);
            su1 += __shfl_xor_sync(0xffffffffu, su1, 1);
            su1 += __shfl_xor_sync(0xffffffffu, su1, 2);
            lrun0 = lrun0 * a0 + su0;
            lrun1 = lrun1 * a1 + su1;
            #pragma unroll
            for (int nf = 0; nf < 20; nf++) {
                oacc[nf].x *= a0;  oacc[nf].y *= a0;
                oacc[nf].z *= a1;  oacc[nf].w *= a1;
            }
        }

        // ---- GEMM2: O += P * V^T ----
        #pragma unroll
        for (int ks2 = 0; ks2 < 4; ks2++) {
            uint4 pa;
            const int src = (lane & ~3) | (tig >> 1);
            {
                float4 c = sacc[ks2];
                float s0  = __shfl_sync(0xffffffffu, c.x, src);
                float s1  = __shfl_sync(0xffffffffu, c.y, src);
                float s0b = __shfl_sync(0xffffffffu, c.x, src + 2);
                float s1b = __shfl_sync(0xffffffffu, c.y, src + 2);
                float A0 = (tig & 1) ? s1 : s0;
                float A2 = (tig & 1) ? s1b : s0b;
                s0  = __shfl_sync(0xffffffffu, c.z, src);
                s1  = __shfl_sync(0xffffffffu, c.w, src);
                s0b = __shfl_sync(0xffffffffu, c.z, src + 2);
                s1b = __shfl_sync(0xffffffffu, c.w, src + 2);
                float A1 = (tig & 1) ? s1 : s0;
                float A3 = (tig & 1) ? s1b : s0b;
                pa = make_uint4(__float_as_uint(A0), __float_as_uint(A1),
                                __float_as_uint(A2), __float_as_uint(A3));
            }
            #pragma unroll
            for (int nf2 = 0; nf2 < 10; nf2++) {
                uint4 bb = *(const uint4*)(Vb + (ks2 * 10 + nf2) * 128 + (lane << 2));
                mma8(oacc[2 * nf2],     pa, make_uint2(bb.x, bb.y));
                mma8(oacc[2 * nf2 + 1], pa, make_uint2(bb.z, bb.w));
            }
        }
    }

    // ---- epilogue: O[d, q] = oacc / l ----
    {
        int r0 = w * 16 + grp;
        int gq = q0 + r0;
        float il0 = 1.0f / lrun0;
        float il1 = 1.0f / lrun1;
        #pragma unroll
        for (int nf = 0; nf < 20; nf++) {
            int d = nf * 8 + tig * 2;
            float4 oa = oacc[nf];
            O[(long)d * S + gq]           = oa.x * il0;
            O[(long)(d + 1) * S + gq]     = oa.y * il0;
            O[(long)d * S + gq + 8]       = oa.z * il1;
            O[(long)(d + 1) * S + gq + 8] = oa.w * il1;
        }
    }
}

// ---------------------------------------------------------------------------
extern "C" void kernel_launch(void* const* d_in, const int* in_sizes, int n_in,
                              void* d_out, int out_size)
{
    using namespace cfg;
    (void)in_sizes; (void)n_in; (void)out_size;

    const float* hidden  = (const float*)d_in[0];  // (B, QD, 1, S)
    const float* context = (const float*)d_in[1];
    const float* mask    = (const float*)d_in[2];  // (B, S, 1, 1)
    const float* Wq      = (const float*)d_in[3];  // (IN, QD)
    const float* Wk      = (const float*)d_in[4];
    const float* Wv      = (const float*)d_in[5];
    const float* Wout    = (const float*)d_in[6];  // (QD, IN)
    const float* bout    = (const float*)d_in[7];
    float*       out     = (float*)d_out;          // (B, QD, 1, S)

    void *pq, *pk, *pv, *pa, *pkf, *pvf, *pwf, *phf, *pcf, *paf;
    cudaGetSymbolAddress(&pq,  g_q);
    cudaGetSymbolAddress(&pk,  g_k);
    cudaGetSymbolAddress(&pv,  g_v);
    cudaGetSymbolAddress(&pa,  g_attn);
    cudaGetSymbolAddress(&pkf, g_kf);
    cudaGetSymbolAddress(&pvf, g_vf);
    cudaGetSymbolAddress(&pwf, g_wf);
    cudaGetSymbolAddress(&phf, g_hf);
    cudaGetSymbolAddress(&pcf, g_cf);
    cudaGetSymbolAddress(&paf, g_af);
    float* q   = (float*)pq;
    float* k   = (float*)pk;
    float* v   = (float*)pv;
    float* at  = (float*)pa;
    float* kf  = (float*)pkf;
    float* vf  = (float*)pvf;
    float* wf  = (float*)pwf;
    float* hf  = (float*)phf;
    float* cf  = (float*)pcf;
    float* af  = (float*)paf;

    const float scale = 1.0f / sqrtf((float)D);
    const long sAct = (long)QD * S;

    cudaFuncSetAttribute(flash4,
                         cudaFuncAttributeMaxDynamicSharedMemorySize, f4::SMEM);
    cudaFuncSetAttribute(gemm_proj,
                         cudaFuncAttributeMaxDynamicSharedMemorySize, gp::SMEM);
    cudaFuncSetAttribute(gemm_out,
                         cudaFuncAttributeMaxDynamicSharedMemorySize, gp::SMEM);

    // 1. pack all four weights (one launch)
    dim3 gra(10, 20, 4);
    repack_a4<<<gra, 256>>>(Wq, Wk, Wv, Wout, wf);

    // 2. pack hidden+context (one launch)
    dim3 grb2(32, 20, 2 * B);
    repack_b2<<<grb2, 256>>>(hidden, context, hf, cf, sAct);

    // 3. q/k/v projections (one launch, grid z = 3*B)
    dim3 ggp(32, 10, 3 * B);
    gemm_proj<<<ggp, 256, gp::SMEM>>>(wf, hf, cf, q, k, v, sAct);

    // 4. pack K/V for flash
    dim3 grep(128, B * H);
    repack_kv<<<grep, 256>>>(k, v, kf, vf);

    // 5. fused attention (128-thread CTAs, 2 per SM)
    dim3 gfl(S / f4::BQ, B * H);
    flash4<<<gfl, 128, f4::SMEM>>>(q, kf, vf, mask, at, scale);

    // 6. pack attn, then out = Wout * attn + bout
    dim3 grb(32, 20, B);
    repack_b<<<grb, 256>>>(at, af, sAct, SPACK);
    dim3 ggo(32, 10, B);
    gemm_out<<<ggo, 256, gp::SMEM>>>(wf, af, out, sAct, bout);
}

// round 17
// speedup vs baseline: 6.8998x; 1.0058x over previous
#include <cuda_runtime.h>
#include <math.h>
#include <stdint.h>

// ---------------------------------------------------------------------------
// CrossAttention, round 17: round-11 pipeline (tcgen05 unavailable on this
// harness's compile target), with flash writing the out-GEMM's packed B
// operand directly (repack_b(attn) + g_attn round-trip deleted).
// B=2, S=4096, H=8, D=160, QUERY_DIM=INNER=1280
// ---------------------------------------------------------------------------

namespace cfg {
constexpr int B  = 2;
constexpr int S  = 4096;
constexpr int H  = 8;
constexpr int D  = 160;
constexpr int QD = 1280;
constexpr int IN = 1280;
}

constexpr long WSZ   = (long)10 * 160 * 8 * 128;   // packed weight size
constexpr long SPACK = (long)32 * 160 * 8 * 128;   // packed activation / batch

__device__ float g_q[(size_t)cfg::B * cfg::IN * cfg::S];
__device__ float g_k[(size_t)cfg::B * cfg::IN * cfg::S];
__device__ float g_v[(size_t)cfg::B * cfg::IN * cfg::S];
// pair-interleaved fragment-packed K/V for flash: [bh][ktile][40 pairs][128]
__device__ float g_kf[(size_t)cfg::B * cfg::H * 128 * 40 * 128];
__device__ float g_vf[(size_t)cfg::B * cfg::H * 128 * 40 * 128];
// A-fragment-packed weights, one block: [Wq | Wk | Wv | Wout]
__device__ float g_wf[(size_t)4 * WSZ];
// B-fragment-pair-packed activations
__device__ float g_hf[(size_t)cfg::B * SPACK];
__device__ float g_cf[(size_t)cfg::B * SPACK];
__device__ float g_af[(size_t)cfg::B * SPACK];

__device__ __forceinline__ float to_tf32(float x) {
    float r; asm("cvt.rna.tf32.f32 %0, %1;" : "=f"(r) : "f"(x)); return r;
}

__device__ __forceinline__ void mma8(float4& d, const uint4& a, const uint2& b) {
    asm volatile(
        "mma.sync.aligned.m16n8k8.row.col.f32.tf32.tf32.f32 "
        "{%0,%1,%2,%3}, {%4,%5,%6,%7}, {%8,%9}, {%0,%1,%2,%3};\n"
        : "+f"(d.x), "+f"(d.y), "+f"(d.z), "+f"(d.w)
        : "r"(a.x), "r"(a.y), "r"(a.z), "r"(a.w), "r"(b.x), "r"(b.y));
}

// ---------------------------------------------------------------------------
// repack_a4: all four weights -> A-fragment order (tf32), one launch.
// grid (kc=10, mc=20, z=4), 256 thr.
// ---------------------------------------------------------------------------
__global__ void __launch_bounds__(256)
repack_a4(const float* __restrict__ w0, const float* __restrict__ w1,
          const float* __restrict__ w2, const float* __restrict__ w3,
          float* __restrict__ wf_all)
{
    __shared__ float sW[64 * 132];
    const int kc = blockIdx.x, mc = blockIdx.y, z = blockIdx.z;
    const float* Wg = (z == 0) ? w0 : (z == 1) ? w1 : (z == 2) ? w2 : w3;
    float* Wf = wf_all + (long)z * WSZ;
    const int t = threadIdx.x;
    #pragma unroll
    for (int i = 0; i < 8; i++) {
        int c = t + i * 256;
        int row = c >> 5, c4 = c & 31;
        float4 v = *(const float4*)(Wg + (long)(mc * 64 + row) * 1280 + kc * 128 + c4 * 4);
        float* d = sW + row * 132 + c4 * 4;
        d[0] = to_tf32(v.x); d[1] = to_tf32(v.y);
        d[2] = to_tf32(v.z); d[3] = to_tf32(v.w);
    }
    __syncthreads();
    const int mt = mc >> 1, mgh = (mc & 1) * 4;
    #pragma unroll
    for (int i = 0; i < 8; i++) {
        int o = t + i * 256;
        int fr = o >> 5, l = o & 31;
        int kfl = fr >> 2, mg = fr & 3;
        int rb = mg * 16 + (l >> 2);
        int cb = kfl * 8 + (l & 3);
        float4 out = make_float4(sW[rb * 132 + cb],       sW[(rb + 8) * 132 + cb],
                                 sW[rb * 132 + cb + 4],   sW[(rb + 8) * 132 + cb + 4]);
        *(float4*)(Wf + ((long)(mt * 160 + kc * 16 + kfl) * 8 + mgh + mg) * 128 + l * 4) = out;
    }
}

// ---------------------------------------------------------------------------
// repack_b core (hidden/context only now).
// ---------------------------------------------------------------------------
__device__ __forceinline__ void repack_b_body(const float* __restrict__ X,
                                              float* __restrict__ Xo,
                                              int nt, int kc, int t, float* sB)
{
    #pragma unroll
    for (int i = 0; i < 8; i++) {
        int c = t + i * 256;
        int row = c >> 5, c4 = c & 31;
        float4 v = *(const float4*)(X + (long)(kc * 64 + row) * 4096 + nt * 128 + c4 * 4);
        float* d = sB + row * 132 + c4 * 4;
        d[0] = to_tf32(v.x); d[1] = to_tf32(v.y);
        d[2] = to_tf32(v.z); d[3] = to_tf32(v.w);
    }
    __syncthreads();
    #pragma unroll
    for (int i = 0; i < 8; i++) {
        int o = t + i * 256;
        int fr = o >> 5, l = o & 31;
        int kfl = fr >> 3, np = fr & 7;
        int rb = kfl * 8 + (l & 3);
        int cb = np * 16 + (l >> 2);
        float4 out = make_float4(sB[rb * 132 + cb],       sB[(rb + 4) * 132 + cb],
                                 sB[rb * 132 + cb + 8],   sB[(rb + 4) * 132 + cb + 8]);
        *(float4*)(Xo + ((long)(nt * 160 + kc * 8 + kfl) * 8 + np) * 128 + l * 4) = out;
    }
}

// merged hidden+context pack: grid (32, 20, 2*B); z = which*B + b
__global__ void __launch_bounds__(256)
repack_b2(const float* __restrict__ hidden, const float* __restrict__ context,
          float* __restrict__ hf, float* __restrict__ cf, long sX)
{
    __shared__ float sB[64 * 132];
    const int z = blockIdx.z;
    const int which = z / cfg::B, b = z % cfg::B;
    const float* X  = (which ? context : hidden) + (long)b * sX;
    float*       Xo = (which ? cf : hf) + (long)b * SPACK;
    repack_b_body(X, Xo, blockIdx.x, blockIdx.y, threadIdx.x, sB);
}

// ---------------------------------------------------------------------------
// gemm core: C(1280 x 4096) = Af (A-frag) * Bf (B-frag-pair), 8 warps x 16
// rows, BN=128, BK=32, 3-stage cp.async (96 KB, 2 CTAs/SM).
// ---------------------------------------------------------------------------
namespace gp {
constexpr int TILE  = 4096;
constexpr int STG   = 2 * TILE;
constexpr int NST   = 3;
constexpr int SMEM  = NST * STG * 4;        // 98,304 B
constexpr int NIT   = 40;
}

template<bool CVT_OUT, bool BIAS>
__device__ __forceinline__ void gemm_body(const float* At, const float* Bt,
                                          float* C, const float* bias,
                                          int nt, int mt, float* sm)
{
    const int t = threadIdx.x, lane = t & 31, w = t >> 5;
    const uint32_t sbase = (uint32_t)__cvta_generic_to_shared(sm);

    auto stage = [&](int it) {
        const int slot = it % gp::NST;
        const uint32_t ab = sbase + (uint32_t)(slot * gp::STG) * 4;
        const uint32_t bb = ab + gp::TILE * 4;
        const float* As = At + (long)it * gp::TILE;
        const float* Bs = Bt + (long)it * gp::TILE;
        #pragma unroll
        for (int i = 0; i < 4; i++) {
            int c = t + i * 256;
            asm volatile("cp.async.cg.shared.global [%0], [%1], 16;\n"
                         :: "r"(ab + (uint32_t)c * 16), "l"(As + c * 4));
        }
        #pragma unroll
        for (int i = 0; i < 4; i++) {
            int c = t + i * 256;
            asm volatile("cp.async.cg.shared.global [%0], [%1], 16;\n"
                         :: "r"(bb + (uint32_t)c * 16), "l"(Bs + c * 4));
        }
        asm volatile("cp.async.commit_group;\n");
    };

    float4 acc[16];
    #pragma unroll
    for (int j = 0; j < 16; j++) acc[j] = make_float4(0.f, 0.f, 0.f, 0.f);

    stage(0); stage(1);

    for (int it = 0; it < gp::NIT; it++) {
        asm volatile("cp.async.wait_group 1;\n" ::: "memory");
        __syncthreads();
        if (it + 2 < gp::NIT) stage(it + 2);

        const float* As_ = sm + (it % gp::NST) * gp::STG;
        const float* Bs_ = As_ + gp::TILE;

        #pragma unroll
        for (int ks = 0; ks < 4; ks++) {
            uint4 a = *(const uint4*)(As_ + (ks * 8 + w) * 128 + (lane << 2));
            #pragma unroll
            for (int np = 0; np < 8; np++) {
                uint4 bv = *(const uint4*)(Bs_ + (ks * 8 + np) * 128 + (lane << 2));
                mma8(acc[2 * np],     a, make_uint2(bv.x, bv.y));
                mma8(acc[2 * np + 1], a, make_uint2(bv.z, bv.w));
            }
        }
    }

    const int m0 = mt * 128 + w * 16 + (lane >> 2);
    const int nb = nt * 128 + (lane & 3) * 2;
    float b0 = 0.f, b1 = 0.f;
    if (BIAS) { b0 = bias[m0]; b1 = bias[m0 + 8]; }
    #pragma unroll
    for (int j = 0; j < 16; j++) {
        float4 ac = acc[j];
        float o0 = ac.x + b0, o1 = ac.y + b0;
        float o2 = ac.z + b1, o3 = ac.w + b1;
        if (CVT_OUT) { o0 = to_tf32(o0); o1 = to_tf32(o1);
                       o2 = to_tf32(o2); o3 = to_tf32(o3); }
        int n = nb + j * 8;
        *(float2*)(C + (long)m0 * 4096 + n)       = make_float2(o0, o1);
        *(float2*)(C + (long)(m0 + 8) * 4096 + n) = make_float2(o2, o3);
    }
}

// merged q/k/v projections: grid (32, 10, 3*B); z = p*B + b
__global__ void __launch_bounds__(256, 2)
gemm_proj(const float* __restrict__ wf, const float* __restrict__ hf,
          const float* __restrict__ cf, float* __restrict__ q,
          float* __restrict__ k, float* __restrict__ v, long sC)
{
    extern __shared__ float sm[];
    const int nt = blockIdx.x, mt = blockIdx.y, z = blockIdx.z;
    const int p = z / cfg::B, b = z % cfg::B;
    const float* At = wf + (long)p * WSZ + (long)mt * 160 * 8 * 128;
    const float* Bt = ((p == 0) ? hf : cf) + (long)b * SPACK + (long)nt * 160 * 8 * 128;
    float* C = ((p == 0) ? q : (p == 1) ? k : v) + (long)b * sC;
    gemm_body<true, false>(At, Bt, C, nullptr, nt, mt, sm);
}

// out projection: grid (32, 10, B)
__global__ void __launch_bounds__(256, 2)
gemm_out(const float* __restrict__ wf, const float* __restrict__ af,
         float* __restrict__ out, long sC, const float* __restrict__ bias)
{
    extern __shared__ float sm[];
    const int nt = blockIdx.x, mt = blockIdx.y, z = blockIdx.z;
    const float* At = wf + (long)3 * WSZ + (long)mt * 160 * 8 * 128;
    const float* Bt = af + (long)z * SPACK + (long)nt * 160 * 8 * 128;
    float* C = out + (long)z * sC;
    gemm_body<false, true>(At, Bt, C, bias, nt, mt, sm);
}

// ---------------------------------------------------------------------------
// repack_kv (unchanged): K/V -> pair-interleaved B-fragment order.
// ---------------------------------------------------------------------------
__global__ void __launch_bounds__(256)
repack_kv(const float* __restrict__ kg, const float* __restrict__ vg,
          float* __restrict__ kf, float* __restrict__ vf)
{
    using namespace cfg;
    __shared__ float sK[160 * 33], sV[160 * 33];
    const int kt = blockIdx.x, bh = blockIdx.y;
    const long base = (long)bh * D * S;
    const int k0 = kt * 32;
    const int t = threadIdx.x;

    #pragma unroll
    for (int i = 0; i < 5; i++) {
        int f = t + i * 256;
        int row = f >> 3, cv = f & 7;
        float4 a = *(const float4*)(kg + base + (long)row * S + k0 + cv * 4);
        float4 b = *(const float4*)(vg + base + (long)row * S + k0 + cv * 4);
        int sa = row * 33 + cv * 4;
        sK[sa] = a.x; sK[sa + 1] = a.y; sK[sa + 2] = a.z; sK[sa + 3] = a.w;
        sV[sa] = b.x; sV[sa + 1] = b.y; sV[sa + 2] = b.z; sV[sa + 3] = b.w;
    }
    __syncthreads();

    const long obase = ((long)bh * 128 + kt) * 5120;
    #pragma unroll
    for (int i = 0; i < 5; i++) {
        int g = t + i * 256;
        int pr = g >> 5, l = g & 31;
        {
            int ks = pr >> 1, nt2 = pr & 1;
            int d0 = ks * 8 + (l & 3);
            int kpe = nt2 * 16 + (l >> 2);
            float4 o = make_float4(sK[d0 * 33 + kpe],       sK[(d0 + 4) * 33 + kpe],
                                   sK[d0 * 33 + kpe + 8],   sK[(d0 + 4) * 33 + kpe + 8]);
            *(float4*)(kf + obase + pr * 128 + l * 4) = o;
        }
        {
            int ks2 = pr / 10, nf2 = pr % 10;
            int de = nf2 * 16 + (l >> 2);
            int kp0 = ks2 * 8 + (l & 3);
            float4 o = make_float4(sV[de * 33 + kp0],       sV[de * 33 + kp0 + 4],
                                   sV[(de + 8) * 33 + kp0], sV[(de + 8) * 33 + kp0 + 4]);
            *(float4*)(vf + obase + pr * 128 + l * 4) = o;
        }
    }
}

// ---------------------------------------------------------------------------
// Flash attention v7: 128-thread CTAs (4 warps x 16 q-rows, BQ=64), 2-stage
// cp.async, 2 CTAs/SM. Epilogue writes the out-GEMM's B operand (g_af)
// directly in packed fragment order (acc->fragment shuffle, coalesced STG.128).
// ---------------------------------------------------------------------------
namespace f4 {
constexpr int BQ   = 64;
constexpr int BK   = 32;
constexpr int NTLE = cfg::S / BK;           // 128
constexpr int KSZ  = 5120;
constexpr int VSZ  = 5120;
constexpr int MSZ  = 32;
constexpr int STG  = KSZ + VSZ + MSZ;       // 10272 floats
constexpr int NST  = 2;
constexpr int SMEM = NST * STG * 4;         // 82,176 B -> 2 CTAs/SM
}

__global__ void __launch_bounds__(128, 2)
flash4(const float* __restrict__ qg, const float* __restrict__ kfg,
       const float* __restrict__ vfg, const float* __restrict__ mask,
       float* __restrict__ af, float scale)
{
    using namespace cfg;
    extern __shared__ float sm[];

    const int qt = blockIdx.x, bh = blockIdx.y, b = bh / H, h = bh % H;
    const long base = (long)bh * D * S;
    const float* Q = qg + base;
    const float* Kf = kfg + (long)bh * 128 * 5120;
    const float* Vf = vfg + (long)bh * 128 * 5120;
    const float* mrow = mask + (long)b * S;
    const int q0 = qt * f4::BQ;

    const int t = threadIdx.x, lane = t & 31, w = t >> 5;
    const int grp = lane >> 2, tig = lane & 3;

    uint4 qa[20];
    {
        const int m0 = q0 + w * 16 + grp;
        #pragma unroll
        for (int ks = 0; ks < 20; ks++) {
            int d0 = ks * 8 + tig;
            qa[ks] = make_uint4(
                __float_as_uint(Q[(long)d0 * S + m0]),
                __float_as_uint(Q[(long)d0 * S + m0 + 8]),
                __float_as_uint(Q[(long)(d0 + 4) * S + m0]),
                __float_as_uint(Q[(long)(d0 + 4) * S + m0 + 8]));
        }
    }

    const uint32_t sbase = (uint32_t)__cvta_generic_to_shared(sm);

    auto stage = [&](int tile) {
        const int slot = tile & (f4::NST - 1);
        const uint32_t kb = sbase + (uint32_t)(slot * f4::STG) * 4;
        const uint32_t vb = kb + f4::KSZ * 4;
        const uint32_t mb = vb + f4::VSZ * 4;
        const float* Kt = Kf + (long)tile * 5120;
        const float* Vt = Vf + (long)tile * 5120;
        #pragma unroll
        for (int i = 0; i < 10; i++) {
            int c = t + i * 128;
            asm volatile("cp.async.cg.shared.global [%0], [%1], 16;\n"
                         :: "r"(kb + (uint32_t)c * 16), "l"(Kt + c * 4));
        }
        #pragma unroll
        for (int i = 0; i < 10; i++) {
            int c = t + i * 128;
            asm volatile("cp.async.cg.shared.global [%0], [%1], 16;\n"
                         :: "r"(vb + (uint32_t)c * 16), "l"(Vt + c * 4));
        }
        if (t < 8) {
            const float* src = mrow + tile * f4::BK + t * 4;
            asm volatile("cp.async.cg.shared.global [%0], [%1], 16;\n"
                         :: "r"(mb + (uint32_t)t * 16), "l"(src));
        }
        asm volatile("cp.async.commit_group;\n");
    };

    float4 oacc[20];
    #pragma unroll
    for (int j = 0; j < 20; j++) oacc[j] = make_float4(0.f, 0.f, 0.f, 0.f);
    float mrun0 = -1e30f, mrun1 = -1e30f;
    float lrun0 = 0.f, lrun1 = 0.f;

    stage(0);

    for (int it = 0; it < f4::NTLE; it++) {
        asm volatile("cp.async.wait_group 0;\n" ::: "memory");
        __syncthreads();
        if (it + 1 < f4::NTLE) stage(it + 1);

        const float* Kb = sm + (it & (f4::NST - 1)) * f4::STG;
        const float* Vb = Kb + f4::KSZ;
        const float* Mb = Vb + f4::VSZ;

        // ---- GEMM1: scores(16q x 32k) ----
        float4 sacc[4];
        #pragma unroll
        for (int j = 0; j < 4; j++) sacc[j] = make_float4(0.f, 0.f, 0.f, 0.f);
        #pragma unroll
        for (int ks = 0; ks < 20; ks++) {
            uint4 b0 = *(const uint4*)(Kb + (ks * 2) * 128 + (lane << 2));
            uint4 b1 = *(const uint4*)(Kb + (ks * 2 + 1) * 128 + (lane << 2));
            mma8(sacc[0], qa[ks], make_uint2(b0.x, b0.y));
            mma8(sacc[1], qa[ks], make_uint2(b0.z, b0.w));
            mma8(sacc[2], qa[ks], make_uint2(b1.x, b1.y));
            mma8(sacc[3], qa[ks], make_uint2(b1.z, b1.w));
        }

        // ---- softmax (register/warp-shuffle; rows owned by this warp) ------
        {
            float r0 = -1e30f, r1 = -1e30f;
            #pragma unroll
            for (int nt = 0; nt < 4; nt++) {
                float mv0 = Mb[nt * 8 + tig * 2];
                float mv1 = Mb[nt * 8 + tig * 2 + 1];
                float4& s = sacc[nt];
                s.x = fmaf(s.x, scale, mv0);  s.y = fmaf(s.y, scale, mv1);
                s.z = fmaf(s.z, scale, mv0);  s.w = fmaf(s.w, scale, mv1);
                r0 = fmaxf(r0, fmaxf(s.x, s.y));
                r1 = fmaxf(r1, fmaxf(s.z, s.w));
            }
            r0 = fmaxf(r0, __shfl_xor_sync(0xffffffffu, r0, 1));
            r0 = fmaxf(r0, __shfl_xor_sync(0xffffffffu, r0, 2));
            r1 = fmaxf(r1, __shfl_xor_sync(0xffffffffu, r1, 1));
            r1 = fmaxf(r1, __shfl_xor_sync(0xffffffffu, r1, 2));
            float mn0 = fmaxf(mrun0, r0);
            float mn1 = fmaxf(mrun1, r1);
            float a0 = __expf(mrun0 - mn0);
            float a1 = __expf(mrun1 - mn1);
            mrun0 = mn0;  mrun1 = mn1;

            float su0 = 0.f, su1 = 0.f;
            #pragma unroll
            for (int nt = 0; nt < 4; nt++) {
                float4& s = sacc[nt];
                s.x = __expf(s.x - mn0);  s.y = __expf(s.y - mn0);
                s.z = __expf(s.z - mn1);  s.w = __expf(s.w - mn1);
                su0 += s.x + s.y;  su1 += s.z + s.w;
            }
            su0 += __shfl_xor_sync(0xffffffffu, su0, 1);
            su0 += __shfl_xor_sync(0xffffffffu, su0, 2);
            su1 += __shfl_xor_sync(0xffffffffu, su1, 1);
            su1 += __shfl_xor_sync(0xffffffffu, su1, 2);
            lrun0 = lrun0 * a0 + su0;
            lrun1 = lrun1 * a1 + su1;
            #pragma unroll
            for (int nf = 0; nf < 20; nf++) {
                oacc[nf].x *= a0;  oacc[nf].y *= a0;
                oacc[nf].z *= a1;  oacc[nf].w *= a1;
            }
        }

        // ---- GEMM2: O += P * V^T ----
        #pragma unroll
        for (int ks2 = 0; ks2 < 4; ks2++) {
            uint4 pa;
            const int src = (lane & ~3) | (tig >> 1);
            {
                float4 c = sacc[ks2];
                float s0  = __shfl_sync(0xffffffffu, c.x, src);
                float s1  = __shfl_sync(0xffffffffu, c.y, src);
                float s0b = __shfl_sync(0xffffffffu, c.x, src + 2);
                float s1b = __shfl_sync(0xffffffffu, c.y, src + 2);
                float A0 = (tig & 1) ? s1 : s0;
                float A2 = (tig & 1) ? s1b : s0b;
                s0  = __shfl_sync(0xffffffffu, c.z, src);
                s1  = __shfl_sync(0xffffffffu, c.w, src);
                s0b = __shfl_sync(0xffffffffu, c.z, src + 2);
                s1b = __shfl_sync(0xffffffffu, c.w, src + 2);
                float A1 = (tig & 1) ? s1 : s0;
                float A3 = (tig & 1) ? s1b : s0b;
                pa = make_uint4(__float_as_uint(A0), __float_as_uint(A1),
                                __float_as_uint(A2), __float_as_uint(A3));
            }
            #pragma unroll
            for (int nf2 = 0; nf2 < 10; nf2++) {
                uint4 bb = *(const uint4*)(Vb + (ks2 * 10 + nf2) * 128 + (lane << 2));
                mma8(oacc[2 * nf2],     pa, make_uint2(bb.x, bb.y));
                mma8(oacc[2 * nf2 + 1], pa, make_uint2(bb.z, bb.w));
            }
        }
    }

    // ---- epilogue: write af (out-GEMM packed B operand) directly -----------
    // acc layout (rows q=grp{,+8}, cols d=2tig{,+1}) -> packed fragment
    // {X[k][n], X[k+4][n], X[k][n+8], X[k+4][n+8]} at lane l (k=l&3, n=l>>2),
    // where X[k][n] = O[q=n][d=k]. Same shuffle as GEMM2's P conversion with
    // components 1<->2 swapped. Values scaled by 1/l and tf32-rounded first
    // (identical rounding point to the old repack_b path -> bit-identical).
    {
        const int nglob = q0 + w * 16;
        const int ntb = nglob >> 7;          // 128-col block
        const int np  = (nglob >> 4) & 7;    // 16-col block within
        float il0 = 1.0f / lrun0;
        float il1 = 1.0f / lrun1;
        float* dst = af + (long)b * SPACK;
        const int src = (lane & ~3) | (tig >> 1);
        #pragma unroll
        for (int nf = 0; nf < 20; nf++) {
            float4 c = oacc[nf];
            c.x = to_tf32(c.x * il0);  c.y = to_tf32(c.y * il0);
            c.z = to_tf32(c.z * il1);  c.w = to_tf32(c.w * il1);
            float s0  = __shfl_sync(0xffffffffu, c.x, src);
            float s1  = __shfl_sync(0xffffffffu, c.y, src);
            float s0b = __shfl_sync(0xffffffffu, c.x, src + 2);
            float s1b = __shfl_sync(0xffffffffu, c.y, src + 2);
            float A0 = (tig & 1) ? s1 : s0;      // O[q][d=l&3]
            float A2 = (tig & 1) ? s1b : s0b;    // O[q][d=(l&3)+4]
            s0  = __shfl_sync(0xffffffffu, c.z, src);
            s1  = __shfl_sync(0xffffffffu, c.w, src);
            s0b = __shfl_sync(0xffffffffu, c.z, src + 2);
            s1b = __shfl_sync(0xffffffffu, c.w, src + 2);
            float A1 = (tig & 1) ? s1 : s0;      // O[q+8][d=l&3]
            float A3 = (tig & 1) ? s1b : s0b;    // O[q+8][d=(l&3)+4]
            int kfl = h * 20 + nf;
            *(float4*)(dst + ((long)(ntb * 160 + kfl) * 8 + np) * 128 + lane * 4)
                = make_float4(A0, A2, A1, A3);
        }
    }
}

// ---------------------------------------------------------------------------
extern "C" void kernel_launch(void* const* d_in, const int* in_sizes, int n_in,
                              void* d_out, int out_size)
{
    using namespace cfg;
    (void)in_sizes; (void)n_in; (void)out_size;

    const float* hidden  = (const float*)d_in[0];  // (B, QD, 1, S)
    const float* context = (const float*)d_in[1];
    const float* mask    = (const float*)d_in[2];  // (B, S, 1, 1)
    const float* Wq      = (const float*)d_in[3];  // (IN, QD)
    const float* Wk      = (const float*)d_in[4];
    const float* Wv      = (const float*)d_in[5];
    const float* Wout    = (const float*)d_in[6];  // (QD, IN)
    const float* bout    = (const float*)d_in[7];
    float*       out     = (float*)d_out;          // (B, QD, 1, S)

    void *pq, *pk, *pv, *pkf, *pvf, *pwf, *phf, *pcf, *paf;
    cudaGetSymbolAddress(&pq,  g_q);
    cudaGetSymbolAddress(&pk,  g_k);
    cudaGetSymbolAddress(&pv,  g_v);
    cudaGetSymbolAddress(&pkf, g_kf);
    cudaGetSymbolAddress(&pvf, g_vf);
    cudaGetSymbolAddress(&pwf, g_wf);
    cudaGetSymbolAddress(&phf, g_hf);
    cudaGetSymbolAddress(&pcf, g_cf);
    cudaGetSymbolAddress(&paf, g_af);
    float* q   = (float*)pq;
    float* k   = (float*)pk;
    float* v   = (float*)pv;
    float* kf  = (float*)pkf;
    float* vf  = (float*)pvf;
    float* wf  = (float*)pwf;
    float* hf  = (float*)phf;
    float* cf  = (float*)pcf;
    float* af  = (float*)paf;

    const float scale = 1.0f / sqrtf((float)D);
    const long sAct = (long)QD * S;

    cudaFuncSetAttribute(flash4,
                         cudaFuncAttributeMaxDynamicSharedMemorySize, f4::SMEM);
    cudaFuncSetAttribute(gemm_proj,
                         cudaFuncAttributeMaxDynamicSharedMemorySize, gp::SMEM);
    cudaFuncSetAttribute(gemm_out,
                         cudaFuncAttributeMaxDynamicSharedMemorySize, gp::SMEM);

    // 1. pack all four weights (one launch)
    dim3 gra(10, 20, 4);
    repack_a4<<<gra, 256>>>(Wq, Wk, Wv, Wout, wf);

    // 2. pack hidden+context (one launch)
    dim3 grb2(32, 20, 2 * B);
    repack_b2<<<grb2, 256>>>(hidden, context, hf, cf, sAct);

    // 3. q/k/v projections (one launch, grid z = 3*B)
    dim3 ggp(32, 10, 3 * B);
    gemm_proj<<<ggp, 256, gp::SMEM>>>(wf, hf, cf, q, k, v, sAct);

    // 4. pack K/V for flash
    dim3 grep(128, B * H);
    repack_kv<<<grep, 256>>>(k, v, kf, vf);

    // 5. fused attention (writes packed af directly)
    dim3 gfl(S / f4::BQ, B * H);
    flash4<<<gfl, 128, f4::SMEM>>>(q, kf, vf, mask, af, scale);

    // 6. out = Wout * attn + bout (reads packed af)
    dim3 ggo(32, 10, B);
    gemm_out<<<ggo, 256, gp::SMEM>>>(wf, af, out, sAct, bout);
}